// round 2
// baseline (speedup 1.0000x reference)
#include <cuda_runtime.h>
#include <math.h>

#define BB 8
#define CIN 256
#define CO 64
#define VV 128
#define TT 128
#define SY 129   // padded smem row stride (conflict-free)

// ---------------- scratch (device globals; no allocation allowed) ----------
__device__ float g_y  [BB*CO*VV*TT];   // y[b][c][v][t]
__device__ float g_ytr[BB*TT*CO*VV];   // y[b][t][c][v]
__device__ float g_OH [BB*CO*VV*TT];   // unnormalized out_H
__device__ float g_OW [BB*CO*VV*TT];   // unnormalized out_W
__device__ float g_av [BB*CO*VV*TT];   // channel-attention output (conv input)
__device__ float g_mH [BB*VV*TT];
__device__ float g_ZH [BB*VV*TT];
__device__ float g_mW [BB*VV*TT];
__device__ float g_ZW [BB*VV*TT];

// ---------------- kernel 1: y = dc_w @ xp + dc_b ---------------------------
// grid (128 v-rows, 8 b), 256 threads. 64x256 GEMM for one padded row (128 t).
__global__ __launch_bounds__(256) void k_y(const float* __restrict__ x,
                                           const float* __restrict__ w,
                                           const float* __restrict__ bias) {
    __shared__ float xs[32][128];
    __shared__ float ws[64][32];
    int v = blockIdx.x, b = blockIdx.y;
    int tid = threadIdx.x, lane = tid & 31, warp = tid >> 5;
    float acc[8][4];
#pragma unroll
    for (int i = 0; i < 8; i++)
#pragma unroll
        for (int j = 0; j < 4; j++) acc[i][j] = 0.f;
    bool vin = (v >= 1 && v <= 126);
    for (int c0 = 0; c0 < CIN; c0 += 32) {
        for (int i = tid; i < 32*128; i += 256) {
            int ci = i >> 7, t = i & 127;
            float val = 0.f;
            if (vin && t >= 1 && t <= 126)
                val = x[(((size_t)b*CIN + c0 + ci)*126 + (v-1))*126 + (t-1)];
            xs[ci][t] = val;
        }
        for (int i = tid; i < 64*32; i += 256)
            ws[i>>5][i&31] = w[(size_t)(i>>5)*CIN + c0 + (i&31)];
        __syncthreads();
#pragma unroll
        for (int ci = 0; ci < 32; ci++) {
            float xv[4];
#pragma unroll
            for (int j = 0; j < 4; j++) xv[j] = xs[ci][lane + 32*j];
#pragma unroll
            for (int i = 0; i < 8; i++) {
                float wv = ws[warp*8 + i][ci];
#pragma unroll
                for (int j = 0; j < 4; j++) acc[i][j] = fmaf(wv, xv[j], acc[i][j]);
            }
        }
        __syncthreads();
    }
#pragma unroll
    for (int i = 0; i < 8; i++) {
        int o = warp*8 + i;
        float bo = bias[o];
#pragma unroll
        for (int j = 0; j < 4; j++)
            g_y[(((size_t)b*CO + o)*VV + v)*TT + lane + 32*j] = acc[i][j] + bo;
    }
}

// ---------------- kernel 1b: transpose y -> y_tr ----------------------------
// grid (16 tiles, 64 c, 8 b), threads (32,8)
__global__ __launch_bounds__(256) void k_tr() {
    __shared__ float s[32][33];
    int tile = blockIdx.x, c = blockIdx.y, b = blockIdx.z;
    int v0 = (tile >> 2) * 32, t0 = (tile & 3) * 32;
    int tx = threadIdx.x, ty = threadIdx.y;
    const float* src = g_y + ((size_t)(b*CO + c))*VV*TT;
#pragma unroll
    for (int i = 0; i < 32; i += 8)
        s[ty+i][tx] = src[(size_t)(v0+ty+i)*TT + t0 + tx];
    __syncthreads();
    float* dst = g_ytr + (size_t)b*TT*CO*VV + (size_t)c*VV;
#pragma unroll
    for (int i = 0; i < 32; i += 8)
        dst[(size_t)(t0+ty+i)*(CO*VV) + v0 + tx] = s[tx][ty+i];
}

// ---------------- kernel 2: W-attention + channel-attention per (b,v) ------
__global__ __launch_bounds__(256) void k_wc(
    const float* __restrict__ qw, const float* __restrict__ qb,
    const float* __restrict__ kw, const float* __restrict__ kb,
    const float* __restrict__ vw, const float* __restrict__ vb,
    const float* __restrict__ cqw, const float* __restrict__ cqb,
    const float* __restrict__ ckw, const float* __restrict__ ckb,
    const float* __restrict__ cvw, const float* __restrict__ cvb) {
    int v = blockIdx.x, b = blockIdx.y;
    int tid = threadIdx.x, lane = tid & 31, warp = tid >> 5;
    extern __shared__ float sm[];
    float* ys = sm;                 // [64][SY]
    float* s1 = sm + 64*SY;

    // load y[b,:,v,:] slice
    const float* ysrc = g_y + (size_t)b*CO*VV*TT + (size_t)v*TT;
    for (int i = tid; i < 64*128; i += 256) {
        int c = i >> 7, t = i & 127;
        ys[c*SY + t] = ysrc[(size_t)c*VV*TT + t];
    }
    __syncthreads();

    // ---- phase W ----
    float* qs = s1;                 // [8][SY]
    float* ks = s1 + 8*SY;          // [8][SY]
    float* vs = s1 + 16*SY;         // [64][SY]
    float* E  = s1 + 80*SY;         // [128][SY]
    for (int i = tid; i < 2*8*128; i += 256) {
        int which = i >> 10, e = i & 1023;
        int cq = e >> 7, t = e & 127;
        const float* W = which ? kw : qw;
        float acc = which ? kb[cq] : qb[cq];
#pragma unroll 16
        for (int c = 0; c < 64; c++) acc = fmaf(W[cq*64 + c], ys[c*SY + t], acc);
        (which ? ks : qs)[cq*SY + t] = acc;
    }
    for (int i = tid; i < 64*128; i += 256) {
        int c = i >> 7, t = i & 127;
        float acc = vb[c];
#pragma unroll 16
        for (int cc = 0; cc < 64; cc++) acc = fmaf(vw[c*64 + cc], ys[cc*SY + t], acc);
        vs[c*SY + t] = acc;
    }
    __syncthreads();
    for (int i = tid; i < 128*128; i += 256) {
        int t = i >> 7, s = i & 127;
        float acc = 0.f;
#pragma unroll
        for (int c = 0; c < 8; c++) acc = fmaf(qs[c*SY + t], ks[c*SY + s], acc);
        E[t*SY + s] = acc;
    }
    __syncthreads();
    if (tid < 128) {
        int t = tid;
        float m = -INFINITY;
        for (int s = 0; s < 128; s++) m = fmaxf(m, E[t*SY + s]);
        float Z = 0.f;
        for (int s = 0; s < 128; s++) { float p = __expf(E[t*SY + s] - m); E[t*SY + s] = p; Z += p; }
        g_mW[((size_t)b*VV + v)*TT + t] = m;
        g_ZW[((size_t)b*VV + v)*TT + t] = Z;
    }
    __syncthreads();
    {   // O_W[c][t] = sum_s vs[c][s] * P[t][s]
        float acc[8][4];
#pragma unroll
        for (int i = 0; i < 8; i++)
#pragma unroll
            for (int j = 0; j < 4; j++) acc[i][j] = 0.f;
        for (int s = 0; s < 128; s++) {
            float pv[4];
#pragma unroll
            for (int j = 0; j < 4; j++) pv[j] = E[(lane + 32*j)*SY + s];
#pragma unroll
            for (int i = 0; i < 8; i++) {
                float vv = vs[(warp*8 + i)*SY + s];
#pragma unroll
                for (int j = 0; j < 4; j++) acc[i][j] = fmaf(vv, pv[j], acc[i][j]);
            }
        }
        float* dst = g_OW + (size_t)b*CO*VV*TT + (size_t)v*TT;
#pragma unroll
        for (int i = 0; i < 8; i++)
#pragma unroll
            for (int j = 0; j < 4; j++)
                dst[(size_t)(warp*8 + i)*VV*TT + lane + 32*j] = acc[i][j];
    }
    __syncthreads();

    // ---- phase C (channel attention), reuse s1 ----
    float* qc = s1;                 // [64][SY]
    float* kc = s1 + 64*SY;
    float* vc = s1 + 128*SY;
    float* Ec = s1 + 192*SY;        // [64][65]
    for (int i = tid; i < 3*64*128; i += 256) {
        int which = i >> 13, e = i & 8191;
        int c = e >> 7, t = e & 127;
        const float* W  = which == 0 ? cqw : (which == 1 ? ckw : cvw);
        const float* Bv = which == 0 ? cqb : (which == 1 ? ckb : cvb);
        float acc = Bv[c];
#pragma unroll 16
        for (int cc = 0; cc < 64; cc++) acc = fmaf(W[c*64 + cc], ys[cc*SY + t], acc);
        (which == 0 ? qc : (which == 1 ? kc : vc))[c*SY + t] = acc;
    }
    __syncthreads();
    for (int i = tid; i < 64*64; i += 256) {
        int c = i >> 6, d = i & 63;
        float acc = 0.f;
#pragma unroll 16
        for (int t = 0; t < 128; t++) acc = fmaf(qc[c*SY + t], kc[d*SY + t], acc);
        Ec[c*65 + d] = acc;
    }
    __syncthreads();
    if (tid < 64) {
        int c = tid;
        float m = -INFINITY;
        for (int d = 0; d < 64; d++) m = fmaxf(m, Ec[c*65 + d]);
        float Z = 0.f;
        for (int d = 0; d < 64; d++) { float p = __expf(Ec[c*65 + d] - m); Ec[c*65 + d] = p; Z += p; }
        float inv = 1.f / Z;
        for (int d = 0; d < 64; d++) Ec[c*65 + d] *= inv;
    }
    __syncthreads();
    {   // av[c][t] = sum_d attn[c][d] * vc[d][t]
        float acc[8][4];
#pragma unroll
        for (int i = 0; i < 8; i++)
#pragma unroll
            for (int j = 0; j < 4; j++) acc[i][j] = 0.f;
        for (int d = 0; d < 64; d++) {
            float vv[4];
#pragma unroll
            for (int j = 0; j < 4; j++) vv[j] = vc[d*SY + lane + 32*j];
#pragma unroll
            for (int i = 0; i < 8; i++) {
                float a = Ec[(warp*8 + i)*65 + d];
#pragma unroll
                for (int j = 0; j < 4; j++) acc[i][j] = fmaf(a, vv[j], acc[i][j]);
            }
        }
        float* dst = g_av + (size_t)b*CO*VV*TT + (size_t)v*TT;
#pragma unroll
        for (int i = 0; i < 8; i++)
#pragma unroll
            for (int j = 0; j < 4; j++)
                dst[(size_t)(warp*8 + i)*VV*TT + lane + 32*j] = acc[i][j];
    }
}

// ---------------- kernel 3: H-attention per (b,t) ---------------------------
__global__ __launch_bounds__(256) void k_h(
    const float* __restrict__ qw, const float* __restrict__ qb,
    const float* __restrict__ kw, const float* __restrict__ kb,
    const float* __restrict__ vw, const float* __restrict__ vb) {
    int t = blockIdx.x, b = blockIdx.y;
    int tid = threadIdx.x, lane = tid & 31, warp = tid >> 5;
    extern __shared__ float sm[];
    float* ys = sm;                 // [64][SY]  (c x u)
    float* qs = sm + 64*SY;         // [8][SY]   (cq x vrow)
    float* ks = qs + 8*SY;
    float* vs = ks + 8*SY;          // [64][SY]  (c x u)
    float* E  = vs + 64*SY;         // [128][SY] (vrow x u)

    const float* ysrc = g_ytr + ((size_t)b*TT + t)*(CO*VV);
    for (int i = tid; i < 64*128; i += 256) {
        int c = i >> 7, u = i & 127;
        ys[c*SY + u] = ysrc[c*VV + u];
    }
    __syncthreads();
    for (int i = tid; i < 2*8*128; i += 256) {
        int which = i >> 10, e = i & 1023;
        int cq = e >> 7, u = e & 127;
        const float* W = which ? kw : qw;
        float acc = which ? kb[cq] : qb[cq];
#pragma unroll 16
        for (int c = 0; c < 64; c++) acc = fmaf(W[cq*64 + c], ys[c*SY + u], acc);
        (which ? ks : qs)[cq*SY + u] = acc;
    }
    for (int i = tid; i < 64*128; i += 256) {
        int c = i >> 7, u = i & 127;
        float acc = vb[c];
#pragma unroll 16
        for (int cc = 0; cc < 64; cc++) acc = fmaf(vw[c*64 + cc], ys[cc*SY + u], acc);
        vs[c*SY + u] = acc;
    }
    __syncthreads();
    for (int i = tid; i < 128*128; i += 256) {
        int vr = i >> 7, u = i & 127;
        float acc;
        if (vr == u) acc = -1e30f;   // diagonal mask
        else {
            acc = 0.f;
#pragma unroll
            for (int c = 0; c < 8; c++) acc = fmaf(qs[c*SY + vr], ks[c*SY + u], acc);
        }
        E[vr*SY + u] = acc;
    }
    __syncthreads();
    if (tid < 128) {
        int vr = tid;
        float m = -INFINITY;
        for (int u = 0; u < 128; u++) m = fmaxf(m, E[vr*SY + u]);
        float Z = 0.f;
        for (int u = 0; u < 128; u++) { float p = __expf(E[vr*SY + u] - m); E[vr*SY + u] = p; Z += p; }
        g_mH[((size_t)b*VV + vr)*TT + t] = m;
        g_ZH[((size_t)b*VV + vr)*TT + t] = Z;
    }
    __syncthreads();
    {   // O_H[c][vr] = sum_u vs[c][u] * P[vr][u]
        float acc[8][4];
#pragma unroll
        for (int i = 0; i < 8; i++)
#pragma unroll
            for (int j = 0; j < 4; j++) acc[i][j] = 0.f;
        for (int u = 0; u < 128; u++) {
            float pv[4];
#pragma unroll
            for (int j = 0; j < 4; j++) pv[j] = E[(lane + 32*j)*SY + u];
#pragma unroll
            for (int i = 0; i < 8; i++) {
                float vv = vs[(warp*8 + i)*SY + u];
#pragma unroll
                for (int j = 0; j < 4; j++) acc[i][j] = fmaf(vv, pv[j], acc[i][j]);
            }
        }
        float* dst = g_OH + (size_t)b*CO*VV*TT + t;
#pragma unroll
        for (int i = 0; i < 8; i++)
#pragma unroll
            for (int j = 0; j < 4; j++)
                dst[(size_t)(warp*8 + i)*VV*TT + (size_t)(lane + 32*j)*TT] = acc[i][j];
    }
}

// ---------------- kernel 4: 3x3 conv on av + recombine ----------------------
// grid (64 tiles, 4 co-groups, 8 b), threads (16 t, 16 v)
__global__ __launch_bounds__(256) void k_final(
    const float* __restrict__ avw,
    const float* __restrict__ gamma_p, const float* __restrict__ sigma_p,
    float* __restrict__ out) {
    __shared__ float tileS[18][19];
    __shared__ float ws[16*9];
    int b = blockIdx.z, cog = blockIdx.y, tile = blockIdx.x;
    int v0 = (tile >> 3) * 16, t0 = (tile & 7) * 16;
    int tx = threadIdx.x, ty = threadIdx.y;
    int tid = ty*16 + tx;
    int v = v0 + ty, t = t0 + tx;
    float acc[16];
#pragma unroll
    for (int o = 0; o < 16; o++) acc[o] = 0.f;

    for (int ci = 0; ci < 64; ci++) {
        const float* src = g_av + (size_t)(b*CO + ci)*VV*TT;
        for (int i = tid; i < 18*18; i += 256) {
            int r = i / 18, cc = i - r*18;
            int vv2 = v0 - 1 + r, tt2 = t0 - 1 + cc;
            float val = 0.f;
            if (vv2 >= 0 && vv2 < 128 && tt2 >= 0 && tt2 < 128)
                val = src[(size_t)vv2*TT + tt2];
            tileS[r][cc] = val;
        }
        if (tid < 144)
            ws[tid] = avw[(size_t)(cog*16 + tid/9)*(64*9) + ci*9 + (tid % 9)];
        __syncthreads();
        float rv[9];
#pragma unroll
        for (int kr = 0; kr < 3; kr++)
#pragma unroll
            for (int kc2 = 0; kc2 < 3; kc2++)
                rv[kr*3 + kc2] = tileS[ty + kr][tx + kc2];
#pragma unroll
        for (int o = 0; o < 16; o++) {
            float a = acc[o];
#pragma unroll
            for (int kk = 0; kk < 9; kk++) a = fmaf(ws[o*9 + kk], rv[kk], a);
            acc[o] = a;
        }
        __syncthreads();
    }

    float gamma = *gamma_p, sigma = *sigma_p;
    size_t sidx = ((size_t)b*VV + v)*TT + t;
    float mH = g_mH[sidx], ZH = g_ZH[sidx], mW = g_mW[sidx], ZW = g_ZW[sidx];
    float m = fmaxf(mH, mW);
    float eH = __expf(mH - m), eW = __expf(mW - m);
    float inv = gamma / (ZH*eH + ZW*eW);
    float sH = eH * inv, sW = eW * inv;
#pragma unroll
    for (int o = 0; o < 16; o++) {
        size_t idx = (((size_t)b*CO + cog*16 + o)*VV + v)*TT + t;
        out[idx] = g_y[idx] + sH*g_OH[idx] + sW*g_OW[idx] + sigma*acc[o];
    }
}

// ---------------- launch -----------------------------------------------------
extern "C" void kernel_launch(void* const* d_in, const int* in_sizes, int n_in,
                              void* d_out, int out_size) {
    (void)in_sizes; (void)n_in; (void)out_size;
    const float* x    = (const float*)d_in[0];
    const float* dc_w = (const float*)d_in[1];
    const float* dc_b = (const float*)d_in[2];
    const float* q_w  = (const float*)d_in[3];
    const float* q_b  = (const float*)d_in[4];
    const float* k_w  = (const float*)d_in[5];
    const float* k_b  = (const float*)d_in[6];
    const float* v_w  = (const float*)d_in[7];
    const float* v_b  = (const float*)d_in[8];
    const float* gamma= (const float*)d_in[9];
    const float* cq_w = (const float*)d_in[10];
    const float* cq_b = (const float*)d_in[11];
    const float* ck_w = (const float*)d_in[12];
    const float* ck_b = (const float*)d_in[13];
    const float* cv_w = (const float*)d_in[14];
    const float* cv_b = (const float*)d_in[15];
    const float* av_w = (const float*)d_in[16];
    const float* sigma= (const float*)d_in[17];
    float* out = (float*)d_out;

    const int SMEM_WC = (64*SY + 192*SY + 64*65) * 4;   // 148736 B
    const int SMEM_H  = (64*SY + 8*SY + 8*SY + 64*SY + 128*SY) * 4; // 140352 B
    cudaFuncSetAttribute(k_wc, cudaFuncAttributeMaxDynamicSharedMemorySize, SMEM_WC);
    cudaFuncSetAttribute(k_h,  cudaFuncAttributeMaxDynamicSharedMemorySize, SMEM_H);

    k_y  <<<dim3(128, 8), 256>>>(x, dc_w, dc_b);
    k_tr <<<dim3(16, 64, 8), dim3(32, 8)>>>();
    k_wc <<<dim3(128, 8), 256, SMEM_WC>>>(q_w, q_b, k_w, k_b, v_w, v_b,
                                          cq_w, cq_b, ck_w, ck_b, cv_w, cv_b);
    k_h  <<<dim3(128, 8), 256, SMEM_H>>>(q_w, q_b, k_w, k_b, v_w, v_b);
    k_final<<<dim3(64, 4, 8), dim3(16, 16)>>>(av_w, gamma, sigma, out);
}

// round 3
// speedup vs baseline: 1.9866x; 1.9866x over previous
#include <cuda_runtime.h>
#include <math.h>

#define BB 8
#define CIN 256
#define CO 64
#define VV 128
#define TT 128
#define SY 132

__device__ float g_y  [BB*CO*VV*TT];
__device__ float g_ytr[BB*TT*CO*VV];   // y_tr, later reused as OH_tr
__device__ float g_OH [BB*CO*VV*TT];
__device__ float g_OW [BB*CO*VV*TT];
__device__ float g_av [BB*CO*VV*TT];
__device__ float g_mH [BB*VV*TT];
__device__ float g_ZH [BB*VV*TT];
__device__ float g_mW [BB*VV*TT];
__device__ float g_ZW [BB*VV*TT];

__device__ __forceinline__ float4 ld4s(const float* p){ return *reinterpret_cast<const float4*>(p); }
__device__ __forceinline__ void st4s(float* p, float4 v){ *reinterpret_cast<float4*>(p) = v; }
__device__ __forceinline__ float4 ld4g(const float* p){ return __ldg(reinterpret_cast<const float4*>(p)); }
__device__ __forceinline__ float dot4(float4 a, float4 b, float c){
    c = fmaf(a.x,b.x,c); c = fmaf(a.y,b.y,c); c = fmaf(a.z,b.z,c); return fmaf(a.w,b.w,c);
}
__device__ __forceinline__ float4 fma4(float s, float4 v, float4 a){
    a.x=fmaf(s,v.x,a.x); a.y=fmaf(s,v.y,a.y); a.z=fmaf(s,v.z,a.z); a.w=fmaf(s,v.w,a.w); return a;
}

// ---------------- k_y: y = dc_w @ xp + dc_b ----------------
__global__ __launch_bounds__(256) void k_y(const float* __restrict__ x,
                                           const float* __restrict__ w,
                                           const float* __restrict__ bias) {
    __shared__ float xs[32][128];
    __shared__ float ws[64][32];
    int v = blockIdx.x, b = blockIdx.y;
    int tid = threadIdx.x, lane = tid & 31, warp = tid >> 5, t4 = lane*4;
    float4 acc[8];
#pragma unroll
    for (int i = 0; i < 8; i++) acc[i] = make_float4(0.f,0.f,0.f,0.f);
    bool vin = (v >= 1 && v <= 126);
    for (int c0 = 0; c0 < CIN; c0 += 32) {
        for (int i = tid; i < 32*128; i += 256) {
            int ci = i >> 7, t = i & 127;
            float val = 0.f;
            if (vin && t >= 1 && t <= 126)
                val = x[(((size_t)b*CIN + c0 + ci)*126 + (v-1))*126 + (t-1)];
            xs[ci][t] = val;
        }
        for (int i = tid; i < 64*32; i += 256)
            ws[i>>5][i&31] = w[(size_t)(i>>5)*CIN + c0 + (i&31)];
        __syncthreads();
#pragma unroll
        for (int ci = 0; ci < 32; ci++) {
            float4 xv = ld4s(&xs[ci][t4]);
#pragma unroll
            for (int i = 0; i < 8; i++) acc[i] = fma4(ws[warp*8+i][ci], xv, acc[i]);
        }
        __syncthreads();
    }
#pragma unroll
    for (int i = 0; i < 8; i++) {
        int o = warp*8 + i;
        float bo = __ldg(bias + o);
        float4 r = acc[i]; r.x += bo; r.y += bo; r.z += bo; r.w += bo;
        st4s(&g_y[(((size_t)b*CO + o)*VV + v)*TT + t4], r);
    }
}

// ------------- generic 128x128 transpose per (b,c) -------------
// src(r,q) at b*1M + c*sc + r*sr + q ; dst(q,r) at b*1M + c*dc + q*dq + r
__global__ __launch_bounds__(256) void k_tr(const float* __restrict__ src,
                                            float* __restrict__ dst,
                                            int sc, int sr, int dc, int dq) {
    __shared__ float s[32][33];
    int tile = blockIdx.x, c = blockIdx.y, b = blockIdx.z;
    int r0 = (tile >> 2) * 32, q0 = (tile & 3) * 32;
    int tx = threadIdx.x, ty = threadIdx.y;
    const float* sp = src + (size_t)b*1048576 + (size_t)c*sc;
#pragma unroll
    for (int i = 0; i < 32; i += 8) s[ty+i][tx] = sp[(size_t)(r0+ty+i)*sr + q0 + tx];
    __syncthreads();
    float* dp = dst + (size_t)b*1048576 + (size_t)c*dc;
#pragma unroll
    for (int i = 0; i < 32; i += 8) dp[(size_t)(q0+ty+i)*dq + r0 + tx] = s[tx][ty+i];
}

// ------------- shared spatial attention kernel (W / H) -------------
template<bool ISH>
__global__ __launch_bounds__(512, 2) void k_att(
    const float* __restrict__ qw, const float* __restrict__ qb,
    const float* __restrict__ kw, const float* __restrict__ kb,
    const float* __restrict__ vw, const float* __restrict__ vb) {
    int idx = blockIdx.x, b = blockIdx.y;
    int tid = threadIdx.x, lane = tid & 31, warp = tid >> 5, t4 = lane*4;
    extern __shared__ float sm[];
    float* E  = sm;              // [128][SY]
    float* ys = sm;              // alias rows 0..63 until E written
    float* qs = sm + 128*SY;
    float* ks = qs + 8*SY;
    float* vs = ks + 8*SY;       // [64][SY]

    if (ISH) {
        const float* ysrc = g_ytr + (size_t)(b*TT + idx)*8192;
        for (int i = tid*4; i < 8192; i += 2048)
            st4s(ys + (i>>7)*SY + (i&127), ld4g(ysrc + i));
    } else {
        const float* ysrc = g_y + (size_t)b*1048576 + (size_t)idx*TT;
        for (int i = tid; i < 2048; i += 512) {
            int c = i >> 5, tt = (i & 31)*4;
            st4s(ys + c*SY + tt, ld4g(ysrc + (size_t)c*16384 + tt));
        }
    }
    __syncthreads();

    { // vs projection: warp owns 4 c-rows
        int c4 = warp * 4;
        float4 acc[4];
#pragma unroll
        for (int i = 0; i < 4; i++) { float bb = __ldg(vb + c4 + i); acc[i] = make_float4(bb,bb,bb,bb); }
        for (int cc = 0; cc < 64; cc += 4) {
            float4 y0 = ld4s(ys + (cc+0)*SY + t4), y1 = ld4s(ys + (cc+1)*SY + t4);
            float4 y2 = ld4s(ys + (cc+2)*SY + t4), y3 = ld4s(ys + (cc+3)*SY + t4);
#pragma unroll
            for (int i = 0; i < 4; i++) {
                float4 wv = ld4g(vw + (size_t)(c4+i)*64 + cc);
                acc[i] = fma4(wv.x, y0, acc[i]); acc[i] = fma4(wv.y, y1, acc[i]);
                acc[i] = fma4(wv.z, y2, acc[i]); acc[i] = fma4(wv.w, y3, acc[i]);
            }
        }
#pragma unroll
        for (int i = 0; i < 4; i++) st4s(vs + (c4+i)*SY + t4, acc[i]);
    }
    { // q/k projection: warps 0-7 -> q rows, 8-15 -> k rows
        int which = warp >> 3, cq = warp & 7;
        const float* W = which ? kw : qw;
        float b0 = __ldg((which ? kb : qb) + cq);
        float4 acc = make_float4(b0,b0,b0,b0);
        for (int cc = 0; cc < 64; cc += 4) {
            float4 wv = ld4g(W + (size_t)cq*64 + cc);
            acc = fma4(wv.x, ld4s(ys + (cc+0)*SY + t4), acc);
            acc = fma4(wv.y, ld4s(ys + (cc+1)*SY + t4), acc);
            acc = fma4(wv.z, ld4s(ys + (cc+2)*SY + t4), acc);
            acc = fma4(wv.w, ld4s(ys + (cc+3)*SY + t4), acc);
        }
        st4s((which ? ks : qs) + cq*SY + t4, acc);
    }
    __syncthreads();

    { // E[r][s] = sum_c qs[c][r]*ks[c][s] (overwrites ys region)
        int r0 = (tid >> 4) * 4, s0 = (tid & 15) * 8;
        float acc[4][8];
#pragma unroll
        for (int i = 0; i < 4; i++)
#pragma unroll
            for (int j = 0; j < 8; j++) acc[i][j] = 0.f;
#pragma unroll
        for (int c = 0; c < 8; c++) {
            float qv[4];
#pragma unroll
            for (int i = 0; i < 4; i++) qv[i] = qs[c*SY + r0 + i];
            float4 kA = ld4s(ks + c*SY + s0), kB = ld4s(ks + c*SY + s0 + 4);
#pragma unroll
            for (int i = 0; i < 4; i++) {
                acc[i][0]=fmaf(qv[i],kA.x,acc[i][0]); acc[i][1]=fmaf(qv[i],kA.y,acc[i][1]);
                acc[i][2]=fmaf(qv[i],kA.z,acc[i][2]); acc[i][3]=fmaf(qv[i],kA.w,acc[i][3]);
                acc[i][4]=fmaf(qv[i],kB.x,acc[i][4]); acc[i][5]=fmaf(qv[i],kB.y,acc[i][5]);
                acc[i][6]=fmaf(qv[i],kB.z,acc[i][6]); acc[i][7]=fmaf(qv[i],kB.w,acc[i][7]);
            }
        }
#pragma unroll
        for (int i = 0; i < 4; i++) {
            if (ISH) {
#pragma unroll
                for (int j = 0; j < 8; j++) if (r0 + i == s0 + j) acc[i][j] = -1e30f;
            }
            st4s(E + (r0+i)*SY + s0,   make_float4(acc[i][0],acc[i][1],acc[i][2],acc[i][3]));
            st4s(E + (r0+i)*SY + s0+4, make_float4(acc[i][4],acc[i][5],acc[i][6],acc[i][7]));
        }
    }
    __syncthreads();

    { // softmax per row, 4 threads/row
        int r = tid >> 2, sub = tid & 3;
        float* row = E + r*SY;
        float4 x[8]; float m = -INFINITY;
#pragma unroll
        for (int k = 0; k < 8; k++) {
            x[k] = ld4s(row + sub*4 + k*16);
            m = fmaxf(m, fmaxf(fmaxf(x[k].x,x[k].y), fmaxf(x[k].z,x[k].w)));
        }
        m = fmaxf(m, __shfl_xor_sync(~0u, m, 1));
        m = fmaxf(m, __shfl_xor_sync(~0u, m, 2));
        float Z = 0.f;
#pragma unroll
        for (int k = 0; k < 8; k++) {
            x[k].x=__expf(x[k].x-m); x[k].y=__expf(x[k].y-m);
            x[k].z=__expf(x[k].z-m); x[k].w=__expf(x[k].w-m);
            Z += x[k].x + x[k].y + x[k].z + x[k].w;
            st4s(row + sub*4 + k*16, x[k]);
        }
        Z += __shfl_xor_sync(~0u, Z, 1);
        Z += __shfl_xor_sync(~0u, Z, 2);
        if (sub == 0) {
            if (ISH) { g_mH[((size_t)b*VV + r)*TT + idx] = m; g_ZH[((size_t)b*VV + r)*TT + idx] = Z; }
            else     { g_mW[((size_t)b*VV + idx)*TT + r] = m; g_ZW[((size_t)b*VV + idx)*TT + r] = Z; }
        }
    }
    __syncthreads();

    { // apply: O[c][r] = sum_s vs[c][s]*P[r][s]; warp owns 8 r, lane owns c & c+32
        int rb = warp * 8;
        float acc[2][8];
#pragma unroll
        for (int i = 0; i < 2; i++)
#pragma unroll
            for (int j = 0; j < 8; j++) acc[i][j] = 0.f;
        for (int s0 = 0; s0 < 128; s0 += 4) {
            float4 a0 = ld4s(vs + lane*SY + s0);
            float4 a1 = ld4s(vs + (lane+32)*SY + s0);
#pragma unroll
            for (int j = 0; j < 8; j++) {
                float4 p = ld4s(E + (rb+j)*SY + s0);
                acc[0][j] = dot4(a0, p, acc[0][j]);
                acc[1][j] = dot4(a1, p, acc[1][j]);
            }
        }
        if (ISH) { // OH_tr[b][t][c][vr] into g_ytr (own slice)
            float* dst = g_ytr + (size_t)(b*TT + idx)*8192 + rb;
#pragma unroll
            for (int i = 0; i < 2; i++) {
                int c = lane + 32*i;
                st4s(dst + c*128,   make_float4(acc[i][0],acc[i][1],acc[i][2],acc[i][3]));
                st4s(dst + c*128+4, make_float4(acc[i][4],acc[i][5],acc[i][6],acc[i][7]));
            }
        } else {
            float* dst = g_OW + (size_t)b*1048576 + (size_t)idx*TT + rb;
#pragma unroll
            for (int i = 0; i < 2; i++) {
                int c = lane + 32*i;
                st4s(dst + (size_t)c*16384,   make_float4(acc[i][0],acc[i][1],acc[i][2],acc[i][3]));
                st4s(dst + (size_t)c*16384+4, make_float4(acc[i][4],acc[i][5],acc[i][6],acc[i][7]));
            }
        }
    }
}

// ------------- channel attention per (b,v): av = (attn@cvw)@ys + attn@cvb -------------
__global__ __launch_bounds__(512, 2) void k_c(
    const float* __restrict__ cqw, const float* __restrict__ cqb,
    const float* __restrict__ ckw, const float* __restrict__ ckb,
    const float* __restrict__ cvw, const float* __restrict__ cvb) {
    int v = blockIdx.x, b = blockIdx.y;
    int tid = threadIdx.x, lane = tid & 31, warp = tid >> 5, t4 = lane*4;
    extern __shared__ float sm[];
    float* ys = sm;              // [64][SY]
    float* qc = sm + 64*SY;      // [64][SY]; later aliased by M [64][68]
    float* kc = sm + 128*SY;     // [64][SY]; later aliased by Ec [64][68]
    float* bC = sm + 192*SY;     // [64]
    float* Ec = kc;
    float* M  = qc;
    int c4 = warp * 4;

    const float* ysrc = g_y + (size_t)b*1048576 + (size_t)v*TT;
    for (int i = tid; i < 2048; i += 512) {
        int c = i >> 5, tt = (i & 31)*4;
        st4s(ys + c*SY + tt, ld4g(ysrc + (size_t)c*16384 + tt));
    }
    __syncthreads();

    for (int pass = 0; pass < 2; pass++) { // qc, kc projections
        const float* W  = pass ? ckw : cqw;
        const float* Bv = pass ? ckb : cqb;
        float* dstp     = pass ? kc  : qc;
        float4 acc[4];
#pragma unroll
        for (int i = 0; i < 4; i++) { float bb = __ldg(Bv + c4 + i); acc[i] = make_float4(bb,bb,bb,bb); }
        for (int cc = 0; cc < 64; cc += 4) {
            float4 y0 = ld4s(ys + (cc+0)*SY + t4), y1 = ld4s(ys + (cc+1)*SY + t4);
            float4 y2 = ld4s(ys + (cc+2)*SY + t4), y3 = ld4s(ys + (cc+3)*SY + t4);
#pragma unroll
            for (int i = 0; i < 4; i++) {
                float4 wv = ld4g(W + (size_t)(c4+i)*64 + cc);
                acc[i] = fma4(wv.x, y0, acc[i]); acc[i] = fma4(wv.y, y1, acc[i]);
                acc[i] = fma4(wv.z, y2, acc[i]); acc[i] = fma4(wv.w, y3, acc[i]);
            }
        }
#pragma unroll
        for (int i = 0; i < 4; i++) st4s(dstp + (c4+i)*SY + t4, acc[i]);
        __syncthreads();
    }

    { // Ec[c][d] = sum_t qc[c][t]*kc[d][t]; warp: 4 c, lane: d & d+32
        float a0[4], a1[4];
#pragma unroll
        for (int i = 0; i < 4; i++) { a0[i] = 0.f; a1[i] = 0.f; }
        for (int tt = 0; tt < 128; tt += 4) {
            float4 kA = ld4s(kc + lane*SY + tt);
            float4 kB = ld4s(kc + (lane+32)*SY + tt);
#pragma unroll
            for (int i = 0; i < 4; i++) {
                float4 q = ld4s(qc + (c4+i)*SY + tt);
                a0[i] = dot4(q, kA, a0[i]); a1[i] = dot4(q, kB, a1[i]);
            }
        }
        __syncthreads();   // all reads of qc/kc done before aliasing Ec over kc
#pragma unroll
        for (int i = 0; i < 4; i++) { Ec[(c4+i)*68 + lane] = a0[i]; Ec[(c4+i)*68 + lane+32] = a1[i]; }
    }
    __syncthreads();

    { // softmax rows of Ec (8 threads/row), normalized in place
        int r = tid >> 3, sub = tid & 7;
        float* row = Ec + r*68;
        float4 x0 = ld4s(row + sub*4), x1 = ld4s(row + sub*4 + 32);
        float m = fmaxf(fmaxf(fmaxf(x0.x,x0.y),fmaxf(x0.z,x0.w)),
                        fmaxf(fmaxf(x1.x,x1.y),fmaxf(x1.z,x1.w)));
        m = fmaxf(m, __shfl_xor_sync(~0u, m, 1));
        m = fmaxf(m, __shfl_xor_sync(~0u, m, 2));
        m = fmaxf(m, __shfl_xor_sync(~0u, m, 4));
        x0.x=__expf(x0.x-m); x0.y=__expf(x0.y-m); x0.z=__expf(x0.z-m); x0.w=__expf(x0.w-m);
        x1.x=__expf(x1.x-m); x1.y=__expf(x1.y-m); x1.z=__expf(x1.z-m); x1.w=__expf(x1.w-m);
        float Z = x0.x+x0.y+x0.z+x0.w + x1.x+x1.y+x1.z+x1.w;
        Z += __shfl_xor_sync(~0u, Z, 1);
        Z += __shfl_xor_sync(~0u, Z, 2);
        Z += __shfl_xor_sync(~0u, Z, 4);
        float inv = 1.f / Z;
        x0.x*=inv; x0.y*=inv; x0.z*=inv; x0.w*=inv;
        x1.x*=inv; x1.y*=inv; x1.z*=inv; x1.w*=inv;
        st4s(row + sub*4, x0); st4s(row + sub*4 + 32, x1);
    }
    __syncthreads();

    if (tid < 64) { // bC = attn @ cvb
        float a = 0.f;
        for (int d = 0; d < 64; d++) a = fmaf(Ec[tid*68 + d], __ldg(cvb + d), a);
        bC[tid] = a;
    }
    { // M[c][e] = sum_d Ec[c][d]*cvw[d][e]; warp: 4 c, lane: e & e+32
        float a0[4], a1[4];
#pragma unroll
        for (int i = 0; i < 4; i++) { a0[i] = 0.f; a1[i] = 0.f; }
        for (int d = 0; d < 64; d++) {
            float w0 = __ldg(cvw + (size_t)d*64 + lane);
            float w1 = __ldg(cvw + (size_t)d*64 + lane + 32);
#pragma unroll
            for (int i = 0; i < 4; i++) {
                float a = Ec[(c4+i)*68 + d];
                a0[i] = fmaf(a, w0, a0[i]); a1[i] = fmaf(a, w1, a1[i]);
            }
        }
        __syncthreads();   // qc reads were done long ago; ensure bC written too
#pragma unroll
        for (int i = 0; i < 4; i++) { M[(c4+i)*68 + lane] = a0[i]; M[(c4+i)*68 + lane+32] = a1[i]; }
    }
    __syncthreads();

    { // av[c][t] = sum_e M[c][e]*ys[e][t] + bC[c]
        float4 acc[4];
#pragma unroll
        for (int i = 0; i < 4; i++) { float bb = bC[c4+i]; acc[i] = make_float4(bb,bb,bb,bb); }
        for (int e = 0; e < 64; e++) {
            float4 yv = ld4s(ys + e*SY + t4);
#pragma unroll
            for (int i = 0; i < 4; i++) acc[i] = fma4(M[(c4+i)*68 + e], yv, acc[i]);
        }
        float* dst = g_av + (size_t)b*1048576 + (size_t)v*TT;
#pragma unroll
        for (int i = 0; i < 4; i++) st4s(dst + (size_t)(c4+i)*16384 + t4, acc[i]);
    }
}

// ------------- k_final: 3x3 conv on av + recombine -------------
// grid (32 tiles, 4 cog, 8 b), threads (16,16); each thread: 2 pixels x 16 co
__global__ __launch_bounds__(256) void k_final(
    const float* __restrict__ avw,
    const float* __restrict__ gamma_p, const float* __restrict__ sigma_p,
    float* __restrict__ out) {
    __shared__ float tileS[34][19];
    __shared__ float ws[64*144];
    int b = blockIdx.z, cog = blockIdx.y, tile = blockIdx.x;
    int v0 = (tile >> 3) * 32, t0 = (tile & 7) * 16;
    int tx = threadIdx.x, ty = threadIdx.y, tid = ty*16 + tx;

    for (int i = tid; i < 64*144; i += 256) {
        int ci = i / 144, r = i - ci*144;
        ws[i] = __ldg(avw + (size_t)(cog*16 + r/9)*576 + ci*9 + (r % 9));
    }
    float acc[2][16];
#pragma unroll
    for (int p = 0; p < 2; p++)
#pragma unroll
        for (int o = 0; o < 16; o++) acc[p][o] = 0.f;
    __syncthreads();

    for (int ci = 0; ci < 64; ci++) {
        const float* src = g_av + (size_t)(b*CO + ci)*16384;
        for (int i = tid; i < 34*18; i += 256) {
            int r = i / 18, cc = i - r*18;
            int vv = v0 - 1 + r, tt = t0 - 1 + cc;
            float val = 0.f;
            if (vv >= 0 && vv < 128 && tt >= 0 && tt < 128) val = src[(size_t)vv*TT + tt];
            tileS[r][cc] = val;
        }
        __syncthreads();
        float rv0[9], rv1[9];
#pragma unroll
        for (int kr = 0; kr < 3; kr++)
#pragma unroll
            for (int kc2 = 0; kc2 < 3; kc2++) {
                rv0[kr*3+kc2] = tileS[ty + kr][tx + kc2];
                rv1[kr*3+kc2] = tileS[ty + 16 + kr][tx + kc2];
            }
        const float* wp = ws + ci*144;
#pragma unroll
        for (int o = 0; o < 16; o++) {
            float a0 = acc[0][o], a1 = acc[1][o];
#pragma unroll
            for (int kk = 0; kk < 9; kk++) {
                float w = wp[o*9 + kk];
                a0 = fmaf(w, rv0[kk], a0);
                a1 = fmaf(w, rv1[kk], a1);
            }
            acc[0][o] = a0; acc[1][o] = a1;
        }
        __syncthreads();
    }

    float gamma = __ldg(gamma_p), sigma = __ldg(sigma_p);
#pragma unroll
    for (int p = 0; p < 2; p++) {
        int v = v0 + ty + p*16, t = t0 + tx;
        size_t sidx = ((size_t)b*VV + v)*TT + t;
        float mH = g_mH[sidx], ZH = g_ZH[sidx], mW = g_mW[sidx], ZW = g_ZW[sidx];
        float m = fmaxf(mH, mW);
        float eH = __expf(mH - m), eW = __expf(mW - m);
        float inv = gamma / (ZH*eH + ZW*eW);
        float sH = eH * inv, sW = eW * inv;
#pragma unroll
        for (int o = 0; o < 16; o++) {
            size_t idx = (((size_t)b*CO + cog*16 + o)*VV + v)*TT + t;
            out[idx] = g_y[idx] + sH*g_OH[idx] + sW*g_OW[idx] + sigma*acc[p][o];
        }
    }
}

// ---------------- launch ----------------
extern "C" void kernel_launch(void* const* d_in, const int* in_sizes, int n_in,
                              void* d_out, int out_size) {
    (void)in_sizes; (void)n_in; (void)out_size;
    const float* x    = (const float*)d_in[0];
    const float* dc_w = (const float*)d_in[1];
    const float* dc_b = (const float*)d_in[2];
    const float* q_w  = (const float*)d_in[3];
    const float* q_b  = (const float*)d_in[4];
    const float* k_w  = (const float*)d_in[5];
    const float* k_b  = (const float*)d_in[6];
    const float* v_w  = (const float*)d_in[7];
    const float* v_b  = (const float*)d_in[8];
    const float* gamma= (const float*)d_in[9];
    const float* cq_w = (const float*)d_in[10];
    const float* cq_b = (const float*)d_in[11];
    const float* ck_w = (const float*)d_in[12];
    const float* ck_b = (const float*)d_in[13];
    const float* cv_w = (const float*)d_in[14];
    const float* cv_b = (const float*)d_in[15];
    const float* av_w = (const float*)d_in[16];
    const float* sigma= (const float*)d_in[17];
    float* out = (float*)d_out;

    float *py, *pytr, *pOH;
    cudaGetSymbolAddress((void**)&py,   g_y);
    cudaGetSymbolAddress((void**)&pytr, g_ytr);
    cudaGetSymbolAddress((void**)&pOH,  g_OH);

    const int SMEM_ATT = 208*SY*4;           // 109,824 B
    const int SMEM_C   = (192*SY + 64)*4;    // 101,632 B
    static bool attr_done = false;
    if (!attr_done) {
        cudaFuncSetAttribute(k_att<false>, cudaFuncAttributeMaxDynamicSharedMemorySize, SMEM_ATT);
        cudaFuncSetAttribute(k_att<true>,  cudaFuncAttributeMaxDynamicSharedMemorySize, SMEM_ATT);
        cudaFuncSetAttribute(k_c,          cudaFuncAttributeMaxDynamicSharedMemorySize, SMEM_C);
        attr_done = true;
    }

    k_y  <<<dim3(128, 8), 256>>>(x, dc_w, dc_b);
    // y[b][c][v][t] -> y_tr[b][t][c][v]
    k_tr <<<dim3(16, 64, 8), dim3(32, 8)>>>(py, pytr, 16384, 128, 128, 8192);
    k_att<false><<<dim3(128, 8), 512, SMEM_ATT>>>(q_w, q_b, k_w, k_b, v_w, v_b);
    k_att<true> <<<dim3(128, 8), 512, SMEM_ATT>>>(q_w, q_b, k_w, k_b, v_w, v_b);
    k_c  <<<dim3(128, 8), 512, SMEM_C>>>(cq_w, cq_b, ck_w, ck_b, cv_w, cv_b);
    // OH_tr[b][t][c][v] -> OH[b][c][v][t]
    k_tr <<<dim3(16, 64, 8), dim3(32, 8)>>>(pytr, pOH, 128, 8192, 16384, 128);
    k_final<<<dim3(32, 4, 8), dim3(16, 16)>>>(av_w, gamma, sigma, out);
}

// round 4
// speedup vs baseline: 2.1714x; 1.0930x over previous
#include <cuda_runtime.h>
#include <math.h>

#define BB 8
#define CIN 256
#define CO 64
#define VV 128
#define TT 128
#define SY 132

__device__ float g_y  [BB*CO*VV*TT];
__device__ float g_ytr[BB*TT*CO*VV];   // y_tr, later reused as OH_tr
__device__ float g_OH [BB*CO*VV*TT];
__device__ float g_OW [BB*CO*VV*TT];
__device__ float g_av [BB*CO*VV*TT];
__device__ float g_mH [BB*VV*TT];
__device__ float g_ZH [BB*VV*TT];
__device__ float g_mW [BB*VV*TT];
__device__ float g_ZW [BB*VV*TT];
__device__ float g_wtr[9*64*64];       // [tap][ci][o]

typedef unsigned long long u64;

__device__ __forceinline__ float4 ld4s(const float* p){ return *reinterpret_cast<const float4*>(p); }
__device__ __forceinline__ void st4s(float* p, float4 v){ *reinterpret_cast<float4*>(p) = v; }
__device__ __forceinline__ float4 ld4g(const float* p){ return __ldg(reinterpret_cast<const float4*>(p)); }
__device__ __forceinline__ ulonglong2 ld2x2s(const float* p){ return *reinterpret_cast<const ulonglong2*>(p); }
__device__ __forceinline__ void st2x2s(float* p, ulonglong2 v){ *reinterpret_cast<ulonglong2*>(p) = v; }
__device__ __forceinline__ u64 pk2(float x){ u64 r; asm("mov.b64 %0,{%1,%1};" : "=l"(r) : "f"(x)); return r; }
__device__ __forceinline__ u64 pk2two(float lo, float hi){ u64 r; asm("mov.b64 %0,{%1,%2};" : "=l"(r) : "f"(lo), "f"(hi)); return r; }
__device__ __forceinline__ u64 fma2(u64 a, u64 b, u64 c){
    u64 d; asm("fma.rn.f32x2 %0,%1,%2,%3;" : "=l"(d) : "l"(a), "l"(b), "l"(c)); return d;
}
__device__ __forceinline__ float dot4(float4 a, float4 b, float c){
    c = fmaf(a.x,b.x,c); c = fmaf(a.y,b.y,c); c = fmaf(a.z,b.z,c); return fmaf(a.w,b.w,c);
}
__device__ __forceinline__ float4 fma4(float s, float4 v, float4 a){
    a.x=fmaf(s,v.x,a.x); a.y=fmaf(s,v.y,a.y); a.z=fmaf(s,v.z,a.z); a.w=fmaf(s,v.w,a.w); return a;
}

// ---------------- k_y: y = dc_w @ xp + dc_b ----------------
__global__ __launch_bounds__(256) void k_y(const float* __restrict__ x,
                                           const float* __restrict__ w,
                                           const float* __restrict__ bias) {
    __shared__ float xs[32][128];
    __shared__ float ws[64][32];
    int v = blockIdx.x, b = blockIdx.y;
    int tid = threadIdx.x, lane = tid & 31, warp = tid >> 5, t4 = lane*4;
    float4 acc[8];
#pragma unroll
    for (int i = 0; i < 8; i++) acc[i] = make_float4(0.f,0.f,0.f,0.f);
    bool vin = (v >= 1 && v <= 126);
    for (int c0 = 0; c0 < CIN; c0 += 32) {
        for (int i = tid; i < 32*128; i += 256) {
            int ci = i >> 7, t = i & 127;
            float val = 0.f;
            if (vin && t >= 1 && t <= 126)
                val = x[(((size_t)b*CIN + c0 + ci)*126 + (v-1))*126 + (t-1)];
            xs[ci][t] = val;
        }
        for (int i = tid; i < 64*32; i += 256)
            ws[i>>5][i&31] = w[(size_t)(i>>5)*CIN + c0 + (i&31)];
        __syncthreads();
#pragma unroll
        for (int ci = 0; ci < 32; ci++) {
            float4 xv = ld4s(&xs[ci][t4]);
#pragma unroll
            for (int i = 0; i < 8; i++) acc[i] = fma4(ws[warp*8+i][ci], xv, acc[i]);
        }
        __syncthreads();
    }
#pragma unroll
    for (int i = 0; i < 8; i++) {
        int o = warp*8 + i;
        float bo = __ldg(bias + o);
        float4 r = acc[i]; r.x += bo; r.y += bo; r.z += bo; r.w += bo;
        st4s(&g_y[(((size_t)b*CO + o)*VV + v)*TT + t4], r);
    }
}

// ------------- generic 128x128 transpose per (b,c) -------------
__global__ __launch_bounds__(256) void k_tr(const float* __restrict__ src,
                                            float* __restrict__ dst,
                                            int sc, int sr, int dc, int dq) {
    __shared__ float s[32][33];
    int tile = blockIdx.x, c = blockIdx.y, b = blockIdx.z;
    int r0 = (tile >> 2) * 32, q0 = (tile & 3) * 32;
    int tx = threadIdx.x, ty = threadIdx.y;
    const float* sp = src + (size_t)b*1048576 + (size_t)c*sc;
#pragma unroll
    for (int i = 0; i < 32; i += 8) s[ty+i][tx] = sp[(size_t)(r0+ty+i)*sr + q0 + tx];
    __syncthreads();
    float* dp = dst + (size_t)b*1048576 + (size_t)c*dc;
#pragma unroll
    for (int i = 0; i < 32; i += 8) dp[(size_t)(q0+ty+i)*dq + r0 + tx] = s[tx][ty+i];
}

// ---------------- weight transpose for conv: g_wtr[kk][ci][o] ----------------
__global__ __launch_bounds__(256) void k_wt(const float* __restrict__ avw) {
    int i = blockIdx.x*256 + threadIdx.x;   // < 36864
    int kk = i >> 12, ci = (i >> 6) & 63, o = i & 63;
    g_wtr[i] = __ldg(avw + (size_t)o*576 + ci*9 + kk);
}

// ------------- spatial attention (W / H), transposed score matrix -------------
template<bool ISH>
__global__ __launch_bounds__(512, 2) void k_att(
    const float* __restrict__ qw, const float* __restrict__ qb,
    const float* __restrict__ kw, const float* __restrict__ kb,
    const float* __restrict__ vw, const float* __restrict__ vb) {
    int idx = blockIdx.x, b = blockIdx.y;
    int tid = threadIdx.x, lane = tid & 31, warp = tid >> 5, t4 = lane*4;
    extern __shared__ float sm[];
    float* E  = sm;              // E_T[s][t], 128 rows of SY
    float* ys = sm;              // alias rows 0..63 until E written
    float* qs = sm + 128*SY;     // 8 rows
    float* ks = qs + 8*SY;       // 8 rows
    float* vs = ks + 8*SY;       // 64 rows
    float* pm = qs;              // reuse after QK: partial max [4][128]
    float* pz = qs + 512;        // partial sum  [4][128]

    // load ys[c][t]
    if (ISH) {
        const float* ysrc = g_ytr + (size_t)(b*TT + idx)*8192;
        for (int i = tid*4; i < 8192; i += 2048)
            st4s(ys + (i>>7)*SY + (i&127), ld4g(ysrc + i));
    } else {
        const float* ysrc = g_y + (size_t)b*1048576 + (size_t)idx*TT;
        for (int i = tid; i < 2048; i += 512) {
            int c = i >> 5, tt = (i & 31)*4;
            st4s(ys + c*SY + tt, ld4g(ysrc + (size_t)c*16384 + tt));
        }
    }
    __syncthreads();

    { // vs projection (f32x2): warp owns c4, lane owns t4
        int c4 = warp * 4;
        ulonglong2 acc[4];
#pragma unroll
        for (int i = 0; i < 4; i++) { u64 bp = pk2(__ldg(vb + c4 + i)); acc[i].x = bp; acc[i].y = bp; }
        for (int cc = 0; cc < 64; cc += 4) {
            ulonglong2 y0 = ld2x2s(ys + (cc+0)*SY + t4);
            ulonglong2 y1 = ld2x2s(ys + (cc+1)*SY + t4);
            ulonglong2 y2 = ld2x2s(ys + (cc+2)*SY + t4);
            ulonglong2 y3 = ld2x2s(ys + (cc+3)*SY + t4);
#pragma unroll
            for (int i = 0; i < 4; i++) {
                float4 wv = ld4g(vw + (size_t)(c4+i)*64 + cc);
                u64 w0 = pk2(wv.x), w1 = pk2(wv.y), w2 = pk2(wv.z), w3 = pk2(wv.w);
                acc[i].x = fma2(w0, y0.x, acc[i].x); acc[i].y = fma2(w0, y0.y, acc[i].y);
                acc[i].x = fma2(w1, y1.x, acc[i].x); acc[i].y = fma2(w1, y1.y, acc[i].y);
                acc[i].x = fma2(w2, y2.x, acc[i].x); acc[i].y = fma2(w2, y2.y, acc[i].y);
                acc[i].x = fma2(w3, y3.x, acc[i].x); acc[i].y = fma2(w3, y3.y, acc[i].y);
            }
        }
#pragma unroll
        for (int i = 0; i < 4; i++) st2x2s(vs + (c4+i)*SY + t4, acc[i]);
    }
    { // q/k projection (f32x2): warps 0-7 -> q rows, 8-15 -> k rows
        int which = warp >> 3, cq = warp & 7;
        const float* W = which ? kw : qw;
        ulonglong2 acc;
        { u64 bp = pk2(__ldg((which ? kb : qb) + cq)); acc.x = bp; acc.y = bp; }
        for (int cc = 0; cc < 64; cc += 4) {
            float4 wv = ld4g(W + (size_t)cq*64 + cc);
            ulonglong2 y0 = ld2x2s(ys + (cc+0)*SY + t4);
            ulonglong2 y1 = ld2x2s(ys + (cc+1)*SY + t4);
            ulonglong2 y2 = ld2x2s(ys + (cc+2)*SY + t4);
            ulonglong2 y3 = ld2x2s(ys + (cc+3)*SY + t4);
            u64 w0 = pk2(wv.x), w1 = pk2(wv.y), w2 = pk2(wv.z), w3 = pk2(wv.w);
            acc.x = fma2(w0, y0.x, acc.x); acc.y = fma2(w0, y0.y, acc.y);
            acc.x = fma2(w1, y1.x, acc.x); acc.y = fma2(w1, y1.y, acc.y);
            acc.x = fma2(w2, y2.x, acc.x); acc.y = fma2(w2, y2.y, acc.y);
            acc.x = fma2(w3, y3.x, acc.x); acc.y = fma2(w3, y3.y, acc.y);
        }
        st2x2s((which ? ks : qs) + cq*SY + t4, acc);
    }
    __syncthreads();

    { // QK -> E_T[s][t] = sum_c ks[c][s]*qs[c][t]   (overwrites ys region)
        int s0 = (tid >> 4) * 4, t0 = (tid & 15) * 8;
        float acc[4][8];
#pragma unroll
        for (int i = 0; i < 4; i++)
#pragma unroll
            for (int j = 0; j < 8; j++) acc[i][j] = 0.f;
#pragma unroll
        for (int c = 0; c < 8; c++) {
            float kv[4];
#pragma unroll
            for (int i = 0; i < 4; i++) kv[i] = ks[c*SY + s0 + i];
            float4 qA = ld4s(qs + c*SY + t0), qB = ld4s(qs + c*SY + t0 + 4);
#pragma unroll
            for (int i = 0; i < 4; i++) {
                acc[i][0]=fmaf(kv[i],qA.x,acc[i][0]); acc[i][1]=fmaf(kv[i],qA.y,acc[i][1]);
                acc[i][2]=fmaf(kv[i],qA.z,acc[i][2]); acc[i][3]=fmaf(kv[i],qA.w,acc[i][3]);
                acc[i][4]=fmaf(kv[i],qB.x,acc[i][4]); acc[i][5]=fmaf(kv[i],qB.y,acc[i][5]);
                acc[i][6]=fmaf(kv[i],qB.z,acc[i][6]); acc[i][7]=fmaf(kv[i],qB.w,acc[i][7]);
            }
        }
#pragma unroll
        for (int i = 0; i < 4; i++) {
            if (ISH) {
#pragma unroll
                for (int j = 0; j < 8; j++) if (s0 + i == t0 + j) acc[i][j] = -1e30f;
            }
            st4s(E + (s0+i)*SY + t0,   make_float4(acc[i][0],acc[i][1],acc[i][2],acc[i][3]));
            st4s(E + (s0+i)*SY + t0+4, make_float4(acc[i][4],acc[i][5],acc[i][6],acc[i][7]));
        }
    }
    __syncthreads();

    { // softmax over s (rows) for each column t; 4 row-quarters per t
        int t = tid & 127, q = tid >> 7;
        int sbeg = q * 32;
        float m = -INFINITY;
#pragma unroll 8
        for (int s = sbeg; s < sbeg + 32; s++) m = fmaxf(m, E[s*SY + t]);
        pm[q*128 + t] = m;
        __syncthreads();
        float M = fmaxf(fmaxf(pm[t], pm[128+t]), fmaxf(pm[256+t], pm[384+t]));
        float Z = 0.f;
#pragma unroll 8
        for (int s = sbeg; s < sbeg + 32; s++) {
            float p = __expf(E[s*SY + t] - M);
            E[s*SY + t] = p; Z += p;
        }
        pz[q*128 + t] = Z;
        __syncthreads();
        if (q == 0) {
            float Zt = pz[t] + pz[128+t] + pz[256+t] + pz[384+t];
            if (ISH) { g_mH[((size_t)b*VV + t)*TT + idx] = M; g_ZH[((size_t)b*VV + t)*TT + idx] = Zt; }
            else     { g_mW[((size_t)b*VV + idx)*TT + t] = M; g_ZW[((size_t)b*VV + idx)*TT + t] = Zt; }
        }
    }
    __syncthreads();

    { // apply (f32x2): O[c][t] = sum_s vs[c][s] * Eexp[s][t]; warp owns c4, lane owns t4
        int c4 = warp * 4;
        ulonglong2 acc[4];
#pragma unroll
        for (int i = 0; i < 4; i++) { acc[i].x = 0ull; acc[i].y = 0ull; }
        for (int s0 = 0; s0 < 128; s0 += 4) {
            ulonglong2 e0 = ld2x2s(E + (s0+0)*SY + t4);
            ulonglong2 e1 = ld2x2s(E + (s0+1)*SY + t4);
            ulonglong2 e2 = ld2x2s(E + (s0+2)*SY + t4);
            ulonglong2 e3 = ld2x2s(E + (s0+3)*SY + t4);
#pragma unroll
            for (int i = 0; i < 4; i++) {
                float4 vv = ld4s(vs + (c4+i)*SY + s0);   // warp-broadcast
                u64 v0 = pk2(vv.x), v1 = pk2(vv.y), v2 = pk2(vv.z), v3 = pk2(vv.w);
                acc[i].x = fma2(v0, e0.x, acc[i].x); acc[i].y = fma2(v0, e0.y, acc[i].y);
                acc[i].x = fma2(v1, e1.x, acc[i].x); acc[i].y = fma2(v1, e1.y, acc[i].y);
                acc[i].x = fma2(v2, e2.x, acc[i].x); acc[i].y = fma2(v2, e2.y, acc[i].y);
                acc[i].x = fma2(v3, e3.x, acc[i].x); acc[i].y = fma2(v3, e3.y, acc[i].y);
            }
        }
        if (ISH) { // OH_tr[b][t][c][vr]
            float* dst = g_ytr + (size_t)(b*TT + idx)*8192 + t4;
#pragma unroll
            for (int i = 0; i < 4; i++)
                st2x2s(dst + (c4+i)*128, acc[i]);
        } else {   // OW[b][c][v][t]
            float* dst = g_OW + (size_t)b*1048576 + (size_t)idx*TT + t4;
#pragma unroll
            for (int i = 0; i < 4; i++)
                st2x2s(dst + (size_t)(c4+i)*16384, acc[i]);
        }
    }
}

// ------------- channel attention per (b,v): av = (attn@cvw)@ys + attn@cvb -------------
__global__ __launch_bounds__(512, 2) void k_c(
    const float* __restrict__ cqw, const float* __restrict__ cqb,
    const float* __restrict__ ckw, const float* __restrict__ ckb,
    const float* __restrict__ cvw, const float* __restrict__ cvb) {
    int v = blockIdx.x, b = blockIdx.y;
    int tid = threadIdx.x, lane = tid & 31, warp = tid >> 5, t4 = lane*4;
    extern __shared__ float sm[];
    float* ys = sm;              // [64][SY]
    float* qc = sm + 64*SY;      // later aliased by M [64][68]
    float* kc = sm + 128*SY;     // later aliased by Ec [64][68]
    float* bC = sm + 192*SY;     // [64]
    float* Ec = kc;
    float* M  = qc;
    int c4 = warp * 4;

    const float* ysrc = g_y + (size_t)b*1048576 + (size_t)v*TT;
    for (int i = tid; i < 2048; i += 512) {
        int c = i >> 5, tt = (i & 31)*4;
        st4s(ys + c*SY + tt, ld4g(ysrc + (size_t)c*16384 + tt));
    }
    __syncthreads();

    for (int pass = 0; pass < 2; pass++) {
        const float* W  = pass ? ckw : cqw;
        const float* Bv = pass ? ckb : cqb;
        float* dstp     = pass ? kc  : qc;
        float4 acc[4];
#pragma unroll
        for (int i = 0; i < 4; i++) { float bb = __ldg(Bv + c4 + i); acc[i] = make_float4(bb,bb,bb,bb); }
        for (int cc = 0; cc < 64; cc += 4) {
            float4 y0 = ld4s(ys + (cc+0)*SY + t4), y1 = ld4s(ys + (cc+1)*SY + t4);
            float4 y2 = ld4s(ys + (cc+2)*SY + t4), y3 = ld4s(ys + (cc+3)*SY + t4);
#pragma unroll
            for (int i = 0; i < 4; i++) {
                float4 wv = ld4g(W + (size_t)(c4+i)*64 + cc);
                acc[i] = fma4(wv.x, y0, acc[i]); acc[i] = fma4(wv.y, y1, acc[i]);
                acc[i] = fma4(wv.z, y2, acc[i]); acc[i] = fma4(wv.w, y3, acc[i]);
            }
        }
#pragma unroll
        for (int i = 0; i < 4; i++) st4s(dstp + (c4+i)*SY + t4, acc[i]);
        __syncthreads();
    }

    { // Ec[c][d] = sum_t qc[c][t]*kc[d][t]
        float a0[4], a1[4];
#pragma unroll
        for (int i = 0; i < 4; i++) { a0[i] = 0.f; a1[i] = 0.f; }
        for (int tt = 0; tt < 128; tt += 4) {
            float4 kA = ld4s(kc + lane*SY + tt);
            float4 kB = ld4s(kc + (lane+32)*SY + tt);
#pragma unroll
            for (int i = 0; i < 4; i++) {
                float4 q = ld4s(qc + (c4+i)*SY + tt);
                a0[i] = dot4(q, kA, a0[i]); a1[i] = dot4(q, kB, a1[i]);
            }
        }
        __syncthreads();
#pragma unroll
        for (int i = 0; i < 4; i++) { Ec[(c4+i)*68 + lane] = a0[i]; Ec[(c4+i)*68 + lane+32] = a1[i]; }
    }
    __syncthreads();

    { // softmax rows of Ec (8 threads/row)
        int r = tid >> 3, sub = tid & 7;
        float* row = Ec + r*68;
        float4 x0 = ld4s(row + sub*4), x1 = ld4s(row + sub*4 + 32);
        float m = fmaxf(fmaxf(fmaxf(x0.x,x0.y),fmaxf(x0.z,x0.w)),
                        fmaxf(fmaxf(x1.x,x1.y),fmaxf(x1.z,x1.w)));
        m = fmaxf(m, __shfl_xor_sync(~0u, m, 1));
        m = fmaxf(m, __shfl_xor_sync(~0u, m, 2));
        m = fmaxf(m, __shfl_xor_sync(~0u, m, 4));
        x0.x=__expf(x0.x-m); x0.y=__expf(x0.y-m); x0.z=__expf(x0.z-m); x0.w=__expf(x0.w-m);
        x1.x=__expf(x1.x-m); x1.y=__expf(x1.y-m); x1.z=__expf(x1.z-m); x1.w=__expf(x1.w-m);
        float Z = x0.x+x0.y+x0.z+x0.w + x1.x+x1.y+x1.z+x1.w;
        Z += __shfl_xor_sync(~0u, Z, 1);
        Z += __shfl_xor_sync(~0u, Z, 2);
        Z += __shfl_xor_sync(~0u, Z, 4);
        float inv = 1.f / Z;
        x0.x*=inv; x0.y*=inv; x0.z*=inv; x0.w*=inv;
        x1.x*=inv; x1.y*=inv; x1.z*=inv; x1.w*=inv;
        st4s(row + sub*4, x0); st4s(row + sub*4 + 32, x1);
    }
    __syncthreads();

    if (tid < 64) {
        float a = 0.f;
        for (int d = 0; d < 64; d++) a = fmaf(Ec[tid*68 + d], __ldg(cvb + d), a);
        bC[tid] = a;
    }
    { // M[c][e] = sum_d Ec[c][d]*cvw[d][e]
        float a0[4], a1[4];
#pragma unroll
        for (int i = 0; i < 4; i++) { a0[i] = 0.f; a1[i] = 0.f; }
        for (int d = 0; d < 64; d++) {
            float w0 = __ldg(cvw + (size_t)d*64 + lane);
            float w1 = __ldg(cvw + (size_t)d*64 + lane + 32);
#pragma unroll
            for (int i = 0; i < 4; i++) {
                float a = Ec[(c4+i)*68 + d];
                a0[i] = fmaf(a, w0, a0[i]); a1[i] = fmaf(a, w1, a1[i]);
            }
        }
        __syncthreads();
#pragma unroll
        for (int i = 0; i < 4; i++) { M[(c4+i)*68 + lane] = a0[i]; M[(c4+i)*68 + lane+32] = a1[i]; }
    }
    __syncthreads();

    { // av[c][t] = sum_e M[c][e]*ys[e][t] + bC[c]
        float4 acc[4];
#pragma unroll
        for (int i = 0; i < 4; i++) { float bb = bC[c4+i]; acc[i] = make_float4(bb,bb,bb,bb); }
        for (int e = 0; e < 64; e++) {
            float4 yv = ld4s(ys + e*SY + t4);
#pragma unroll
            for (int i = 0; i < 4; i++) acc[i] = fma4(M[(c4+i)*68 + e], yv, acc[i]);
        }
        float* dst = g_av + (size_t)b*1048576 + (size_t)v*TT;
#pragma unroll
        for (int i = 0; i < 4; i++) st4s(dst + (size_t)(c4+i)*16384 + t4, acc[i]);
    }
}

// ------------- k_final: per-tap GEMM 3x3 conv + recombine -------------
// grid (64 tiles of 16x16, 8 b), 256 threads; all 64 co per block
#define AVS 328
__global__ __launch_bounds__(256, 2) void k_final(
    const float* __restrict__ gamma_p, const float* __restrict__ sigma_p,
    float* __restrict__ out) {
    extern __shared__ float smf[];
    float* avs = smf;            // [64][AVS], rows of 18 inside (18x18 halo tile)
    float* ws2 = smf + 64*AVS;   // [64 ci][68] o-fast
    int b = blockIdx.y, tile = blockIdx.x;
    int v0 = (tile >> 3) * 16, t0 = (tile & 7) * 16;
    int tid = threadIdx.x, lane = tid & 31, warp = tid >> 5;
    int o8 = warp * 8;
    int r0 = lane >> 2, c0 = (lane & 3) * 4;

    // stage av halo tiles
    for (int rr = tid; rr < 64*18; rr += 256) {
        int ci = rr / 18, r = rr - ci*18;
        int vv = v0 - 1 + r;
        float* dstp = avs + ci*AVS + r*18;
        if (vv < 0 || vv > 127) {
#pragma unroll
            for (int k = 0; k < 18; k++) dstp[k] = 0.f;
        } else {
            const float* srcp = g_av + (size_t)(b*64 + ci)*16384 + (size_t)vv*128 + (t0 - 1);
#pragma unroll
            for (int k = 0; k < 18; k++) {
                int t = t0 - 1 + k;
                dstp[k] = (t >= 0 && t < 128) ? srcp[k] : 0.f;
            }
        }
    }

    ulonglong2 acc2[8][2];
#pragma unroll
    for (int i = 0; i < 8; i++)
#pragma unroll
        for (int g = 0; g < 2; g++) { acc2[i][g].x = 0ull; acc2[i][g].y = 0ull; }

    for (int kk = 0; kk < 9; kk++) {
        __syncthreads();
        for (int i = tid; i < 4096; i += 256) {
            int ci = i >> 6, o = i & 63;
            ws2[ci*68 + o] = g_wtr[kk*4096 + i];
        }
        __syncthreads();
        int dv = kk / 3, dt = kk - dv*3;
        int base0 = (r0 + dv)*18 + c0 + dt;
        int base1 = (r0 + 8 + dv)*18 + c0 + dt;
        for (int ci = 0; ci < 64; ci++) {
            const float* ar = avs + ci*AVS;
            float a00 = ar[base0], a01 = ar[base0+1], a02 = ar[base0+2], a03 = ar[base0+3];
            float a10 = ar[base1], a11 = ar[base1+1], a12 = ar[base1+2], a13 = ar[base1+3];
            ulonglong2 ap0, ap1;
            ap0.x = pk2two(a00, a01); ap0.y = pk2two(a02, a03);
            ap1.x = pk2two(a10, a11); ap1.y = pk2two(a12, a13);
            const float* wr = ws2 + ci*68 + o8;
#pragma unroll
            for (int oi = 0; oi < 8; oi++) {
                u64 wp = pk2(wr[oi]);   // warp-broadcast
                acc2[oi][0].x = fma2(wp, ap0.x, acc2[oi][0].x);
                acc2[oi][0].y = fma2(wp, ap0.y, acc2[oi][0].y);
                acc2[oi][1].x = fma2(wp, ap1.x, acc2[oi][1].x);
                acc2[oi][1].y = fma2(wp, ap1.y, acc2[oi][1].y);
            }
        }
    }

    // epilogue: out = y + sH*OH + sW*OW + sigma*conv
    float gamma = __ldg(gamma_p), sigma = __ldg(sigma_p);
#pragma unroll
    for (int g = 0; g < 2; g++) {
        int v = v0 + r0 + g*8, t = t0 + c0;
        size_t sidx = ((size_t)b*VV + v)*TT + t;
        float4 mH4 = ld4g(&g_mH[sidx]), ZH4 = ld4g(&g_ZH[sidx]);
        float4 mW4 = ld4g(&g_mW[sidx]), ZW4 = ld4g(&g_ZW[sidx]);
        float sH[4], sW[4];
        {
            float mh[4] = {mH4.x, mH4.y, mH4.z, mH4.w};
            float zh[4] = {ZH4.x, ZH4.y, ZH4.z, ZH4.w};
            float mw[4] = {mW4.x, mW4.y, mW4.z, mW4.w};
            float zw[4] = {ZW4.x, ZW4.y, ZW4.z, ZW4.w};
#pragma unroll
            for (int p = 0; p < 4; p++) {
                float m = fmaxf(mh[p], mw[p]);
                float eH = __expf(mh[p] - m), eW = __expf(mw[p] - m);
                float inv = gamma / (zh[p]*eH + zw[p]*eW);
                sH[p] = eH * inv; sW[p] = eW * inv;
            }
        }
#pragma unroll
        for (int oi = 0; oi < 8; oi++) {
            int o = o8 + oi;
            size_t oidx = (((size_t)b*CO + o)*VV + v)*TT + t;
            float4 yv = ld4g(&g_y[oidx]);
            float4 oh = ld4g(&g_OH[oidx]);
            float4 ow = ld4g(&g_OW[oidx]);
            float2 ca = *reinterpret_cast<float2*>(&acc2[oi][g].x);
            float2 cb = *reinterpret_cast<float2*>(&acc2[oi][g].y);
            float4 r;
            r.x = yv.x + sH[0]*oh.x + sW[0]*ow.x + sigma*ca.x;
            r.y = yv.y + sH[1]*oh.y + sW[1]*ow.y + sigma*ca.y;
            r.z = yv.z + sH[2]*oh.z + sW[2]*ow.z + sigma*cb.x;
            r.w = yv.w + sH[3]*oh.w + sW[3]*ow.w + sigma*cb.y;
            *reinterpret_cast<float4*>(out + oidx) = r;
        }
    }
}

// ---------------- launch ----------------
extern "C" void kernel_launch(void* const* d_in, const int* in_sizes, int n_in,
                              void* d_out, int out_size) {
    (void)in_sizes; (void)n_in; (void)out_size;
    const float* x    = (const float*)d_in[0];
    const float* dc_w = (const float*)d_in[1];
    const float* dc_b = (const float*)d_in[2];
    const float* q_w  = (const float*)d_in[3];
    const float* q_b  = (const float*)d_in[4];
    const float* k_w  = (const float*)d_in[5];
    const float* k_b  = (const float*)d_in[6];
    const float* v_w  = (const float*)d_in[7];
    const float* v_b  = (const float*)d_in[8];
    const float* gamma= (const float*)d_in[9];
    const float* cq_w = (const float*)d_in[10];
    const float* cq_b = (const float*)d_in[11];
    const float* ck_w = (const float*)d_in[12];
    const float* ck_b = (const float*)d_in[13];
    const float* cv_w = (const float*)d_in[14];
    const float* cv_b = (const float*)d_in[15];
    const float* av_w = (const float*)d_in[16];
    const float* sigma= (const float*)d_in[17];
    float* out = (float*)d_out;

    float *py, *pytr, *pOH;
    cudaGetSymbolAddress((void**)&py,   g_y);
    cudaGetSymbolAddress((void**)&pytr, g_ytr);
    cudaGetSymbolAddress((void**)&pOH,  g_OH);

    const int SMEM_ATT = 208*SY*4;             // 109,824 B
    const int SMEM_C   = (192*SY + 64)*4;      // 101,632 B
    const int SMEM_F   = (64*AVS + 64*68)*4;   // 101,376 B
    static bool attr_done = false;
    if (!attr_done) {
        cudaFuncSetAttribute(k_att<false>, cudaFuncAttributeMaxDynamicSharedMemorySize, SMEM_ATT);
        cudaFuncSetAttribute(k_att<true>,  cudaFuncAttributeMaxDynamicSharedMemorySize, SMEM_ATT);
        cudaFuncSetAttribute(k_c,          cudaFuncAttributeMaxDynamicSharedMemorySize, SMEM_C);
        cudaFuncSetAttribute(k_final,      cudaFuncAttributeMaxDynamicSharedMemorySize, SMEM_F);
        attr_done = true;
    }

    k_wt <<<144, 256>>>(av_w);
    k_y  <<<dim3(128, 8), 256>>>(x, dc_w, dc_b);
    k_tr <<<dim3(16, 64, 8), dim3(32, 8)>>>(py, pytr, 16384, 128, 128, 8192);
    k_att<false><<<dim3(128, 8), 512, SMEM_ATT>>>(q_w, q_b, k_w, k_b, v_w, v_b);
    k_att<true> <<<dim3(128, 8), 512, SMEM_ATT>>>(q_w, q_b, k_w, k_b, v_w, v_b);
    k_c  <<<dim3(128, 8), 512, SMEM_C>>>(cq_w, cq_b, ck_w, ck_b, cv_w, cv_b);
    k_tr <<<dim3(16, 64, 8), dim3(32, 8)>>>(pytr, pOH, 128, 8192, 16384, 128);
    k_final<<<dim3(64, 8), 256, SMEM_F>>>(gamma, sigma, out);
}

// round 5
// speedup vs baseline: 2.5121x; 1.1569x over previous
#include <cuda_runtime.h>
#include <math.h>

#define BB 8
#define CIN 256
#define CO 64
#define VV 128
#define TT 128
#define SY 132

__device__ float g_y  [BB*CO*VV*TT];
__device__ float g_ytr[BB*TT*CO*VV];   // y_tr, later reused as OH_tr
__device__ float g_OH [BB*CO*VV*TT];
__device__ float g_OW [BB*CO*VV*TT];
__device__ float g_av [BB*CO*VV*TT];
__device__ float g_mH [BB*VV*TT];
__device__ float g_ZH [BB*VV*TT];
__device__ float g_mW [BB*VV*TT];
__device__ float g_ZW [BB*VV*TT];
__device__ float g_wtr[64*576];        // [ci][kk][o]

typedef unsigned long long u64;

__device__ __forceinline__ float4 ld4s(const float* p){ return *reinterpret_cast<const float4*>(p); }
__device__ __forceinline__ void st4s(float* p, float4 v){ *reinterpret_cast<float4*>(p) = v; }
__device__ __forceinline__ float2 ld2f(const float* p){ return *reinterpret_cast<const float2*>(p); }
__device__ __forceinline__ float4 ld4g(const float* p){ return __ldg(reinterpret_cast<const float4*>(p)); }
__device__ __forceinline__ ulonglong2 ld2x2s(const float* p){ return *reinterpret_cast<const ulonglong2*>(p); }
__device__ __forceinline__ void st2x2s(float* p, ulonglong2 v){ *reinterpret_cast<ulonglong2*>(p) = v; }
__device__ __forceinline__ u64 pk2(float x){ u64 r; asm("mov.b64 %0,{%1,%1};" : "=l"(r) : "f"(x)); return r; }
__device__ __forceinline__ u64 pk2two(float lo, float hi){ u64 r; asm("mov.b64 %0,{%1,%2};" : "=l"(r) : "f"(lo), "f"(hi)); return r; }
__device__ __forceinline__ u64 fma2(u64 a, u64 b, u64 c){
    u64 d; asm("fma.rn.f32x2 %0,%1,%2,%3;" : "=l"(d) : "l"(a), "l"(b), "l"(c)); return d;
}
__device__ __forceinline__ u64 add2(u64 a, u64 b){
    u64 d; asm("add.rn.f32x2 %0,%1,%2;" : "=l"(d) : "l"(a), "l"(b)); return d;
}
__device__ __forceinline__ float dot4(float4 a, float4 b, float c){
    c = fmaf(a.x,b.x,c); c = fmaf(a.y,b.y,c); c = fmaf(a.z,b.z,c); return fmaf(a.w,b.w,c);
}
__device__ __forceinline__ float4 fma4(float s, float4 v, float4 a){
    a.x=fmaf(s,v.x,a.x); a.y=fmaf(s,v.y,a.y); a.z=fmaf(s,v.z,a.z); a.w=fmaf(s,v.w,a.w); return a;
}

// ---------------- k_y: y = dc_w @ xp + dc_b ----------------
__global__ __launch_bounds__(256) void k_y(const float* __restrict__ x,
                                           const float* __restrict__ w,
                                           const float* __restrict__ bias) {
    __shared__ float xs[32][128];
    __shared__ float wsT[32*64];   // [ci][o]
    int v = blockIdx.x, b = blockIdx.y;
    int tid = threadIdx.x, lane = tid & 31, warp = tid >> 5, t4 = lane*4;
    int o8 = warp * 8;
    ulonglong2 acc[8];
#pragma unroll
    for (int i = 0; i < 8; i++) { acc[i].x = 0ull; acc[i].y = 0ull; }
    bool vin = (v >= 1 && v <= 126);
    for (int c0 = 0; c0 < CIN; c0 += 32) {
        for (int i = tid; i < 32*128; i += 256) {
            int ci = i >> 7, t = i & 127;
            float val = 0.f;
            if (vin && t >= 1 && t <= 126)
                val = x[(((size_t)b*CIN + c0 + ci)*126 + (v-1))*126 + (t-1)];
            xs[ci][t] = val;
        }
        for (int i = tid; i < 2048; i += 256)
            wsT[i] = __ldg(w + (size_t)(i & 63)*CIN + c0 + (i >> 6));
        __syncthreads();
#pragma unroll 4
        for (int ci = 0; ci < 32; ci++) {
            ulonglong2 xv = ld2x2s(&xs[ci][t4]);
            float4 wA = ld4s(wsT + ci*64 + o8);
            float4 wB = ld4s(wsT + ci*64 + o8 + 4);
            u64 wp[8] = {pk2(wA.x),pk2(wA.y),pk2(wA.z),pk2(wA.w),
                         pk2(wB.x),pk2(wB.y),pk2(wB.z),pk2(wB.w)};
#pragma unroll
            for (int i = 0; i < 8; i++) {
                acc[i].x = fma2(wp[i], xv.x, acc[i].x);
                acc[i].y = fma2(wp[i], xv.y, acc[i].y);
            }
        }
        __syncthreads();
    }
#pragma unroll
    for (int i = 0; i < 8; i++) {
        int o = o8 + i;
        float bo = __ldg(bias + o);
        float2 lo = *reinterpret_cast<float2*>(&acc[i].x);
        float2 hi = *reinterpret_cast<float2*>(&acc[i].y);
        float4 r = make_float4(lo.x+bo, lo.y+bo, hi.x+bo, hi.y+bo);
        st4s(&g_y[(((size_t)b*CO + o)*VV + v)*TT + t4], r);
    }
}

// ------------- generic 128x128 transpose per (b,c) -------------
__global__ __launch_bounds__(256) void k_tr(const float* __restrict__ src,
                                            float* __restrict__ dst,
                                            int sc, int sr, int dc, int dq) {
    __shared__ float s[32][33];
    int tile = blockIdx.x, c = blockIdx.y, b = blockIdx.z;
    int r0 = (tile >> 2) * 32, q0 = (tile & 3) * 32;
    int tx = threadIdx.x, ty = threadIdx.y;
    const float* sp = src + (size_t)b*1048576 + (size_t)c*sc;
#pragma unroll
    for (int i = 0; i < 32; i += 8) s[ty+i][tx] = sp[(size_t)(r0+ty+i)*sr + q0 + tx];
    __syncthreads();
    float* dp = dst + (size_t)b*1048576 + (size_t)c*dc;
#pragma unroll
    for (int i = 0; i < 32; i += 8) dp[(size_t)(q0+ty+i)*dq + r0 + tx] = s[tx][ty+i];
}

// ---------------- weight transpose for conv: g_wtr[ci][kk][o] ----------------
__global__ __launch_bounds__(256) void k_wt(const float* __restrict__ avw) {
    int i = blockIdx.x*256 + threadIdx.x;   // < 36864
    int ci = i / 576, rem = i - ci*576;
    int kk = rem >> 6, o = rem & 63;
    g_wtr[i] = __ldg(avw + (size_t)o*576 + ci*9 + kk);
}

// ------------- spatial attention (W / H), transposed score matrix -------------
template<bool ISH>
__global__ __launch_bounds__(512, 2) void k_att(
    const float* __restrict__ qw, const float* __restrict__ qb,
    const float* __restrict__ kw, const float* __restrict__ kb,
    const float* __restrict__ vw, const float* __restrict__ vb) {
    int idx = blockIdx.x, b = blockIdx.y;
    int tid = threadIdx.x, lane = tid & 31, warp = tid >> 5, t4 = lane*4;
    extern __shared__ float sm[];
    float* E  = sm;              // E_T[s][t], 128 rows of SY
    float* ys = sm;              // alias rows 0..63 until E written
    float* qs = sm + 128*SY;     // 8 rows
    float* ks = qs + 8*SY;       // 8 rows
    float* vs = ks + 8*SY;       // 64 rows
    float* pm = qs;              // reuse after QK: partial max [4][128]
    float* pz = qs + 512;        // partial sum  [4][128]

    // load ys[c][t]
    if (ISH) {
        const float* ysrc = g_ytr + (size_t)(b*TT + idx)*8192;
        for (int i = tid*4; i < 8192; i += 2048)
            st4s(ys + (i>>7)*SY + (i&127), ld4g(ysrc + i));
    } else {
        const float* ysrc = g_y + (size_t)b*1048576 + (size_t)idx*TT;
        for (int i = tid; i < 2048; i += 512) {
            int c = i >> 5, tt = (i & 31)*4;
            st4s(ys + c*SY + tt, ld4g(ysrc + (size_t)c*16384 + tt));
        }
    }
    __syncthreads();

    { // vs projection (f32x2): warp owns c4, lane owns t4
        int c4 = warp * 4;
        ulonglong2 acc[4];
#pragma unroll
        for (int i = 0; i < 4; i++) { u64 bp = pk2(__ldg(vb + c4 + i)); acc[i].x = bp; acc[i].y = bp; }
        for (int cc = 0; cc < 64; cc += 4) {
            ulonglong2 y0 = ld2x2s(ys + (cc+0)*SY + t4);
            ulonglong2 y1 = ld2x2s(ys + (cc+1)*SY + t4);
            ulonglong2 y2 = ld2x2s(ys + (cc+2)*SY + t4);
            ulonglong2 y3 = ld2x2s(ys + (cc+3)*SY + t4);
#pragma unroll
            for (int i = 0; i < 4; i++) {
                float4 wv = ld4g(vw + (size_t)(c4+i)*64 + cc);
                u64 w0 = pk2(wv.x), w1 = pk2(wv.y), w2 = pk2(wv.z), w3 = pk2(wv.w);
                acc[i].x = fma2(w0, y0.x, acc[i].x); acc[i].y = fma2(w0, y0.y, acc[i].y);
                acc[i].x = fma2(w1, y1.x, acc[i].x); acc[i].y = fma2(w1, y1.y, acc[i].y);
                acc[i].x = fma2(w2, y2.x, acc[i].x); acc[i].y = fma2(w2, y2.y, acc[i].y);
                acc[i].x = fma2(w3, y3.x, acc[i].x); acc[i].y = fma2(w3, y3.y, acc[i].y);
            }
        }
#pragma unroll
        for (int i = 0; i < 4; i++) st2x2s(vs + (c4+i)*SY + t4, acc[i]);
    }
    { // q/k projection (f32x2): warps 0-7 -> q rows, 8-15 -> k rows
        int which = warp >> 3, cq = warp & 7;
        const float* W = which ? kw : qw;
        ulonglong2 acc;
        { u64 bp = pk2(__ldg((which ? kb : qb) + cq)); acc.x = bp; acc.y = bp; }
        for (int cc = 0; cc < 64; cc += 4) {
            float4 wv = ld4g(W + (size_t)cq*64 + cc);
            ulonglong2 y0 = ld2x2s(ys + (cc+0)*SY + t4);
            ulonglong2 y1 = ld2x2s(ys + (cc+1)*SY + t4);
            ulonglong2 y2 = ld2x2s(ys + (cc+2)*SY + t4);
            ulonglong2 y3 = ld2x2s(ys + (cc+3)*SY + t4);
            u64 w0 = pk2(wv.x), w1 = pk2(wv.y), w2 = pk2(wv.z), w3 = pk2(wv.w);
            acc.x = fma2(w0, y0.x, acc.x); acc.y = fma2(w0, y0.y, acc.y);
            acc.x = fma2(w1, y1.x, acc.x); acc.y = fma2(w1, y1.y, acc.y);
            acc.x = fma2(w2, y2.x, acc.x); acc.y = fma2(w2, y2.y, acc.y);
            acc.x = fma2(w3, y3.x, acc.x); acc.y = fma2(w3, y3.y, acc.y);
        }
        st2x2s((which ? ks : qs) + cq*SY + t4, acc);
    }
    __syncthreads();

    { // QK -> E_T[s][t] = sum_c ks[c][s]*qs[c][t]   (overwrites ys region)
        int s0 = (tid >> 4) * 4, t0 = (tid & 15) * 8;
        float acc[4][8];
#pragma unroll
        for (int i = 0; i < 4; i++)
#pragma unroll
            for (int j = 0; j < 8; j++) acc[i][j] = 0.f;
#pragma unroll
        for (int c = 0; c < 8; c++) {
            float kv[4];
#pragma unroll
            for (int i = 0; i < 4; i++) kv[i] = ks[c*SY + s0 + i];
            float4 qA = ld4s(qs + c*SY + t0), qB = ld4s(qs + c*SY + t0 + 4);
#pragma unroll
            for (int i = 0; i < 4; i++) {
                acc[i][0]=fmaf(kv[i],qA.x,acc[i][0]); acc[i][1]=fmaf(kv[i],qA.y,acc[i][1]);
                acc[i][2]=fmaf(kv[i],qA.z,acc[i][2]); acc[i][3]=fmaf(kv[i],qA.w,acc[i][3]);
                acc[i][4]=fmaf(kv[i],qB.x,acc[i][4]); acc[i][5]=fmaf(kv[i],qB.y,acc[i][5]);
                acc[i][6]=fmaf(kv[i],qB.z,acc[i][6]); acc[i][7]=fmaf(kv[i],qB.w,acc[i][7]);
            }
        }
#pragma unroll
        for (int i = 0; i < 4; i++) {
            if (ISH) {
#pragma unroll
                for (int j = 0; j < 8; j++) if (s0 + i == t0 + j) acc[i][j] = -1e30f;
            }
            st4s(E + (s0+i)*SY + t0,   make_float4(acc[i][0],acc[i][1],acc[i][2],acc[i][3]));
            st4s(E + (s0+i)*SY + t0+4, make_float4(acc[i][4],acc[i][5],acc[i][6],acc[i][7]));
        }
    }
    __syncthreads();

    { // softmax over s (rows) for each column t; 4 row-quarters per t
        int t = tid & 127, q = tid >> 7;
        int sbeg = q * 32;
        float m = -INFINITY;
#pragma unroll 8
        for (int s = sbeg; s < sbeg + 32; s++) m = fmaxf(m, E[s*SY + t]);
        pm[q*128 + t] = m;
        __syncthreads();
        float M = fmaxf(fmaxf(pm[t], pm[128+t]), fmaxf(pm[256+t], pm[384+t]));
        float Z = 0.f;
#pragma unroll 8
        for (int s = sbeg; s < sbeg + 32; s++) {
            float p = __expf(E[s*SY + t] - M);
            E[s*SY + t] = p; Z += p;
        }
        pz[q*128 + t] = Z;
        __syncthreads();
        if (q == 0) {
            float Zt = pz[t] + pz[128+t] + pz[256+t] + pz[384+t];
            if (ISH) { g_mH[((size_t)b*VV + t)*TT + idx] = M; g_ZH[((size_t)b*VV + t)*TT + idx] = Zt; }
            else     { g_mW[((size_t)b*VV + idx)*TT + t] = M; g_ZW[((size_t)b*VV + idx)*TT + t] = Zt; }
        }
    }
    __syncthreads();

    { // apply, split-K over s: thread owns 8c x 4t over half the s-range
        int shalf = tid >> 8;              // 0 or 1
        int u = tid & 255;
        int c8 = (u >> 5) * 8;             // warp-uniform
        int ta = (u & 31) * 4;
        int sbase = shalf * 64;
        ulonglong2 acc[8];
#pragma unroll
        for (int i = 0; i < 8; i++) { acc[i].x = 0ull; acc[i].y = 0ull; }
        for (int s0 = sbase; s0 < sbase + 64; s0 += 4) {
            ulonglong2 e0 = ld2x2s(E + (s0+0)*SY + ta);
            ulonglong2 e1 = ld2x2s(E + (s0+1)*SY + ta);
            ulonglong2 e2 = ld2x2s(E + (s0+2)*SY + ta);
            ulonglong2 e3 = ld2x2s(E + (s0+3)*SY + ta);
#pragma unroll
            for (int i = 0; i < 8; i++) {
                float4 vv = ld4s(vs + (c8+i)*SY + s0);   // warp-broadcast
                acc[i].x = fma2(pk2(vv.x), e0.x, acc[i].x); acc[i].y = fma2(pk2(vv.x), e0.y, acc[i].y);
                acc[i].x = fma2(pk2(vv.y), e1.x, acc[i].x); acc[i].y = fma2(pk2(vv.y), e1.y, acc[i].y);
                acc[i].x = fma2(pk2(vv.z), e2.x, acc[i].x); acc[i].y = fma2(pk2(vv.z), e2.y, acc[i].y);
                acc[i].x = fma2(pk2(vv.w), e3.x, acc[i].x); acc[i].y = fma2(pk2(vv.w), e3.y, acc[i].y);
            }
        }
        __syncthreads();
        if (shalf == 1) {
#pragma unroll
            for (int i = 0; i < 8; i++) st2x2s(E + (c8+i)*SY + ta, acc[i]);
        }
        __syncthreads();
        if (shalf == 0) {
#pragma unroll
            for (int i = 0; i < 8; i++) {
                ulonglong2 p = ld2x2s(E + (c8+i)*SY + ta);
                acc[i].x = add2(acc[i].x, p.x);
                acc[i].y = add2(acc[i].y, p.y);
            }
            if (ISH) { // OH_tr[b][t][c][vr]
                float* dst = g_ytr + (size_t)(b*TT + idx)*8192 + ta;
#pragma unroll
                for (int i = 0; i < 8; i++) st2x2s(dst + (c8+i)*128, acc[i]);
            } else {   // OW[b][c][v][t]
                float* dst = g_OW + (size_t)b*1048576 + (size_t)idx*TT + ta;
#pragma unroll
                for (int i = 0; i < 8; i++) st2x2s(dst + (size_t)(c8+i)*16384, acc[i]);
            }
        }
    }
}

// ------------- channel attention per (b,v): av = (attn@cvw)@ys + attn@cvb -------------
__global__ __launch_bounds__(512, 2) void k_c(
    const float* __restrict__ cqw, const float* __restrict__ cqb,
    const float* __restrict__ ckw, const float* __restrict__ ckb,
    const float* __restrict__ cvw, const float* __restrict__ cvb) {
    int v = blockIdx.x, b = blockIdx.y;
    int tid = threadIdx.x, lane = tid & 31, warp = tid >> 5, t4 = lane*4;
    extern __shared__ float sm[];
    float* ys = sm;              // [64][SY]
    float* qc = sm + 64*SY;      // later aliased by M [64][68]
    float* kc = sm + 128*SY;     // later aliased by Ec [64][68]
    float* bC = sm + 192*SY;     // [64]
    float* Ec = kc;
    float* M  = qc;
    int c4 = warp * 4;

    const float* ysrc = g_y + (size_t)b*1048576 + (size_t)v*TT;
    for (int i = tid; i < 2048; i += 512) {
        int c = i >> 5, tt = (i & 31)*4;
        st4s(ys + c*SY + tt, ld4g(ysrc + (size_t)c*16384 + tt));
    }
    __syncthreads();

    for (int pass = 0; pass < 2; pass++) {
        const float* W  = pass ? ckw : cqw;
        const float* Bv = pass ? ckb : cqb;
        float* dstp     = pass ? kc  : qc;
        ulonglong2 acc[4];
#pragma unroll
        for (int i = 0; i < 4; i++) { u64 bp = pk2(__ldg(Bv + c4 + i)); acc[i].x = bp; acc[i].y = bp; }
        for (int cc = 0; cc < 64; cc += 4) {
            ulonglong2 y0 = ld2x2s(ys + (cc+0)*SY + t4);
            ulonglong2 y1 = ld2x2s(ys + (cc+1)*SY + t4);
            ulonglong2 y2 = ld2x2s(ys + (cc+2)*SY + t4);
            ulonglong2 y3 = ld2x2s(ys + (cc+3)*SY + t4);
#pragma unroll
            for (int i = 0; i < 4; i++) {
                float4 wv = ld4g(W + (size_t)(c4+i)*64 + cc);
                u64 w0 = pk2(wv.x), w1 = pk2(wv.y), w2 = pk2(wv.z), w3 = pk2(wv.w);
                acc[i].x = fma2(w0, y0.x, acc[i].x); acc[i].y = fma2(w0, y0.y, acc[i].y);
                acc[i].x = fma2(w1, y1.x, acc[i].x); acc[i].y = fma2(w1, y1.y, acc[i].y);
                acc[i].x = fma2(w2, y2.x, acc[i].x); acc[i].y = fma2(w2, y2.y, acc[i].y);
                acc[i].x = fma2(w3, y3.x, acc[i].x); acc[i].y = fma2(w3, y3.y, acc[i].y);
            }
        }
#pragma unroll
        for (int i = 0; i < 4; i++) st2x2s(dstp + (c4+i)*SY + t4, acc[i]);
        __syncthreads();
    }

    { // Ec[c][d] = sum_t qc[c][t]*kc[d][t]
        float a0[4], a1[4];
#pragma unroll
        for (int i = 0; i < 4; i++) { a0[i] = 0.f; a1[i] = 0.f; }
        for (int tt = 0; tt < 128; tt += 4) {
            float4 kA = ld4s(kc + lane*SY + tt);
            float4 kB = ld4s(kc + (lane+32)*SY + tt);
#pragma unroll
            for (int i = 0; i < 4; i++) {
                float4 q = ld4s(qc + (c4+i)*SY + tt);
                a0[i] = dot4(q, kA, a0[i]); a1[i] = dot4(q, kB, a1[i]);
            }
        }
        __syncthreads();
#pragma unroll
        for (int i = 0; i < 4; i++) { Ec[(c4+i)*68 + lane] = a0[i]; Ec[(c4+i)*68 + lane+32] = a1[i]; }
    }
    __syncthreads();

    { // softmax rows of Ec (8 threads/row)
        int r = tid >> 3, sub = tid & 7;
        float* row = Ec + r*68;
        float4 x0 = ld4s(row + sub*4), x1 = ld4s(row + sub*4 + 32);
        float m = fmaxf(fmaxf(fmaxf(x0.x,x0.y),fmaxf(x0.z,x0.w)),
                        fmaxf(fmaxf(x1.x,x1.y),fmaxf(x1.z,x1.w)));
        m = fmaxf(m, __shfl_xor_sync(~0u, m, 1));
        m = fmaxf(m, __shfl_xor_sync(~0u, m, 2));
        m = fmaxf(m, __shfl_xor_sync(~0u, m, 4));
        x0.x=__expf(x0.x-m); x0.y=__expf(x0.y-m); x0.z=__expf(x0.z-m); x0.w=__expf(x0.w-m);
        x1.x=__expf(x1.x-m); x1.y=__expf(x1.y-m); x1.z=__expf(x1.z-m); x1.w=__expf(x1.w-m);
        float Z = x0.x+x0.y+x0.z+x0.w + x1.x+x1.y+x1.z+x1.w;
        Z += __shfl_xor_sync(~0u, Z, 1);
        Z += __shfl_xor_sync(~0u, Z, 2);
        Z += __shfl_xor_sync(~0u, Z, 4);
        float inv = 1.f / Z;
        x0.x*=inv; x0.y*=inv; x0.z*=inv; x0.w*=inv;
        x1.x*=inv; x1.y*=inv; x1.z*=inv; x1.w*=inv;
        st4s(row + sub*4, x0); st4s(row + sub*4 + 32, x1);
    }
    __syncthreads();

    if (tid < 64) {
        float a = 0.f;
        for (int d = 0; d < 64; d++) a = fmaf(Ec[tid*68 + d], __ldg(cvb + d), a);
        bC[tid] = a;
    }
    { // M[c][e] = sum_d Ec[c][d]*cvw[d][e]
        float a0[4], a1[4];
#pragma unroll
        for (int i = 0; i < 4; i++) { a0[i] = 0.f; a1[i] = 0.f; }
        for (int d = 0; d < 64; d++) {
            float w0 = __ldg(cvw + (size_t)d*64 + lane);
            float w1 = __ldg(cvw + (size_t)d*64 + lane + 32);
#pragma unroll
            for (int i = 0; i < 4; i++) {
                float a = Ec[(c4+i)*68 + d];
                a0[i] = fmaf(a, w0, a0[i]); a1[i] = fmaf(a, w1, a1[i]);
            }
        }
        __syncthreads();
#pragma unroll
        for (int i = 0; i < 4; i++) { M[(c4+i)*68 + lane] = a0[i]; M[(c4+i)*68 + lane+32] = a1[i]; }
    }
    __syncthreads();

    { // av[c][t] = sum_e M[c][e]*ys[e][t] + bC[c]
        ulonglong2 acc[4];
#pragma unroll
        for (int i = 0; i < 4; i++) { u64 bp = pk2(bC[c4+i]); acc[i].x = bp; acc[i].y = bp; }
        for (int e = 0; e < 64; e += 2) {
            ulonglong2 y0 = ld2x2s(ys + (e+0)*SY + t4);
            ulonglong2 y1 = ld2x2s(ys + (e+1)*SY + t4);
#pragma unroll
            for (int i = 0; i < 4; i++) {
                u64 m0 = pk2(M[(c4+i)*68 + e]);
                u64 m1 = pk2(M[(c4+i)*68 + e + 1]);
                acc[i].x = fma2(m0, y0.x, acc[i].x); acc[i].y = fma2(m0, y0.y, acc[i].y);
                acc[i].x = fma2(m1, y1.x, acc[i].x); acc[i].y = fma2(m1, y1.y, acc[i].y);
            }
        }
        float* dst = g_av + (size_t)b*1048576 + (size_t)v*TT;
#pragma unroll
        for (int i = 0; i < 4; i++) st2x2s(dst + (size_t)(c4+i)*16384 + t4, acc[i]);
    }
}

// ------------- k_final: register-window 3x3 conv + recombine -------------
// grid (64 tiles of 16x16, 8 b), 512 threads, ci-chunked staging
#define AVR 20
#define AVC (18*AVR)
__global__ __launch_bounds__(512, 2) void k_final(
    const float* __restrict__ gamma_p, const float* __restrict__ sigma_p,
    float* __restrict__ out) {
    extern __shared__ float smf[];
    float* avs = smf;                 // [16 ci][18 rows][AVR]
    float* wss = smf + 16*AVC;        // [16 ci][9 kk][64 o]
    int b = blockIdx.y, tile = blockIdx.x;
    int v0 = (tile >> 3) * 16, t0 = (tile & 7) * 16;
    int tid = threadIdx.x, lane = tid & 31, warp = tid >> 5;
    int o8 = (warp & 7) * 8;
    int r0 = (lane >> 2) + (warp >> 3) * 8;   // 0..15
    int c0 = (lane & 3) * 4;

    ulonglong2 acc[8];
#pragma unroll
    for (int i = 0; i < 8; i++) { acc[i].x = 0ull; acc[i].y = 0ull; }

    for (int chunk = 0; chunk < 4; chunk++) {
        int ci0 = chunk * 16;
        __syncthreads();
        // stage av halo tiles (16 ci x 18x18)
        for (int i = tid; i < 16*324; i += 512) {
            int ci = i / 324, rr = i - ci*324;
            int r = rr / 18, cc = rr - r*18;
            int vv = v0 - 1 + r, t = t0 - 1 + cc;
            float val = 0.f;
            if (vv >= 0 && vv < 128 && t >= 0 && t < 128)
                val = g_av[(size_t)(b*64 + ci0 + ci)*16384 + (size_t)vv*128 + t];
            avs[ci*AVC + r*AVR + cc] = val;
        }
        // stage weights (contiguous copy)
        for (int i = tid; i < 16*576; i += 512)
            wss[i] = g_wtr[ci0*576 + i];
        __syncthreads();

        for (int ci = 0; ci < 16; ci++) {
            const float* ap = avs + ci*AVC;
            const float* wr = wss + ci*576;
#pragma unroll
            for (int dv = 0; dv < 3; dv++) {
                float4 a4 = ld4s(ap + (r0+dv)*AVR + c0);
                float2 a2 = ld2f(ap + (r0+dv)*AVR + c0 + 4);
                float w6[6] = {a4.x, a4.y, a4.z, a4.w, a2.x, a2.y};
#pragma unroll
                for (int dt = 0; dt < 3; dt++) {
                    int kk = dv*3 + dt;
                    u64 apx = pk2two(w6[dt],   w6[dt+1]);
                    u64 apy = pk2two(w6[dt+2], w6[dt+3]);
                    float4 wA = ld4s(wr + kk*64 + o8);       // broadcast
                    float4 wB = ld4s(wr + kk*64 + o8 + 4);   // broadcast
                    acc[0].x = fma2(pk2(wA.x), apx, acc[0].x); acc[0].y = fma2(pk2(wA.x), apy, acc[0].y);
                    acc[1].x = fma2(pk2(wA.y), apx, acc[1].x); acc[1].y = fma2(pk2(wA.y), apy, acc[1].y);
                    acc[2].x = fma2(pk2(wA.z), apx, acc[2].x); acc[2].y = fma2(pk2(wA.z), apy, acc[2].y);
                    acc[3].x = fma2(pk2(wA.w), apx, acc[3].x); acc[3].y = fma2(pk2(wA.w), apy, acc[3].y);
                    acc[4].x = fma2(pk2(wB.x), apx, acc[4].x); acc[4].y = fma2(pk2(wB.x), apy, acc[4].y);
                    acc[5].x = fma2(pk2(wB.y), apx, acc[5].x); acc[5].y = fma2(pk2(wB.y), apy, acc[5].y);
                    acc[6].x = fma2(pk2(wB.z), apx, acc[6].x); acc[6].y = fma2(pk2(wB.z), apy, acc[6].y);
                    acc[7].x = fma2(pk2(wB.w), apx, acc[7].x); acc[7].y = fma2(pk2(wB.w), apy, acc[7].y);
                }
            }
        }
    }

    // epilogue: out = y + sH*OH + sW*OW + sigma*conv
    float gamma = __ldg(gamma_p), sigma = __ldg(sigma_p);
    int v = v0 + r0, t = t0 + c0;
    size_t sidx = ((size_t)b*VV + v)*TT + t;
    float4 mH4 = ld4g(&g_mH[sidx]), ZH4 = ld4g(&g_ZH[sidx]);
    float4 mW4 = ld4g(&g_mW[sidx]), ZW4 = ld4g(&g_ZW[sidx]);
    float sH[4], sW[4];
    {
        float mh[4] = {mH4.x, mH4.y, mH4.z, mH4.w};
        float zh[4] = {ZH4.x, ZH4.y, ZH4.z, ZH4.w};
        float mw[4] = {mW4.x, mW4.y, mW4.z, mW4.w};
        float zw[4] = {ZW4.x, ZW4.y, ZW4.z, ZW4.w};
#pragma unroll
        for (int p = 0; p < 4; p++) {
            float m = fmaxf(mh[p], mw[p]);
            float eH = __expf(mh[p] - m), eW = __expf(mw[p] - m);
            float inv = gamma / (zh[p]*eH + zw[p]*eW);
            sH[p] = eH * inv; sW[p] = eW * inv;
        }
    }
#pragma unroll
    for (int oi = 0; oi < 8; oi++) {
        int o = o8 + oi;
        size_t oidx = (((size_t)b*CO + o)*VV + v)*TT + t;
        float4 yv = ld4g(&g_y[oidx]);
        float4 oh = ld4g(&g_OH[oidx]);
        float4 ow = ld4g(&g_OW[oidx]);
        float2 ca = *reinterpret_cast<float2*>(&acc[oi].x);
        float2 cb = *reinterpret_cast<float2*>(&acc[oi].y);
        float4 r;
        r.x = yv.x + sH[0]*oh.x + sW[0]*ow.x + sigma*ca.x;
        r.y = yv.y + sH[1]*oh.y + sW[1]*ow.y + sigma*ca.y;
        r.z = yv.z + sH[2]*oh.z + sW[2]*ow.z + sigma*cb.x;
        r.w = yv.w + sH[3]*oh.w + sW[3]*ow.w + sigma*cb.y;
        *reinterpret_cast<float4*>(out + oidx) = r;
    }
}

// ---------------- launch ----------------
extern "C" void kernel_launch(void* const* d_in, const int* in_sizes, int n_in,
                              void* d_out, int out_size) {
    (void)in_sizes; (void)n_in; (void)out_size;
    const float* x    = (const float*)d_in[0];
    const float* dc_w = (const float*)d_in[1];
    const float* dc_b = (const float*)d_in[2];
    const float* q_w  = (const float*)d_in[3];
    const float* q_b  = (const float*)d_in[4];
    const float* k_w  = (const float*)d_in[5];
    const float* k_b  = (const float*)d_in[6];
    const float* v_w  = (const float*)d_in[7];
    const float* v_b  = (const float*)d_in[8];
    const float* gamma= (const float*)d_in[9];
    const float* cq_w = (const float*)d_in[10];
    const float* cq_b = (const float*)d_in[11];
    const float* ck_w = (const float*)d_in[12];
    const float* ck_b = (const float*)d_in[13];
    const float* cv_w = (const float*)d_in[14];
    const float* cv_b = (const float*)d_in[15];
    const float* av_w = (const float*)d_in[16];
    const float* sigma= (const float*)d_in[17];
    float* out = (float*)d_out;

    float *py, *pytr, *pOH;
    cudaGetSymbolAddress((void**)&py,   g_y);
    cudaGetSymbolAddress((void**)&pytr, g_ytr);
    cudaGetSymbolAddress((void**)&pOH,  g_OH);

    const int SMEM_ATT = 208*SY*4;                  // 109,824 B
    const int SMEM_C   = (192*SY + 64)*4;           // 101,632 B
    const int SMEM_F   = (16*AVC + 16*576)*4;       // 59,904 B
    static bool attr_done = false;
    if (!attr_done) {
        cudaFuncSetAttribute(k_att<false>, cudaFuncAttributeMaxDynamicSharedMemorySize, SMEM_ATT);
        cudaFuncSetAttribute(k_att<true>,  cudaFuncAttributeMaxDynamicSharedMemorySize, SMEM_ATT);
        cudaFuncSetAttribute(k_c,          cudaFuncAttributeMaxDynamicSharedMemorySize, SMEM_C);
        cudaFuncSetAttribute(k_final,      cudaFuncAttributeMaxDynamicSharedMemorySize, SMEM_F);
        attr_done = true;
    }

    k_wt <<<144, 256>>>(av_w);
    k_y  <<<dim3(128, 8), 256>>>(x, dc_w, dc_b);
    k_tr <<<dim3(16, 64, 8), dim3(32, 8)>>>(py, pytr, 16384, 128, 128, 8192);
    k_att<false><<<dim3(128, 8), 512, SMEM_ATT>>>(q_w, q_b, k_w, k_b, v_w, v_b);
    k_att<true> <<<dim3(128, 8), 512, SMEM_ATT>>>(q_w, q_b, k_w, k_b, v_w, v_b);
    k_c  <<<dim3(128, 8), 512, SMEM_C>>>(cq_w, cq_b, ck_w, ck_b, cv_w, cv_b);
    k_tr <<<dim3(16, 64, 8), dim3(32, 8)>>>(pytr, pOH, 128, 8192, 16384, 128);
    k_final<<<dim3(64, 8), 512, SMEM_F>>>(gamma, sigma, out);
}

// round 6
// speedup vs baseline: 2.5854x; 1.0292x over previous
#include <cuda_runtime.h>
#include <math.h>

#define BB 8
#define CIN 256
#define CO 64
#define VV 128
#define TT 128
#define SY 132

__device__ float g_y  [BB*CO*VV*TT];
__device__ float g_ytr[BB*TT*CO*VV];   // y_tr, later reused as OH_tr
__device__ float g_OH [BB*CO*VV*TT];
__device__ float g_OW [BB*CO*VV*TT];
__device__ float g_av [BB*CO*VV*TT];
__device__ float g_mH [BB*VV*TT];
__device__ float g_ZH [BB*VV*TT];
__device__ float g_mW [BB*VV*TT];
__device__ float g_ZW [BB*VV*TT];
__device__ float g_wtr[64*576];        // [ci][kk][o]

typedef unsigned long long u64;

__device__ __forceinline__ float4 ld4s(const float* p){ return *reinterpret_cast<const float4*>(p); }
__device__ __forceinline__ void st4s(float* p, float4 v){ *reinterpret_cast<float4*>(p) = v; }
__device__ __forceinline__ float2 ld2f(const float* p){ return *reinterpret_cast<const float2*>(p); }
__device__ __forceinline__ float4 ld4g(const float* p){ return __ldg(reinterpret_cast<const float4*>(p)); }
__device__ __forceinline__ ulonglong2 ld2x2s(const float* p){ return *reinterpret_cast<const ulonglong2*>(p); }
__device__ __forceinline__ void st2x2s(float* p, ulonglong2 v){ *reinterpret_cast<ulonglong2*>(p) = v; }
__device__ __forceinline__ u64 pk2(float x){ u64 r; asm("mov.b64 %0,{%1,%1};" : "=l"(r) : "f"(x)); return r; }
__device__ __forceinline__ u64 pk2two(float lo, float hi){ u64 r; asm("mov.b64 %0,{%1,%2};" : "=l"(r) : "f"(lo), "f"(hi)); return r; }
__device__ __forceinline__ float2 up2(u64 a){ float2 f; asm("mov.b64 {%0,%1},%2;" : "=f"(f.x), "=f"(f.y) : "l"(a)); return f; }
__device__ __forceinline__ u64 fma2(u64 a, u64 b, u64 c){
    u64 d; asm("fma.rn.f32x2 %0,%1,%2,%3;" : "=l"(d) : "l"(a), "l"(b), "l"(c)); return d;
}
__device__ __forceinline__ u64 add2(u64 a, u64 b){
    u64 d; asm("add.rn.f32x2 %0,%1,%2;" : "=l"(d) : "l"(a), "l"(b)); return d;
}
__device__ __forceinline__ float dot4(float4 a, float4 b, float c){
    c = fmaf(a.x,b.x,c); c = fmaf(a.y,b.y,c); c = fmaf(a.z,b.z,c); return fmaf(a.w,b.w,c);
}
__device__ __forceinline__ float4 fma4(float s, float4 v, float4 a){
    a.x=fmaf(s,v.x,a.x); a.y=fmaf(s,v.y,a.y); a.z=fmaf(s,v.z,a.z); a.w=fmaf(s,v.w,a.w); return a;
}

// ---------------- k_y: y = dc_w @ xp + dc_b ----------------
__global__ __launch_bounds__(256) void k_y(const float* __restrict__ x,
                                           const float* __restrict__ w,
                                           const float* __restrict__ bias) {
    __shared__ float xs[32][128];
    __shared__ float wsT[32*64];   // [ci][o]
    int v = blockIdx.x, b = blockIdx.y;
    int tid = threadIdx.x, lane = tid & 31, warp = tid >> 5, t4 = lane*4;
    int o8 = warp * 8;
    ulonglong2 acc[8];
#pragma unroll
    for (int i = 0; i < 8; i++) { acc[i].x = 0ull; acc[i].y = 0ull; }
    bool vin = (v >= 1 && v <= 126);
    for (int c0 = 0; c0 < CIN; c0 += 32) {
        for (int i = tid; i < 32*128; i += 256) {
            int ci = i >> 7, t = i & 127;
            float val = 0.f;
            if (vin && t >= 1 && t <= 126)
                val = x[(((size_t)b*CIN + c0 + ci)*126 + (v-1))*126 + (t-1)];
            xs[ci][t] = val;
        }
        for (int i = tid; i < 2048; i += 256)
            wsT[i] = __ldg(w + (size_t)(i & 63)*CIN + c0 + (i >> 6));
        __syncthreads();
#pragma unroll 4
        for (int ci = 0; ci < 32; ci++) {
            ulonglong2 xv = ld2x2s(&xs[ci][t4]);
            float4 wA = ld4s(wsT + ci*64 + o8);
            float4 wB = ld4s(wsT + ci*64 + o8 + 4);
            u64 wp[8] = {pk2(wA.x),pk2(wA.y),pk2(wA.z),pk2(wA.w),
                         pk2(wB.x),pk2(wB.y),pk2(wB.z),pk2(wB.w)};
#pragma unroll
            for (int i = 0; i < 8; i++) {
                acc[i].x = fma2(wp[i], xv.x, acc[i].x);
                acc[i].y = fma2(wp[i], xv.y, acc[i].y);
            }
        }
        __syncthreads();
    }
#pragma unroll
    for (int i = 0; i < 8; i++) {
        int o = o8 + i;
        float bo = __ldg(bias + o);
        float2 lo = up2(acc[i].x);
        float2 hi = up2(acc[i].y);
        float4 r = make_float4(lo.x+bo, lo.y+bo, hi.x+bo, hi.y+bo);
        st4s(&g_y[(((size_t)b*CO + o)*VV + v)*TT + t4], r);
    }
}

// ------------- generic 128x128 transpose per (b,c) -------------
__global__ __launch_bounds__(256) void k_tr(const float* __restrict__ src,
                                            float* __restrict__ dst,
                                            int sc, int sr, int dc, int dq) {
    __shared__ float s[32][33];
    int tile = blockIdx.x, c = blockIdx.y, b = blockIdx.z;
    int r0 = (tile >> 2) * 32, q0 = (tile & 3) * 32;
    int tx = threadIdx.x, ty = threadIdx.y;
    const float* sp = src + (size_t)b*1048576 + (size_t)c*sc;
#pragma unroll
    for (int i = 0; i < 32; i += 8) s[ty+i][tx] = sp[(size_t)(r0+ty+i)*sr + q0 + tx];
    __syncthreads();
    float* dp = dst + (size_t)b*1048576 + (size_t)c*dc;
#pragma unroll
    for (int i = 0; i < 32; i += 8) dp[(size_t)(q0+ty+i)*dq + r0 + tx] = s[tx][ty+i];
}

// ---------------- weight transpose for conv: g_wtr[ci][kk][o] ----------------
__global__ __launch_bounds__(256) void k_wt(const float* __restrict__ avw) {
    int i = blockIdx.x*256 + threadIdx.x;   // < 36864
    int ci = i / 576, rem = i - ci*576;
    int kk = rem >> 6, o = rem & 63;
    g_wtr[i] = __ldg(avw + (size_t)o*576 + ci*9 + kk);
}

// ------------- spatial attention (W / H), transposed score matrix -------------
template<bool ISH>
__global__ __launch_bounds__(512, 2) void k_att(
    const float* __restrict__ qw, const float* __restrict__ qb,
    const float* __restrict__ kw, const float* __restrict__ kb,
    const float* __restrict__ vw, const float* __restrict__ vb) {
    int idx = blockIdx.x, b = blockIdx.y;
    int tid = threadIdx.x, lane = tid & 31, warp = tid >> 5, t4 = lane*4;
    extern __shared__ float sm[];
    float* E  = sm;              // E_T[s][t], 128 rows of SY
    float* ys = sm;              // alias rows 0..63 until E written
    float* qs = sm + 128*SY;     // 8 rows
    float* ks = qs + 8*SY;       // 8 rows
    float* vs = ks + 8*SY;       // 64 rows
    float* pm = qs;              // reuse after QK: partial max [4][128]
    float* pz = qs + 512;        // partial sum  [4][128]

    // load ys[c][t]
    if (ISH) {
        const float* ysrc = g_ytr + (size_t)(b*TT + idx)*8192;
        for (int i = tid*4; i < 8192; i += 2048)
            st4s(ys + (i>>7)*SY + (i&127), ld4g(ysrc + i));
    } else {
        const float* ysrc = g_y + (size_t)b*1048576 + (size_t)idx*TT;
        for (int i = tid; i < 2048; i += 512) {
            int c = i >> 5, tt = (i & 31)*4;
            st4s(ys + c*SY + tt, ld4g(ysrc + (size_t)c*16384 + tt));
        }
    }
    __syncthreads();

    { // FUSED q/k/v projection: ONE pass over ys.
      // warp owns 4 v-rows (c4..c4+3) AND one q-or-k row (cq).
        int c4 = warp * 4;
        int which = warp >> 3, cq = warp & 7;
        const float* Wqk = which ? kw : qw;
        ulonglong2 acc[4], qa;
#pragma unroll
        for (int i = 0; i < 4; i++) { u64 bp = pk2(__ldg(vb + c4 + i)); acc[i].x = bp; acc[i].y = bp; }
        { u64 bp = pk2(__ldg((which ? kb : qb) + cq)); qa.x = bp; qa.y = bp; }
        for (int cc = 0; cc < 64; cc += 4) {
            ulonglong2 y0 = ld2x2s(ys + (cc+0)*SY + t4);
            ulonglong2 y1 = ld2x2s(ys + (cc+1)*SY + t4);
            ulonglong2 y2 = ld2x2s(ys + (cc+2)*SY + t4);
            ulonglong2 y3 = ld2x2s(ys + (cc+3)*SY + t4);
            float4 wq = ld4g(Wqk + (size_t)cq*64 + cc);
            qa.x = fma2(pk2(wq.x), y0.x, qa.x); qa.y = fma2(pk2(wq.x), y0.y, qa.y);
            qa.x = fma2(pk2(wq.y), y1.x, qa.x); qa.y = fma2(pk2(wq.y), y1.y, qa.y);
            qa.x = fma2(pk2(wq.z), y2.x, qa.x); qa.y = fma2(pk2(wq.z), y2.y, qa.y);
            qa.x = fma2(pk2(wq.w), y3.x, qa.x); qa.y = fma2(pk2(wq.w), y3.y, qa.y);
#pragma unroll
            for (int i = 0; i < 4; i++) {
                float4 wv = ld4g(vw + (size_t)(c4+i)*64 + cc);
                acc[i].x = fma2(pk2(wv.x), y0.x, acc[i].x); acc[i].y = fma2(pk2(wv.x), y0.y, acc[i].y);
                acc[i].x = fma2(pk2(wv.y), y1.x, acc[i].x); acc[i].y = fma2(pk2(wv.y), y1.y, acc[i].y);
                acc[i].x = fma2(pk2(wv.z), y2.x, acc[i].x); acc[i].y = fma2(pk2(wv.z), y2.y, acc[i].y);
                acc[i].x = fma2(pk2(wv.w), y3.x, acc[i].x); acc[i].y = fma2(pk2(wv.w), y3.y, acc[i].y);
            }
        }
#pragma unroll
        for (int i = 0; i < 4; i++) st2x2s(vs + (c4+i)*SY + t4, acc[i]);
        st2x2s((which ? ks : qs) + cq*SY + t4, qa);
    }
    __syncthreads();

    { // QK (f32x2) -> E_T[s][t] = sum_c ks[c][s]*qs[c][t]   (overwrites ys region)
        int s0 = (tid >> 4) * 4, t0 = (tid & 15) * 8;
        u64 acc[4][4];
#pragma unroll
        for (int i = 0; i < 4; i++)
#pragma unroll
            for (int j = 0; j < 4; j++) acc[i][j] = 0ull;
#pragma unroll
        for (int c = 0; c < 8; c++) {
            float kv[4];
#pragma unroll
            for (int i = 0; i < 4; i++) kv[i] = ks[c*SY + s0 + i];
            ulonglong2 qA = ld2x2s(qs + c*SY + t0);
            ulonglong2 qB = ld2x2s(qs + c*SY + t0 + 4);
#pragma unroll
            for (int i = 0; i < 4; i++) {
                u64 kp = pk2(kv[i]);
                acc[i][0] = fma2(kp, qA.x, acc[i][0]);
                acc[i][1] = fma2(kp, qA.y, acc[i][1]);
                acc[i][2] = fma2(kp, qB.x, acc[i][2]);
                acc[i][3] = fma2(kp, qB.y, acc[i][3]);
            }
        }
#pragma unroll
        for (int i = 0; i < 4; i++) {
            float2 p0 = up2(acc[i][0]), p1 = up2(acc[i][1]);
            float2 p2 = up2(acc[i][2]), p3 = up2(acc[i][3]);
            float vals[8] = {p0.x,p0.y,p1.x,p1.y,p2.x,p2.y,p3.x,p3.y};
            if (ISH) {
                int d = s0 + i - t0;
                if (d >= 0 && d < 8) vals[d] = -1e30f;
            }
            st4s(E + (s0+i)*SY + t0,   make_float4(vals[0],vals[1],vals[2],vals[3]));
            st4s(E + (s0+i)*SY + t0+4, make_float4(vals[4],vals[5],vals[6],vals[7]));
        }
    }
    __syncthreads();

    { // softmax over s (rows) for each column t; 4 row-quarters per t
        int t = tid & 127, q = tid >> 7;
        int sbeg = q * 32;
        float m = -INFINITY;
#pragma unroll 8
        for (int s = sbeg; s < sbeg + 32; s++) m = fmaxf(m, E[s*SY + t]);
        pm[q*128 + t] = m;
        __syncthreads();
        float M = fmaxf(fmaxf(pm[t], pm[128+t]), fmaxf(pm[256+t], pm[384+t]));
        float Z = 0.f;
#pragma unroll 8
        for (int s = sbeg; s < sbeg + 32; s++) {
            float p = __expf(E[s*SY + t] - M);
            E[s*SY + t] = p; Z += p;
        }
        pz[q*128 + t] = Z;
        __syncthreads();
        if (q == 0) {
            float Zt = pz[t] + pz[128+t] + pz[256+t] + pz[384+t];
            if (ISH) { g_mH[((size_t)b*VV + t)*TT + idx] = M; g_ZH[((size_t)b*VV + t)*TT + idx] = Zt; }
            else     { g_mW[((size_t)b*VV + idx)*TT + t] = M; g_ZW[((size_t)b*VV + idx)*TT + t] = Zt; }
        }
    }
    __syncthreads();

    { // apply, split-K over s: thread owns 8c x 4t over half the s-range
        int shalf = tid >> 8;              // 0 or 1
        int u = tid & 255;
        int c8 = (u >> 5) * 8;             // warp-uniform
        int ta = (u & 31) * 4;
        int sbase = shalf * 64;
        ulonglong2 acc[8];
#pragma unroll
        for (int i = 0; i < 8; i++) { acc[i].x = 0ull; acc[i].y = 0ull; }
        for (int s0 = sbase; s0 < sbase + 64; s0 += 4) {
            ulonglong2 e0 = ld2x2s(E + (s0+0)*SY + ta);
            ulonglong2 e1 = ld2x2s(E + (s0+1)*SY + ta);
            ulonglong2 e2 = ld2x2s(E + (s0+2)*SY + ta);
            ulonglong2 e3 = ld2x2s(E + (s0+3)*SY + ta);
#pragma unroll
            for (int i = 0; i < 8; i++) {
                float4 vv = ld4s(vs + (c8+i)*SY + s0);   // warp-broadcast
                acc[i].x = fma2(pk2(vv.x), e0.x, acc[i].x); acc[i].y = fma2(pk2(vv.x), e0.y, acc[i].y);
                acc[i].x = fma2(pk2(vv.y), e1.x, acc[i].x); acc[i].y = fma2(pk2(vv.y), e1.y, acc[i].y);
                acc[i].x = fma2(pk2(vv.z), e2.x, acc[i].x); acc[i].y = fma2(pk2(vv.z), e2.y, acc[i].y);
                acc[i].x = fma2(pk2(vv.w), e3.x, acc[i].x); acc[i].y = fma2(pk2(vv.w), e3.y, acc[i].y);
            }
        }
        __syncthreads();
        if (shalf == 1) {
#pragma unroll
            for (int i = 0; i < 8; i++) st2x2s(E + (c8+i)*SY + ta, acc[i]);
        }
        __syncthreads();
        if (shalf == 0) {
#pragma unroll
            for (int i = 0; i < 8; i++) {
                ulonglong2 p = ld2x2s(E + (c8+i)*SY + ta);
                acc[i].x = add2(acc[i].x, p.x);
                acc[i].y = add2(acc[i].y, p.y);
            }
            if (ISH) { // OH_tr[b][t][c][vr]
                float* dst = g_ytr + (size_t)(b*TT + idx)*8192 + ta;
#pragma unroll
                for (int i = 0; i < 8; i++) st2x2s(dst + (c8+i)*128, acc[i]);
            } else {   // OW[b][c][v][t]
                float* dst = g_OW + (size_t)b*1048576 + (size_t)idx*TT + ta;
#pragma unroll
                for (int i = 0; i < 8; i++) st2x2s(dst + (size_t)(c8+i)*16384, acc[i]);
            }
        }
    }
}

// ------------- channel attention per (b,v): av = (attn@cvw)@ys + attn@cvb -------------
__global__ __launch_bounds__(512, 2) void k_c(
    const float* __restrict__ cqw, const float* __restrict__ cqb,
    const float* __restrict__ ckw, const float* __restrict__ ckb,
    const float* __restrict__ cvw, const float* __restrict__ cvb) {
    int v = blockIdx.x, b = blockIdx.y;
    int tid = threadIdx.x, lane = tid & 31, warp = tid >> 5, t4 = lane*4;
    extern __shared__ float sm[];
    float* ys = sm;              // [64][SY]
    float* qc = sm + 64*SY;      // later aliased by M [64][68]
    float* kc = sm + 128*SY;     // later aliased by Ec [64][68]
    float* bC = sm + 192*SY;     // [64]
    float* Ec = kc;
    float* M  = qc;
    int c4 = warp * 4;

    const float* ysrc = g_y + (size_t)b*1048576 + (size_t)v*TT;
    for (int i = tid; i < 2048; i += 512) {
        int c = i >> 5, tt = (i & 31)*4;
        st4s(ys + c*SY + tt, ld4g(ysrc + (size_t)c*16384 + tt));
    }
    __syncthreads();

    { // FUSED qc+kc projection: one ys pass, warp owns 4 rows of each
        ulonglong2 qa[4], ka[4];
#pragma unroll
        for (int i = 0; i < 4; i++) {
            u64 bq = pk2(__ldg(cqb + c4 + i)); qa[i].x = bq; qa[i].y = bq;
            u64 bk = pk2(__ldg(ckb + c4 + i)); ka[i].x = bk; ka[i].y = bk;
        }
        for (int cc = 0; cc < 64; cc += 2) {
            ulonglong2 y0 = ld2x2s(ys + (cc+0)*SY + t4);
            ulonglong2 y1 = ld2x2s(ys + (cc+1)*SY + t4);
#pragma unroll
            for (int i = 0; i < 4; i++) {
                float2 wq = __ldg(reinterpret_cast<const float2*>(cqw + (size_t)(c4+i)*64 + cc));
                float2 wk = __ldg(reinterpret_cast<const float2*>(ckw + (size_t)(c4+i)*64 + cc));
                qa[i].x = fma2(pk2(wq.x), y0.x, qa[i].x); qa[i].y = fma2(pk2(wq.x), y0.y, qa[i].y);
                qa[i].x = fma2(pk2(wq.y), y1.x, qa[i].x); qa[i].y = fma2(pk2(wq.y), y1.y, qa[i].y);
                ka[i].x = fma2(pk2(wk.x), y0.x, ka[i].x); ka[i].y = fma2(pk2(wk.x), y0.y, ka[i].y);
                ka[i].x = fma2(pk2(wk.y), y1.x, ka[i].x); ka[i].y = fma2(pk2(wk.y), y1.y, ka[i].y);
            }
        }
#pragma unroll
        for (int i = 0; i < 4; i++) {
            st2x2s(qc + (c4+i)*SY + t4, qa[i]);
            st2x2s(kc + (c4+i)*SY + t4, ka[i]);
        }
    }
    __syncthreads();

    { // Ec[c][d] = sum_t qc[c][t]*kc[d][t]
        float a0[4], a1[4];
#pragma unroll
        for (int i = 0; i < 4; i++) { a0[i] = 0.f; a1[i] = 0.f; }
        for (int tt = 0; tt < 128; tt += 4) {
            float4 kA = ld4s(kc + lane*SY + tt);
            float4 kB = ld4s(kc + (lane+32)*SY + tt);
#pragma unroll
            for (int i = 0; i < 4; i++) {
                float4 q = ld4s(qc + (c4+i)*SY + tt);
                a0[i] = dot4(q, kA, a0[i]); a1[i] = dot4(q, kB, a1[i]);
            }
        }
        __syncthreads();
#pragma unroll
        for (int i = 0; i < 4; i++) { Ec[(c4+i)*68 + lane] = a0[i]; Ec[(c4+i)*68 + lane+32] = a1[i]; }
    }
    __syncthreads();

    { // softmax rows of Ec (8 threads/row)
        int r = tid >> 3, sub = tid & 7;
        float* row = Ec + r*68;
        float4 x0 = ld4s(row + sub*4), x1 = ld4s(row + sub*4 + 32);
        float m = fmaxf(fmaxf(fmaxf(x0.x,x0.y),fmaxf(x0.z,x0.w)),
                        fmaxf(fmaxf(x1.x,x1.y),fmaxf(x1.z,x1.w)));
        m = fmaxf(m, __shfl_xor_sync(~0u, m, 1));
        m = fmaxf(m, __shfl_xor_sync(~0u, m, 2));
        m = fmaxf(m, __shfl_xor_sync(~0u, m, 4));
        x0.x=__expf(x0.x-m); x0.y=__expf(x0.y-m); x0.z=__expf(x0.z-m); x0.w=__expf(x0.w-m);
        x1.x=__expf(x1.x-m); x1.y=__expf(x1.y-m); x1.z=__expf(x1.z-m); x1.w=__expf(x1.w-m);
        float Z = x0.x+x0.y+x0.z+x0.w + x1.x+x1.y+x1.z+x1.w;
        Z += __shfl_xor_sync(~0u, Z, 1);
        Z += __shfl_xor_sync(~0u, Z, 2);
        Z += __shfl_xor_sync(~0u, Z, 4);
        float inv = 1.f / Z;
        x0.x*=inv; x0.y*=inv; x0.z*=inv; x0.w*=inv;
        x1.x*=inv; x1.y*=inv; x1.z*=inv; x1.w*=inv;
        st4s(row + sub*4, x0); st4s(row + sub*4 + 32, x1);
    }
    __syncthreads();

    if (tid < 64) {
        float a = 0.f;
        for (int d = 0; d < 64; d++) a = fmaf(Ec[tid*68 + d], __ldg(cvb + d), a);
        bC[tid] = a;
    }
    { // M[c][e] = sum_d Ec[c][d]*cvw[d][e]
        float a0[4], a1[4];
#pragma unroll
        for (int i = 0; i < 4; i++) { a0[i] = 0.f; a1[i] = 0.f; }
        for (int d = 0; d < 64; d++) {
            float w0 = __ldg(cvw + (size_t)d*64 + lane);
            float w1 = __ldg(cvw + (size_t)d*64 + lane + 32);
#pragma unroll
            for (int i = 0; i < 4; i++) {
                float a = Ec[(c4+i)*68 + d];
                a0[i] = fmaf(a, w0, a0[i]); a1[i] = fmaf(a, w1, a1[i]);
            }
        }
        __syncthreads();
#pragma unroll
        for (int i = 0; i < 4; i++) { M[(c4+i)*68 + lane] = a0[i]; M[(c4+i)*68 + lane+32] = a1[i]; }
    }
    __syncthreads();

    { // av[c][t] = sum_e M[c][e]*ys[e][t] + bC[c]
        ulonglong2 acc[4];
#pragma unroll
        for (int i = 0; i < 4; i++) { u64 bp = pk2(bC[c4+i]); acc[i].x = bp; acc[i].y = bp; }
        for (int e = 0; e < 64; e += 2) {
            ulonglong2 y0 = ld2x2s(ys + (e+0)*SY + t4);
            ulonglong2 y1 = ld2x2s(ys + (e+1)*SY + t4);
#pragma unroll
            for (int i = 0; i < 4; i++) {
                u64 m0 = pk2(M[(c4+i)*68 + e]);
                u64 m1 = pk2(M[(c4+i)*68 + e + 1]);
                acc[i].x = fma2(m0, y0.x, acc[i].x); acc[i].y = fma2(m0, y0.y, acc[i].y);
                acc[i].x = fma2(m1, y1.x, acc[i].x); acc[i].y = fma2(m1, y1.y, acc[i].y);
            }
        }
        float* dst = g_av + (size_t)b*1048576 + (size_t)v*TT;
#pragma unroll
        for (int i = 0; i < 4; i++) st2x2s(dst + (size_t)(c4+i)*16384 + t4, acc[i]);
    }
}

// ------------- k_final: register-window 3x3 conv + recombine -------------
// grid (64 tiles of 16x16, 8 b), 512 threads, ci-chunked staging
#define AVR 20
#define AVC (18*AVR)
__global__ __launch_bounds__(512, 2) void k_final(
    const float* __restrict__ gamma_p, const float* __restrict__ sigma_p,
    float* __restrict__ out) {
    extern __shared__ float smf[];
    float* avs = smf;                 // [16 ci][18 rows][AVR]
    float* wss = smf + 16*AVC;        // [16 ci][9 kk][64 o]
    int b = blockIdx.y, tile = blockIdx.x;
    int v0 = (tile >> 3) * 16, t0 = (tile & 7) * 16;
    int tid = threadIdx.x, lane = tid & 31, warp = tid >> 5;
    int o8 = (warp & 7) * 8;
    int r0 = (lane >> 2) + (warp >> 3) * 8;   // 0..15
    int c0 = (lane & 3) * 4;

    ulonglong2 acc[8];
#pragma unroll
    for (int i = 0; i < 8; i++) { acc[i].x = 0ull; acc[i].y = 0ull; }

    for (int chunk = 0; chunk < 4; chunk++) {
        int ci0 = chunk * 16;
        __syncthreads();
        // stage av halo tiles (16 ci x 18x18)
        for (int i = tid; i < 16*324; i += 512) {
            int ci = i / 324, rr = i - ci*324;
            int r = rr / 18, cc = rr - r*18;
            int vv = v0 - 1 + r, t = t0 - 1 + cc;
            float val = 0.f;
            if (vv >= 0 && vv < 128 && t >= 0 && t < 128)
                val = g_av[(size_t)(b*64 + ci0 + ci)*16384 + (size_t)vv*128 + t];
            avs[ci*AVC + r*AVR + cc] = val;
        }
        // stage weights (contiguous copy)
        for (int i = tid; i < 16*576; i += 512)
            wss[i] = g_wtr[ci0*576 + i];
        __syncthreads();

        for (int ci = 0; ci < 16; ci++) {
            const float* ap = avs + ci*AVC;
            const float* wr = wss + ci*576;
#pragma unroll
            for (int dv = 0; dv < 3; dv++) {
                float4 a4 = ld4s(ap + (r0+dv)*AVR + c0);
                float2 a2 = ld2f(ap + (r0+dv)*AVR + c0 + 4);
                float w6[6] = {a4.x, a4.y, a4.z, a4.w, a2.x, a2.y};
#pragma unroll
                for (int dt = 0; dt < 3; dt++) {
                    int kk = dv*3 + dt;
                    u64 apx = pk2two(w6[dt],   w6[dt+1]);
                    u64 apy = pk2two(w6[dt+2], w6[dt+3]);
                    float4 wA = ld4s(wr + kk*64 + o8);       // broadcast
                    float4 wB = ld4s(wr + kk*64 + o8 + 4);   // broadcast
                    acc[0].x = fma2(pk2(wA.x), apx, acc[0].x); acc[0].y = fma2(pk2(wA.x), apy, acc[0].y);
                    acc[1].x = fma2(pk2(wA.y), apx, acc[1].x); acc[1].y = fma2(pk2(wA.y), apy, acc[1].y);
                    acc[2].x = fma2(pk2(wA.z), apx, acc[2].x); acc[2].y = fma2(pk2(wA.z), apy, acc[2].y);
                    acc[3].x = fma2(pk2(wA.w), apx, acc[3].x); acc[3].y = fma2(pk2(wA.w), apy, acc[3].y);
                    acc[4].x = fma2(pk2(wB.x), apx, acc[4].x); acc[4].y = fma2(pk2(wB.x), apy, acc[4].y);
                    acc[5].x = fma2(pk2(wB.y), apx, acc[5].x); acc[5].y = fma2(pk2(wB.y), apy, acc[5].y);
                    acc[6].x = fma2(pk2(wB.z), apx, acc[6].x); acc[6].y = fma2(pk2(wB.z), apy, acc[6].y);
                    acc[7].x = fma2(pk2(wB.w), apx, acc[7].x); acc[7].y = fma2(pk2(wB.w), apy, acc[7].y);
                }
            }
        }
    }

    // epilogue: out = y + sH*OH + sW*OW + sigma*conv
    float gamma = __ldg(gamma_p), sigma = __ldg(sigma_p);
    int v = v0 + r0, t = t0 + c0;
    size_t sidx = ((size_t)b*VV + v)*TT + t;
    float4 mH4 = ld4g(&g_mH[sidx]), ZH4 = ld4g(&g_ZH[sidx]);
    float4 mW4 = ld4g(&g_mW[sidx]), ZW4 = ld4g(&g_ZW[sidx]);
    float sH[4], sW[4];
    {
        float mh[4] = {mH4.x, mH4.y, mH4.z, mH4.w};
        float zh[4] = {ZH4.x, ZH4.y, ZH4.z, ZH4.w};
        float mw[4] = {mW4.x, mW4.y, mW4.z, mW4.w};
        float zw[4] = {ZW4.x, ZW4.y, ZW4.z, ZW4.w};
#pragma unroll
        for (int p = 0; p < 4; p++) {
            float m = fmaxf(mh[p], mw[p]);
            float eH = __expf(mh[p] - m), eW = __expf(mw[p] - m);
            float inv = gamma / (zh[p]*eH + zw[p]*eW);
            sH[p] = eH * inv; sW[p] = eW * inv;
        }
    }
#pragma unroll
    for (int oi = 0; oi < 8; oi++) {
        int o = o8 + oi;
        size_t oidx = (((size_t)b*CO + o)*VV + v)*TT + t;
        float4 yv = ld4g(&g_y[oidx]);
        float4 oh = ld4g(&g_OH[oidx]);
        float4 ow = ld4g(&g_OW[oidx]);
        float2 ca = up2(acc[oi].x);
        float2 cb = up2(acc[oi].y);
        float4 r;
        r.x = yv.x + sH[0]*oh.x + sW[0]*ow.x + sigma*ca.x;
        r.y = yv.y + sH[1]*oh.y + sW[1]*ow.y + sigma*ca.y;
        r.z = yv.z + sH[2]*oh.z + sW[2]*ow.z + sigma*cb.x;
        r.w = yv.w + sH[3]*oh.w + sW[3]*ow.w + sigma*cb.y;
        *reinterpret_cast<float4*>(out + oidx) = r;
    }
}

// ---------------- launch ----------------
extern "C" void kernel_launch(void* const* d_in, const int* in_sizes, int n_in,
                              void* d_out, int out_size) {
    (void)in_sizes; (void)n_in; (void)out_size;
    const float* x    = (const float*)d_in[0];
    const float* dc_w = (const float*)d_in[1];
    const float* dc_b = (const float*)d_in[2];
    const float* q_w  = (const float*)d_in[3];
    const float* q_b  = (const float*)d_in[4];
    const float* k_w  = (const float*)d_in[5];
    const float* k_b  = (const float*)d_in[6];
    const float* v_w  = (const float*)d_in[7];
    const float* v_b  = (const float*)d_in[8];
    const float* gamma= (const float*)d_in[9];
    const float* cq_w = (const float*)d_in[10];
    const float* cq_b = (const float*)d_in[11];
    const float* ck_w = (const float*)d_in[12];
    const float* ck_b = (const float*)d_in[13];
    const float* cv_w = (const float*)d_in[14];
    const float* cv_b = (const float*)d_in[15];
    const float* av_w = (const float*)d_in[16];
    const float* sigma= (const float*)d_in[17];
    float* out = (float*)d_out;

    float *py, *pytr, *pOH;
    cudaGetSymbolAddress((void**)&py,   g_y);
    cudaGetSymbolAddress((void**)&pytr, g_ytr);
    cudaGetSymbolAddress((void**)&pOH,  g_OH);

    const int SMEM_ATT = 208*SY*4;                  // 109,824 B
    const int SMEM_C   = (192*SY + 64)*4;           // 101,632 B
    const int SMEM_F   = (16*AVC + 16*576)*4;       // 59,904 B
    static bool attr_done = false;
    if (!attr_done) {
        cudaFuncSetAttribute(k_att<false>, cudaFuncAttributeMaxDynamicSharedMemorySize, SMEM_ATT);
        cudaFuncSetAttribute(k_att<true>,  cudaFuncAttributeMaxDynamicSharedMemorySize, SMEM_ATT);
        cudaFuncSetAttribute(k_c,          cudaFuncAttributeMaxDynamicSharedMemorySize, SMEM_C);
        cudaFuncSetAttribute(k_final,      cudaFuncAttributeMaxDynamicSharedMemorySize, SMEM_F);
        attr_done = true;
    }

    k_wt <<<144, 256>>>(av_w);
    k_y  <<<dim3(128, 8), 256>>>(x, dc_w, dc_b);
    k_tr <<<dim3(16, 64, 8), dim3(32, 8)>>>(py, pytr, 16384, 128, 128, 8192);
    k_att<false><<<dim3(128, 8), 512, SMEM_ATT>>>(q_w, q_b, k_w, k_b, v_w, v_b);
    k_att<true> <<<dim3(128, 8), 512, SMEM_ATT>>>(q_w, q_b, k_w, k_b, v_w, v_b);
    k_c  <<<dim3(128, 8), 512, SMEM_C>>>(cq_w, cq_b, ck_w, ck_b, cv_w, cv_b);
    k_tr <<<dim3(16, 64, 8), dim3(32, 8)>>>(pytr, pOH, 128, 8192, 16384, 128);
    k_final<<<dim3(64, 8), 512, SMEM_F>>>(gamma, sigma, out);
}

// round 7
// speedup vs baseline: 2.6606x; 1.0291x over previous
#include <cuda_runtime.h>
#include <math.h>

#define BB 8
#define CIN 256
#define CO 64
#define VV 128
#define TT 128
#define SY 132

__device__ float g_y  [BB*CO*VV*TT];
__device__ float g_ytr[BB*TT*CO*VV];   // y_tr, later reused as OH_tr
__device__ float g_OH [BB*CO*VV*TT];
__device__ float g_OW [BB*CO*VV*TT];
__device__ float g_av [BB*CO*VV*TT];
__device__ float g_mH [BB*VV*TT];
__device__ float g_ZH [BB*VV*TT];
__device__ float g_mW [BB*VV*TT];
__device__ float g_ZW [BB*VV*TT];
__device__ float g_wtr[64*576];        // [ci][kk][o]

typedef unsigned long long u64;

__device__ __forceinline__ float4 ld4s(const float* p){ return *reinterpret_cast<const float4*>(p); }
__device__ __forceinline__ void st4s(float* p, float4 v){ *reinterpret_cast<float4*>(p) = v; }
__device__ __forceinline__ float2 ld2f(const float* p){ return *reinterpret_cast<const float2*>(p); }
__device__ __forceinline__ float4 ld4g(const float* p){ return __ldg(reinterpret_cast<const float4*>(p)); }
__device__ __forceinline__ ulonglong2 ld2x2s(const float* p){ return *reinterpret_cast<const ulonglong2*>(p); }
__device__ __forceinline__ void st2x2s(float* p, ulonglong2 v){ *reinterpret_cast<ulonglong2*>(p) = v; }
__device__ __forceinline__ u64 pk2(float x){ u64 r; asm("mov.b64 %0,{%1,%1};" : "=l"(r) : "f"(x)); return r; }
__device__ __forceinline__ u64 pk2two(float lo, float hi){ u64 r; asm("mov.b64 %0,{%1,%2};" : "=l"(r) : "f"(lo), "f"(hi)); return r; }
__device__ __forceinline__ float2 up2(u64 a){ float2 f; asm("mov.b64 {%0,%1},%2;" : "=f"(f.x), "=f"(f.y) : "l"(a)); return f; }
__device__ __forceinline__ u64 fma2(u64 a, u64 b, u64 c){
    u64 d; asm("fma.rn.f32x2 %0,%1,%2,%3;" : "=l"(d) : "l"(a), "l"(b), "l"(c)); return d;
}
__device__ __forceinline__ u64 add2(u64 a, u64 b){
    u64 d; asm("add.rn.f32x2 %0,%1,%2;" : "=l"(d) : "l"(a), "l"(b)); return d;
}
__device__ __forceinline__ float dot4(float4 a, float4 b, float c){
    c = fmaf(a.x,b.x,c); c = fmaf(a.y,b.y,c); c = fmaf(a.z,b.z,c); return fmaf(a.w,b.w,c);
}
__device__ __forceinline__ float4 fma4(float s, float4 v, float4 a){
    a.x=fmaf(s,v.x,a.x); a.y=fmaf(s,v.y,a.y); a.z=fmaf(s,v.z,a.z); a.w=fmaf(s,v.w,a.w); return a;
}

// ---------------- k_y: y = dc_w @ xp + dc_b ----------------
__global__ __launch_bounds__(256) void k_y(const float* __restrict__ x,
                                           const float* __restrict__ w,
                                           const float* __restrict__ bias) {
    __shared__ float xs[32][128];
    __shared__ float wsT[32*64];   // [ci][o]
    int v = blockIdx.x, b = blockIdx.y;
    int tid = threadIdx.x, lane = tid & 31, warp = tid >> 5, t4 = lane*4;
    int o8 = warp * 8;
    ulonglong2 acc[8];
#pragma unroll
    for (int i = 0; i < 8; i++) { acc[i].x = 0ull; acc[i].y = 0ull; }
    bool vin = (v >= 1 && v <= 126);
    for (int c0 = 0; c0 < CIN; c0 += 32) {
        for (int i = tid; i < 32*128; i += 256) {
            int ci = i >> 7, t = i & 127;
            float val = 0.f;
            if (vin && t >= 1 && t <= 126)
                val = x[(((size_t)b*CIN + c0 + ci)*126 + (v-1))*126 + (t-1)];
            xs[ci][t] = val;
        }
        for (int i = tid; i < 2048; i += 256)
            wsT[i] = __ldg(w + (size_t)(i & 63)*CIN + c0 + (i >> 6));
        __syncthreads();
#pragma unroll 4
        for (int ci = 0; ci < 32; ci++) {
            ulonglong2 xv = ld2x2s(&xs[ci][t4]);
            float4 wA = ld4s(wsT + ci*64 + o8);
            float4 wB = ld4s(wsT + ci*64 + o8 + 4);
            u64 wp[8] = {pk2(wA.x),pk2(wA.y),pk2(wA.z),pk2(wA.w),
                         pk2(wB.x),pk2(wB.y),pk2(wB.z),pk2(wB.w)};
#pragma unroll
            for (int i = 0; i < 8; i++) {
                acc[i].x = fma2(wp[i], xv.x, acc[i].x);
                acc[i].y = fma2(wp[i], xv.y, acc[i].y);
            }
        }
        __syncthreads();
    }
#pragma unroll
    for (int i = 0; i < 8; i++) {
        int o = o8 + i;
        float bo = __ldg(bias + o);
        float2 lo = up2(acc[i].x);
        float2 hi = up2(acc[i].y);
        float4 r = make_float4(lo.x+bo, lo.y+bo, hi.x+bo, hi.y+bo);
        st4s(&g_y[(((size_t)b*CO + o)*VV + v)*TT + t4], r);
    }
}

// ------------- generic 128x128 transpose per (b,c) -------------
__global__ __launch_bounds__(256) void k_tr(const float* __restrict__ src,
                                            float* __restrict__ dst,
                                            int sc, int sr, int dc, int dq) {
    __shared__ float s[32][33];
    int tile = blockIdx.x, c = blockIdx.y, b = blockIdx.z;
    int r0 = (tile >> 2) * 32, q0 = (tile & 3) * 32;
    int tx = threadIdx.x, ty = threadIdx.y;
    const float* sp = src + (size_t)b*1048576 + (size_t)c*sc;
#pragma unroll
    for (int i = 0; i < 32; i += 8) s[ty+i][tx] = sp[(size_t)(r0+ty+i)*sr + q0 + tx];
    __syncthreads();
    float* dp = dst + (size_t)b*1048576 + (size_t)c*dc;
#pragma unroll
    for (int i = 0; i < 32; i += 8) dp[(size_t)(q0+ty+i)*dq + r0 + tx] = s[tx][ty+i];
}

// ---------------- weight transpose for conv: g_wtr[ci][kk][o] ----------------
__global__ __launch_bounds__(256) void k_wt(const float* __restrict__ avw) {
    int i = blockIdx.x*256 + threadIdx.x;   // < 36864
    int ci = i / 576, rem = i - ci*576;
    int kk = rem >> 6, o = rem & 63;
    g_wtr[i] = __ldg(avw + (size_t)o*576 + ci*9 + kk);
}

// ------------- spatial attention (W / H), transposed score matrix -------------
template<bool ISH>
__global__ __launch_bounds__(512, 2) void k_att(
    const float* __restrict__ qw, const float* __restrict__ qb,
    const float* __restrict__ kw, const float* __restrict__ kb,
    const float* __restrict__ vw, const float* __restrict__ vb) {
    int idx = blockIdx.x, b = blockIdx.y;
    int tid = threadIdx.x, lane = tid & 31, warp = tid >> 5, t4 = lane*4;
    extern __shared__ float sm[];
    float* E  = sm;              // E_T[s][t], 128 rows of SY
    float* ys = sm;              // alias rows 0..63 until E written
    float* qs = sm + 128*SY;     // 8 rows
    float* ks = qs + 8*SY;       // 8 rows
    float* vs = ks + 8*SY;       // 64 rows
    float* pm = qs;              // reuse after QK: partial max [4][128]
    float* pz = qs + 512;        // partial sum  [4][128]

    // load ys[c][t]
    if (ISH) {
        const float* ysrc = g_ytr + (size_t)(b*TT + idx)*8192;
        for (int i = tid*4; i < 8192; i += 2048)
            st4s(ys + (i>>7)*SY + (i&127), ld4g(ysrc + i));
    } else {
        const float* ysrc = g_y + (size_t)b*1048576 + (size_t)idx*TT;
        for (int i = tid; i < 2048; i += 512) {
            int c = i >> 5, tt = (i & 31)*4;
            st4s(ys + c*SY + tt, ld4g(ysrc + (size_t)c*16384 + tt));
        }
    }
    __syncthreads();

    { // FUSED q/k/v projection: ONE pass over ys.
        int c4 = warp * 4;
        int which = warp >> 3, cq = warp & 7;
        const float* Wqk = which ? kw : qw;
        ulonglong2 acc[4], qa;
#pragma unroll
        for (int i = 0; i < 4; i++) { u64 bp = pk2(__ldg(vb + c4 + i)); acc[i].x = bp; acc[i].y = bp; }
        { u64 bp = pk2(__ldg((which ? kb : qb) + cq)); qa.x = bp; qa.y = bp; }
        for (int cc = 0; cc < 64; cc += 4) {
            ulonglong2 y0 = ld2x2s(ys + (cc+0)*SY + t4);
            ulonglong2 y1 = ld2x2s(ys + (cc+1)*SY + t4);
            ulonglong2 y2 = ld2x2s(ys + (cc+2)*SY + t4);
            ulonglong2 y3 = ld2x2s(ys + (cc+3)*SY + t4);
            float4 wq = ld4g(Wqk + (size_t)cq*64 + cc);
            qa.x = fma2(pk2(wq.x), y0.x, qa.x); qa.y = fma2(pk2(wq.x), y0.y, qa.y);
            qa.x = fma2(pk2(wq.y), y1.x, qa.x); qa.y = fma2(pk2(wq.y), y1.y, qa.y);
            qa.x = fma2(pk2(wq.z), y2.x, qa.x); qa.y = fma2(pk2(wq.z), y2.y, qa.y);
            qa.x = fma2(pk2(wq.w), y3.x, qa.x); qa.y = fma2(pk2(wq.w), y3.y, qa.y);
#pragma unroll
            for (int i = 0; i < 4; i++) {
                float4 wv = ld4g(vw + (size_t)(c4+i)*64 + cc);
                acc[i].x = fma2(pk2(wv.x), y0.x, acc[i].x); acc[i].y = fma2(pk2(wv.x), y0.y, acc[i].y);
                acc[i].x = fma2(pk2(wv.y), y1.x, acc[i].x); acc[i].y = fma2(pk2(wv.y), y1.y, acc[i].y);
                acc[i].x = fma2(pk2(wv.z), y2.x, acc[i].x); acc[i].y = fma2(pk2(wv.z), y2.y, acc[i].y);
                acc[i].x = fma2(pk2(wv.w), y3.x, acc[i].x); acc[i].y = fma2(pk2(wv.w), y3.y, acc[i].y);
            }
        }
#pragma unroll
        for (int i = 0; i < 4; i++) st2x2s(vs + (c4+i)*SY + t4, acc[i]);
        st2x2s((which ? ks : qs) + cq*SY + t4, qa);
    }
    __syncthreads();

    { // QK (f32x2) -> E_T[s][t] = sum_c ks[c][s]*qs[c][t]   (overwrites ys region)
        int s0 = (tid >> 4) * 4, t0 = (tid & 15) * 8;
        u64 acc[4][4];
#pragma unroll
        for (int i = 0; i < 4; i++)
#pragma unroll
            for (int j = 0; j < 4; j++) acc[i][j] = 0ull;
#pragma unroll
        for (int c = 0; c < 8; c++) {
            float kv[4];
#pragma unroll
            for (int i = 0; i < 4; i++) kv[i] = ks[c*SY + s0 + i];
            ulonglong2 qA = ld2x2s(qs + c*SY + t0);
            ulonglong2 qB = ld2x2s(qs + c*SY + t0 + 4);
#pragma unroll
            for (int i = 0; i < 4; i++) {
                u64 kp = pk2(kv[i]);
                acc[i][0] = fma2(kp, qA.x, acc[i][0]);
                acc[i][1] = fma2(kp, qA.y, acc[i][1]);
                acc[i][2] = fma2(kp, qB.x, acc[i][2]);
                acc[i][3] = fma2(kp, qB.y, acc[i][3]);
            }
        }
#pragma unroll
        for (int i = 0; i < 4; i++) {
            float2 p0 = up2(acc[i][0]), p1 = up2(acc[i][1]);
            float2 p2 = up2(acc[i][2]), p3 = up2(acc[i][3]);
            float vals[8] = {p0.x,p0.y,p1.x,p1.y,p2.x,p2.y,p3.x,p3.y};
            if (ISH) {
                int d = s0 + i - t0;
                if (d >= 0 && d < 8) vals[d] = -1e30f;
            }
            st4s(E + (s0+i)*SY + t0,   make_float4(vals[0],vals[1],vals[2],vals[3]));
            st4s(E + (s0+i)*SY + t0+4, make_float4(vals[4],vals[5],vals[6],vals[7]));
        }
    }
    __syncthreads();

    { // softmax over s (rows) for each column t; 4 row-quarters per t
        int t = tid & 127, q = tid >> 7;
        int sbeg = q * 32;
        float m = -INFINITY;
#pragma unroll 8
        for (int s = sbeg; s < sbeg + 32; s++) m = fmaxf(m, E[s*SY + t]);
        pm[q*128 + t] = m;
        __syncthreads();
        float M = fmaxf(fmaxf(pm[t], pm[128+t]), fmaxf(pm[256+t], pm[384+t]));
        float Z = 0.f;
#pragma unroll 8
        for (int s = sbeg; s < sbeg + 32; s++) {
            float p = __expf(E[s*SY + t] - M);
            E[s*SY + t] = p; Z += p;
        }
        pz[q*128 + t] = Z;
        __syncthreads();
        if (q == 0) {
            float Zt = pz[t] + pz[128+t] + pz[256+t] + pz[384+t];
            if (ISH) { g_mH[((size_t)b*VV + t)*TT + idx] = M; g_ZH[((size_t)b*VV + t)*TT + idx] = Zt; }
            else     { g_mW[((size_t)b*VV + idx)*TT + t] = M; g_ZW[((size_t)b*VV + idx)*TT + t] = Zt; }
        }
    }
    __syncthreads();

    { // apply, split-K over s: thread owns 8c x 4t over half the s-range
        int shalf = tid >> 8;              // 0 or 1
        int u = tid & 255;
        int c8 = (u >> 5) * 8;             // warp-uniform
        int ta = (u & 31) * 4;
        int sbase = shalf * 64;
        ulonglong2 acc[8];
#pragma unroll
        for (int i = 0; i < 8; i++) { acc[i].x = 0ull; acc[i].y = 0ull; }
        for (int s0 = sbase; s0 < sbase + 64; s0 += 4) {
            ulonglong2 e0 = ld2x2s(E + (s0+0)*SY + ta);
            ulonglong2 e1 = ld2x2s(E + (s0+1)*SY + ta);
            ulonglong2 e2 = ld2x2s(E + (s0+2)*SY + ta);
            ulonglong2 e3 = ld2x2s(E + (s0+3)*SY + ta);
#pragma unroll
            for (int i = 0; i < 8; i++) {
                float4 vv = ld4s(vs + (c8+i)*SY + s0);   // warp-broadcast
                acc[i].x = fma2(pk2(vv.x), e0.x, acc[i].x); acc[i].y = fma2(pk2(vv.x), e0.y, acc[i].y);
                acc[i].x = fma2(pk2(vv.y), e1.x, acc[i].x); acc[i].y = fma2(pk2(vv.y), e1.y, acc[i].y);
                acc[i].x = fma2(pk2(vv.z), e2.x, acc[i].x); acc[i].y = fma2(pk2(vv.z), e2.y, acc[i].y);
                acc[i].x = fma2(pk2(vv.w), e3.x, acc[i].x); acc[i].y = fma2(pk2(vv.w), e3.y, acc[i].y);
            }
        }
        __syncthreads();
        if (shalf == 1) {
#pragma unroll
            for (int i = 0; i < 8; i++) st2x2s(E + (c8+i)*SY + ta, acc[i]);
        }
        __syncthreads();
        if (shalf == 0) {
#pragma unroll
            for (int i = 0; i < 8; i++) {
                ulonglong2 p = ld2x2s(E + (c8+i)*SY + ta);
                acc[i].x = add2(acc[i].x, p.x);
                acc[i].y = add2(acc[i].y, p.y);
            }
            if (ISH) { // OH_tr[b][t][c][vr]
                float* dst = g_ytr + (size_t)(b*TT + idx)*8192 + ta;
#pragma unroll
                for (int i = 0; i < 8; i++) st2x2s(dst + (c8+i)*128, acc[i]);
            } else {   // OW[b][c][v][t]
                float* dst = g_OW + (size_t)b*1048576 + (size_t)idx*TT + ta;
#pragma unroll
                for (int i = 0; i < 8; i++) st2x2s(dst + (size_t)(c8+i)*16384, acc[i]);
            }
        }
    }
}

// ------------- channel attention per (b,v): av = (attn@cvw)@ys + attn@cvb -------------
__global__ __launch_bounds__(512, 2) void k_c(
    const float* __restrict__ cqw, const float* __restrict__ cqb,
    const float* __restrict__ ckw, const float* __restrict__ ckb,
    const float* __restrict__ cvw, const float* __restrict__ cvb) {
    int v = blockIdx.x, b = blockIdx.y;
    int tid = threadIdx.x, lane = tid & 31, warp = tid >> 5, t4 = lane*4;
    extern __shared__ float sm[];
    float* ys = sm;              // [64][SY]
    float* qc = sm + 64*SY;      // later aliased by M [64][68]
    float* kc = sm + 128*SY;     // later aliased by Ec [64][68]
    float* bC = sm + 192*SY;     // [64]
    float* Ec = kc;
    float* M  = qc;
    int c4 = warp * 4;

    const float* ysrc = g_y + (size_t)b*1048576 + (size_t)v*TT;
    for (int i = tid; i < 2048; i += 512) {
        int c = i >> 5, tt = (i & 31)*4;
        st4s(ys + c*SY + tt, ld4g(ysrc + (size_t)c*16384 + tt));
    }
    __syncthreads();

    { // FUSED qc+kc projection: one ys pass, warp owns 4 rows of each
        ulonglong2 qa[4], ka[4];
#pragma unroll
        for (int i = 0; i < 4; i++) {
            u64 bq = pk2(__ldg(cqb + c4 + i)); qa[i].x = bq; qa[i].y = bq;
            u64 bk = pk2(__ldg(ckb + c4 + i)); ka[i].x = bk; ka[i].y = bk;
        }
        for (int cc = 0; cc < 64; cc += 2) {
            ulonglong2 y0 = ld2x2s(ys + (cc+0)*SY + t4);
            ulonglong2 y1 = ld2x2s(ys + (cc+1)*SY + t4);
#pragma unroll
            for (int i = 0; i < 4; i++) {
                float2 wq = __ldg(reinterpret_cast<const float2*>(cqw + (size_t)(c4+i)*64 + cc));
                float2 wk = __ldg(reinterpret_cast<const float2*>(ckw + (size_t)(c4+i)*64 + cc));
                qa[i].x = fma2(pk2(wq.x), y0.x, qa[i].x); qa[i].y = fma2(pk2(wq.x), y0.y, qa[i].y);
                qa[i].x = fma2(pk2(wq.y), y1.x, qa[i].x); qa[i].y = fma2(pk2(wq.y), y1.y, qa[i].y);
                ka[i].x = fma2(pk2(wk.x), y0.x, ka[i].x); ka[i].y = fma2(pk2(wk.x), y0.y, ka[i].y);
                ka[i].x = fma2(pk2(wk.y), y1.x, ka[i].x); ka[i].y = fma2(pk2(wk.y), y1.y, ka[i].y);
            }
        }
#pragma unroll
        for (int i = 0; i < 4; i++) {
            st2x2s(qc + (c4+i)*SY + t4, qa[i]);
            st2x2s(kc + (c4+i)*SY + t4, ka[i]);
        }
    }
    __syncthreads();

    { // Ec[c][d] = sum_t qc[c][t]*kc[d][t]
        float a0[4], a1[4];
#pragma unroll
        for (int i = 0; i < 4; i++) { a0[i] = 0.f; a1[i] = 0.f; }
        for (int tt = 0; tt < 128; tt += 4) {
            float4 kA = ld4s(kc + lane*SY + tt);
            float4 kB = ld4s(kc + (lane+32)*SY + tt);
#pragma unroll
            for (int i = 0; i < 4; i++) {
                float4 q = ld4s(qc + (c4+i)*SY + tt);
                a0[i] = dot4(q, kA, a0[i]); a1[i] = dot4(q, kB, a1[i]);
            }
        }
        __syncthreads();
#pragma unroll
        for (int i = 0; i < 4; i++) { Ec[(c4+i)*68 + lane] = a0[i]; Ec[(c4+i)*68 + lane+32] = a1[i]; }
    }
    __syncthreads();

    { // softmax rows of Ec (8 threads/row)
        int r = tid >> 3, sub = tid & 7;
        float* row = Ec + r*68;
        float4 x0 = ld4s(row + sub*4), x1 = ld4s(row + sub*4 + 32);
        float m = fmaxf(fmaxf(fmaxf(x0.x,x0.y),fmaxf(x0.z,x0.w)),
                        fmaxf(fmaxf(x1.x,x1.y),fmaxf(x1.z,x1.w)));
        m = fmaxf(m, __shfl_xor_sync(~0u, m, 1));
        m = fmaxf(m, __shfl_xor_sync(~0u, m, 2));
        m = fmaxf(m, __shfl_xor_sync(~0u, m, 4));
        x0.x=__expf(x0.x-m); x0.y=__expf(x0.y-m); x0.z=__expf(x0.z-m); x0.w=__expf(x0.w-m);
        x1.x=__expf(x1.x-m); x1.y=__expf(x1.y-m); x1.z=__expf(x1.z-m); x1.w=__expf(x1.w-m);
        float Z = x0.x+x0.y+x0.z+x0.w + x1.x+x1.y+x1.z+x1.w;
        Z += __shfl_xor_sync(~0u, Z, 1);
        Z += __shfl_xor_sync(~0u, Z, 2);
        Z += __shfl_xor_sync(~0u, Z, 4);
        float inv = 1.f / Z;
        x0.x*=inv; x0.y*=inv; x0.z*=inv; x0.w*=inv;
        x1.x*=inv; x1.y*=inv; x1.z*=inv; x1.w*=inv;
        st4s(row + sub*4, x0); st4s(row + sub*4 + 32, x1);
    }
    __syncthreads();

    if (tid < 64) {
        float a = 0.f;
        for (int d = 0; d < 64; d++) a = fmaf(Ec[tid*68 + d], __ldg(cvb + d), a);
        bC[tid] = a;
    }
    { // M[c][e] = sum_d Ec[c][d]*cvw[d][e]
        float a0[4], a1[4];
#pragma unroll
        for (int i = 0; i < 4; i++) { a0[i] = 0.f; a1[i] = 0.f; }
        for (int d = 0; d < 64; d++) {
            float w0 = __ldg(cvw + (size_t)d*64 + lane);
            float w1 = __ldg(cvw + (size_t)d*64 + lane + 32);
#pragma unroll
            for (int i = 0; i < 4; i++) {
                float a = Ec[(c4+i)*68 + d];
                a0[i] = fmaf(a, w0, a0[i]); a1[i] = fmaf(a, w1, a1[i]);
            }
        }
        __syncthreads();
#pragma unroll
        for (int i = 0; i < 4; i++) { M[(c4+i)*68 + lane] = a0[i]; M[(c4+i)*68 + lane+32] = a1[i]; }
    }
    __syncthreads();

    { // av[c][t] = sum_e M[c][e]*ys[e][t] + bC[c]
        ulonglong2 acc[4];
#pragma unroll
        for (int i = 0; i < 4; i++) { u64 bp = pk2(bC[c4+i]); acc[i].x = bp; acc[i].y = bp; }
        for (int e = 0; e < 64; e += 2) {
            ulonglong2 y0 = ld2x2s(ys + (e+0)*SY + t4);
            ulonglong2 y1 = ld2x2s(ys + (e+1)*SY + t4);
#pragma unroll
            for (int i = 0; i < 4; i++) {
                u64 m0 = pk2(M[(c4+i)*68 + e]);
                u64 m1 = pk2(M[(c4+i)*68 + e + 1]);
                acc[i].x = fma2(m0, y0.x, acc[i].x); acc[i].y = fma2(m0, y0.y, acc[i].y);
                acc[i].x = fma2(m1, y1.x, acc[i].x); acc[i].y = fma2(m1, y1.y, acc[i].y);
            }
        }
        float* dst = g_av + (size_t)b*1048576 + (size_t)v*TT;
#pragma unroll
        for (int i = 0; i < 4; i++) st2x2s(dst + (size_t)(c4+i)*16384 + t4, acc[i]);
    }
}

// ------------- k_final: register-window 3x3 conv + recombine -------------
#define AVR 20
#define AVC (18*AVR)
__global__ __launch_bounds__(512, 2) void k_final(
    const float* __restrict__ gamma_p, const float* __restrict__ sigma_p,
    float* __restrict__ out) {
    extern __shared__ float smf[];
    float* avs = smf;                 // [16 ci][18 rows][AVR]
    float* wss = smf + 16*AVC;        // [16 ci][9 kk][64 o]
    int b = blockIdx.y, tile = blockIdx.x;
    int v0 = (tile >> 3) * 16, t0 = (tile & 7) * 16;
    int tid = threadIdx.x, lane = tid & 31, warp = tid >> 5;
    int o8 = (warp & 7) * 8;
    int r0 = (lane >> 2) + (warp >> 3) * 8;   // 0..15
    int c0 = (lane & 3) * 4;

    ulonglong2 acc[8];
#pragma unroll
    for (int i = 0; i < 8; i++) { acc[i].x = 0ull; acc[i].y = 0ull; }

    for (int chunk = 0; chunk < 4; chunk++) {
        int ci0 = chunk * 16;
        __syncthreads();
        for (int i = tid; i < 16*324; i += 512) {
            int ci = i / 324, rr = i - ci*324;
            int r = rr / 18, cc = rr - r*18;
            int vv = v0 - 1 + r, t = t0 - 1 + cc;
            float val = 0.f;
            if (vv >= 0 && vv < 128 && t >= 0 && t < 128)
                val = g_av[(size_t)(b*64 + ci0 + ci)*16384 + (size_t)vv*128 + t];
            avs[ci*AVC + r*AVR + cc] = val;
        }
        for (int i = tid; i < 16*576; i += 512)
            wss[i] = g_wtr[ci0*576 + i];
        __syncthreads();

        for (int ci = 0; ci < 16; ci++) {
            const float* ap = avs + ci*AVC;
            const float* wr = wss + ci*576;
#pragma unroll
            for (int dv = 0; dv < 3; dv++) {
                float4 a4 = ld4s(ap + (r0+dv)*AVR + c0);
                float2 a2 = ld2f(ap + (r0+dv)*AVR + c0 + 4);
                float w6[6] = {a4.x, a4.y, a4.z, a4.w, a2.x, a2.y};
#pragma unroll
                for (int dt = 0; dt < 3; dt++) {
                    int kk = dv*3 + dt;
                    u64 apx = pk2two(w6[dt],   w6[dt+1]);
                    u64 apy = pk2two(w6[dt+2], w6[dt+3]);
                    float4 wA = ld4s(wr + kk*64 + o8);       // broadcast
                    float4 wB = ld4s(wr + kk*64 + o8 + 4);   // broadcast
                    acc[0].x = fma2(pk2(wA.x), apx, acc[0].x); acc[0].y = fma2(pk2(wA.x), apy, acc[0].y);
                    acc[1].x = fma2(pk2(wA.y), apx, acc[1].x); acc[1].y = fma2(pk2(wA.y), apy, acc[1].y);
                    acc[2].x = fma2(pk2(wA.z), apx, acc[2].x); acc[2].y = fma2(pk2(wA.z), apy, acc[2].y);
                    acc[3].x = fma2(pk2(wA.w), apx, acc[3].x); acc[3].y = fma2(pk2(wA.w), apy, acc[3].y);
                    acc[4].x = fma2(pk2(wB.x), apx, acc[4].x); acc[4].y = fma2(pk2(wB.x), apy, acc[4].y);
                    acc[5].x = fma2(pk2(wB.y), apx, acc[5].x); acc[5].y = fma2(pk2(wB.y), apy, acc[5].y);
                    acc[6].x = fma2(pk2(wB.z), apx, acc[6].x); acc[6].y = fma2(pk2(wB.z), apy, acc[6].y);
                    acc[7].x = fma2(pk2(wB.w), apx, acc[7].x); acc[7].y = fma2(pk2(wB.w), apy, acc[7].y);
                }
            }
        }
    }

    float gamma = __ldg(gamma_p), sigma = __ldg(sigma_p);
    int v = v0 + r0, t = t0 + c0;
    size_t sidx = ((size_t)b*VV + v)*TT + t;
    float4 mH4 = ld4g(&g_mH[sidx]), ZH4 = ld4g(&g_ZH[sidx]);
    float4 mW4 = ld4g(&g_mW[sidx]), ZW4 = ld4g(&g_ZW[sidx]);
    float sH[4], sW[4];
    {
        float mh[4] = {mH4.x, mH4.y, mH4.z, mH4.w};
        float zh[4] = {ZH4.x, ZH4.y, ZH4.z, ZH4.w};
        float mw[4] = {mW4.x, mW4.y, mW4.z, mW4.w};
        float zw[4] = {ZW4.x, ZW4.y, ZW4.z, ZW4.w};
#pragma unroll
        for (int p = 0; p < 4; p++) {
            float m = fmaxf(mh[p], mw[p]);
            float eH = __expf(mh[p] - m), eW = __expf(mw[p] - m);
            float inv = gamma / (zh[p]*eH + zw[p]*eW);
            sH[p] = eH * inv; sW[p] = eW * inv;
        }
    }
#pragma unroll
    for (int oi = 0; oi < 8; oi++) {
        int o = o8 + oi;
        size_t oidx = (((size_t)b*CO + o)*VV + v)*TT + t;
        float4 yv = ld4g(&g_y[oidx]);
        float4 oh = ld4g(&g_OH[oidx]);
        float4 ow = ld4g(&g_OW[oidx]);
        float2 ca = up2(acc[oi].x);
        float2 cb = up2(acc[oi].y);
        float4 r;
        r.x = yv.x + sH[0]*oh.x + sW[0]*ow.x + sigma*ca.x;
        r.y = yv.y + sH[1]*oh.y + sW[1]*ow.y + sigma*ca.y;
        r.z = yv.z + sH[2]*oh.z + sW[2]*ow.z + sigma*cb.x;
        r.w = yv.w + sH[3]*oh.w + sW[3]*ow.w + sigma*cb.y;
        *reinterpret_cast<float4*>(out + oidx) = r;
    }
}

// ---------------- launch: stream-parallel DAG ----------------
extern "C" void kernel_launch(void* const* d_in, const int* in_sizes, int n_in,
                              void* d_out, int out_size) {
    (void)in_sizes; (void)n_in; (void)out_size;
    const float* x    = (const float*)d_in[0];
    const float* dc_w = (const float*)d_in[1];
    const float* dc_b = (const float*)d_in[2];
    const float* q_w  = (const float*)d_in[3];
    const float* q_b  = (const float*)d_in[4];
    const float* k_w  = (const float*)d_in[5];
    const float* k_b  = (const float*)d_in[6];
    const float* v_w  = (const float*)d_in[7];
    const float* v_b  = (const float*)d_in[8];
    const float* gamma= (const float*)d_in[9];
    const float* cq_w = (const float*)d_in[10];
    const float* cq_b = (const float*)d_in[11];
    const float* ck_w = (const float*)d_in[12];
    const float* ck_b = (const float*)d_in[13];
    const float* cv_w = (const float*)d_in[14];
    const float* cv_b = (const float*)d_in[15];
    const float* av_w = (const float*)d_in[16];
    const float* sigma= (const float*)d_in[17];
    float* out = (float*)d_out;

    float *py, *pytr, *pOH;
    cudaGetSymbolAddress((void**)&py,   g_y);
    cudaGetSymbolAddress((void**)&pytr, g_ytr);
    cudaGetSymbolAddress((void**)&pOH,  g_OH);

    const int SMEM_ATT = 208*SY*4;                  // 109,824 B
    const int SMEM_C   = (192*SY + 64)*4;           // 101,632 B
    const int SMEM_F   = (16*AVC + 16*576)*4;       // 59,904 B

    static cudaStream_t s1 = nullptr, s2 = nullptr;
    static cudaEvent_t evy = nullptr, evw = nullptr, evc = nullptr;
    if (!s1) {
        cudaFuncSetAttribute(k_att<false>, cudaFuncAttributeMaxDynamicSharedMemorySize, SMEM_ATT);
        cudaFuncSetAttribute(k_att<true>,  cudaFuncAttributeMaxDynamicSharedMemorySize, SMEM_ATT);
        cudaFuncSetAttribute(k_c,          cudaFuncAttributeMaxDynamicSharedMemorySize, SMEM_C);
        cudaFuncSetAttribute(k_final,      cudaFuncAttributeMaxDynamicSharedMemorySize, SMEM_F);
        cudaStreamCreateWithFlags(&s1, cudaStreamNonBlocking);
        cudaStreamCreateWithFlags(&s2, cudaStreamNonBlocking);
        cudaEventCreateWithFlags(&evy, cudaEventDisableTiming);
        cudaEventCreateWithFlags(&evw, cudaEventDisableTiming);
        cudaEventCreateWithFlags(&evc, cudaEventDisableTiming);
    }

    // independent prologue on s1
    k_wt <<<144, 256, 0, s1>>>(av_w);

    // default stream: k_y, then fork
    k_y  <<<dim3(128, 8), 256>>>(x, dc_w, dc_b);
    cudaEventRecord(evy, 0);
    cudaStreamWaitEvent(s1, evy, 0);
    cudaStreamWaitEvent(s2, evy, 0);

    // s1: W-attention  |  s2: channel attention  |  default: tr -> H-attention -> tr
    k_att<false><<<dim3(128, 8), 512, SMEM_ATT, s1>>>(q_w, q_b, k_w, k_b, v_w, v_b);
    cudaEventRecord(evw, s1);
    k_c  <<<dim3(128, 8), 512, SMEM_C, s2>>>(cq_w, cq_b, ck_w, ck_b, cv_w, cv_b);
    cudaEventRecord(evc, s2);

    k_tr <<<dim3(16, 64, 8), dim3(32, 8)>>>(py, pytr, 16384, 128, 128, 8192);
    k_att<true> <<<dim3(128, 8), 512, SMEM_ATT>>>(q_w, q_b, k_w, k_b, v_w, v_b);
    k_tr <<<dim3(16, 64, 8), dim3(32, 8)>>>(pytr, pOH, 128, 8192, 16384, 128);

    // join and finish
    cudaStreamWaitEvent(0, evw, 0);
    cudaStreamWaitEvent(0, evc, 0);
    k_final<<<dim3(64, 8), 512, SMEM_F>>>(gamma, sigma, out);
}

// round 9
// speedup vs baseline: 3.0611x; 1.1505x over previous
#include <cuda_runtime.h>
#include <math.h>

#define BB 8
#define CIN 256
#define CO 64
#define VV 128
#define TT 128
#define SY 132

__device__ float g_y  [BB*CO*VV*TT];
__device__ float g_ytr[BB*TT*CO*VV];   // y_tr, later reused as OH_tr
__device__ float g_OH [BB*CO*VV*TT];
__device__ float g_OW [BB*CO*VV*TT];
__device__ float g_av [BB*CO*VV*TT];
__device__ float g_mH [BB*VV*TT];
__device__ float g_ZH [BB*VV*TT];
__device__ float g_mW [BB*VV*TT];
__device__ float g_ZW [BB*VV*TT];
__device__ float g_wtr[64*576];        // [ci][kk][o], tf32-rounded bits

typedef unsigned long long u64;

__device__ __forceinline__ float4 ld4s(const float* p){ return *reinterpret_cast<const float4*>(p); }
__device__ __forceinline__ void st4s(float* p, float4 v){ *reinterpret_cast<float4*>(p) = v; }
__device__ __forceinline__ float2 ld2f(const float* p){ return *reinterpret_cast<const float2*>(p); }
__device__ __forceinline__ float4 ld4g(const float* p){ return __ldg(reinterpret_cast<const float4*>(p)); }
__device__ __forceinline__ ulonglong2 ld2x2s(const float* p){ return *reinterpret_cast<const ulonglong2*>(p); }
__device__ __forceinline__ void st2x2s(float* p, ulonglong2 v){ *reinterpret_cast<ulonglong2*>(p) = v; }
__device__ __forceinline__ u64 pk2(float x){ u64 r; asm("mov.b64 %0,{%1,%1};" : "=l"(r) : "f"(x)); return r; }
__device__ __forceinline__ float2 up2(u64 a){ float2 f; asm("mov.b64 {%0,%1},%2;" : "=f"(f.x), "=f"(f.y) : "l"(a)); return f; }
__device__ __forceinline__ u64 fma2(u64 a, u64 b, u64 c){
    u64 d; asm("fma.rn.f32x2 %0,%1,%2,%3;" : "=l"(d) : "l"(a), "l"(b), "l"(c)); return d;
}
__device__ __forceinline__ u64 add2(u64 a, u64 b){
    u64 d; asm("add.rn.f32x2 %0,%1,%2;" : "=l"(d) : "l"(a), "l"(b)); return d;
}
__device__ __forceinline__ float dot4(float4 a, float4 b, float c){
    c = fmaf(a.x,b.x,c); c = fmaf(a.y,b.y,c); c = fmaf(a.z,b.z,c); return fmaf(a.w,b.w,c);
}
__device__ __forceinline__ unsigned tf32b(float x){
    unsigned u; asm("cvt.rna.tf32.f32 %0, %1;" : "=r"(u) : "f"(x)); return u;
}
__device__ __forceinline__ void mma_tf32(float* d, unsigned a0, unsigned a1, unsigned a2, unsigned a3,
                                         unsigned b0, unsigned b1){
    asm("mma.sync.aligned.m16n8k8.row.col.f32.tf32.tf32.f32 "
        "{%0,%1,%2,%3}, {%4,%5,%6,%7}, {%8,%9}, {%0,%1,%2,%3};"
        : "+f"(d[0]), "+f"(d[1]), "+f"(d[2]), "+f"(d[3])
        : "r"(a0), "r"(a1), "r"(a2), "r"(a3), "r"(b0), "r"(b1));
}

// ---------------- k_y: y = dc_w @ xp + dc_b ----------------
__global__ __launch_bounds__(256) void k_y(const float* __restrict__ x,
                                           const float* __restrict__ w,
                                           const float* __restrict__ bias) {
    __shared__ float xs[32][128];
    __shared__ float wsT[32*64];   // [ci][o]
    int v = blockIdx.x, b = blockIdx.y;
    int tid = threadIdx.x, lane = tid & 31, warp = tid >> 5, t4 = lane*4;
    int o8 = warp * 8;
    ulonglong2 acc[8];
#pragma unroll
    for (int i = 0; i < 8; i++) { acc[i].x = 0ull; acc[i].y = 0ull; }
    bool vin = (v >= 1 && v <= 126);
    for (int c0 = 0; c0 < CIN; c0 += 32) {
        for (int i = tid; i < 32*128; i += 256) {
            int ci = i >> 7, t = i & 127;
            float val = 0.f;
            if (vin && t >= 1 && t <= 126)
                val = x[(((size_t)b*CIN + c0 + ci)*126 + (v-1))*126 + (t-1)];
            xs[ci][t] = val;
        }
        for (int i = tid; i < 2048; i += 256)
            wsT[i] = __ldg(w + (size_t)(i & 63)*CIN + c0 + (i >> 6));
        __syncthreads();
#pragma unroll 4
        for (int ci = 0; ci < 32; ci++) {
            ulonglong2 xv = ld2x2s(&xs[ci][t4]);
            float4 wA = ld4s(wsT + ci*64 + o8);
            float4 wB = ld4s(wsT + ci*64 + o8 + 4);
            u64 wp[8] = {pk2(wA.x),pk2(wA.y),pk2(wA.z),pk2(wA.w),
                         pk2(wB.x),pk2(wB.y),pk2(wB.z),pk2(wB.w)};
#pragma unroll
            for (int i = 0; i < 8; i++) {
                acc[i].x = fma2(wp[i], xv.x, acc[i].x);
                acc[i].y = fma2(wp[i], xv.y, acc[i].y);
            }
        }
        __syncthreads();
    }
#pragma unroll
    for (int i = 0; i < 8; i++) {
        int o = o8 + i;
        float bo = __ldg(bias + o);
        float2 lo = up2(acc[i].x);
        float2 hi = up2(acc[i].y);
        float4 r = make_float4(lo.x+bo, lo.y+bo, hi.x+bo, hi.y+bo);
        st4s(&g_y[(((size_t)b*CO + o)*VV + v)*TT + t4], r);
    }
}

// ------------- generic 128x128 transpose per (b,c) -------------
__global__ __launch_bounds__(256) void k_tr(const float* __restrict__ src,
                                            float* __restrict__ dst,
                                            int sc, int sr, int dc, int dq) {
    __shared__ float s[32][33];
    int tile = blockIdx.x, c = blockIdx.y, b = blockIdx.z;
    int r0 = (tile >> 2) * 32, q0 = (tile & 3) * 32;
    int tx = threadIdx.x, ty = threadIdx.y;
    const float* sp = src + (size_t)b*1048576 + (size_t)c*sc;
#pragma unroll
    for (int i = 0; i < 32; i += 8) s[ty+i][tx] = sp[(size_t)(r0+ty+i)*sr + q0 + tx];
    __syncthreads();
    float* dp = dst + (size_t)b*1048576 + (size_t)c*dc;
#pragma unroll
    for (int i = 0; i < 32; i += 8) dp[(size_t)(q0+ty+i)*dq + r0 + tx] = s[tx][ty+i];
}

// ---------------- weight transpose for conv: g_wtr[ci][kk][o], tf32 ----------------
__global__ __launch_bounds__(256) void k_wt(const float* __restrict__ avw) {
    int i = blockIdx.x*256 + threadIdx.x;   // < 36864
    int ci = i / 576, rem = i - ci*576;
    int kk = rem >> 6, o = rem & 63;
    float w = __ldg(avw + (size_t)o*576 + ci*9 + kk);
    g_wtr[i] = __uint_as_float(tf32b(w));
}

// ------------- spatial attention (W / H), transposed score matrix -------------
template<bool ISH>
__global__ __launch_bounds__(512, 2) void k_att(
    const float* __restrict__ qw, const float* __restrict__ qb,
    const float* __restrict__ kw, const float* __restrict__ kb,
    const float* __restrict__ vw, const float* __restrict__ vb) {
    int idx = blockIdx.x, b = blockIdx.y;
    int tid = threadIdx.x, lane = tid & 31, warp = tid >> 5, t4 = lane*4;
    extern __shared__ float sm[];
    float* E  = sm;              // E_T[s][t], 128 rows of SY
    float* ys = sm;              // alias rows 0..63 until E written
    float* qs = sm + 128*SY;     // 8 rows
    float* ks = qs + 8*SY;       // 8 rows
    float* vs = ks + 8*SY;       // 64 rows
    float* pm = qs;              // reuse after QK: partial max [4][128]
    float* pz = qs + 512;        // partial sum  [4][128]

    if (ISH) {
        const float* ysrc = g_ytr + (size_t)(b*TT + idx)*8192;
        for (int i = tid*4; i < 8192; i += 2048)
            st4s(ys + (i>>7)*SY + (i&127), ld4g(ysrc + i));
    } else {
        const float* ysrc = g_y + (size_t)b*1048576 + (size_t)idx*TT;
        for (int i = tid; i < 2048; i += 512) {
            int c = i >> 5, tt = (i & 31)*4;
            st4s(ys + c*SY + tt, ld4g(ysrc + (size_t)c*16384 + tt));
        }
    }
    __syncthreads();

    { // FUSED q/k/v projection: ONE pass over ys.
        int c4 = warp * 4;
        int which = warp >> 3, cq = warp & 7;
        const float* Wqk = which ? kw : qw;
        ulonglong2 acc[4], qa;
#pragma unroll
        for (int i = 0; i < 4; i++) { u64 bp = pk2(__ldg(vb + c4 + i)); acc[i].x = bp; acc[i].y = bp; }
        { u64 bp = pk2(__ldg((which ? kb : qb) + cq)); qa.x = bp; qa.y = bp; }
        for (int cc = 0; cc < 64; cc += 4) {
            ulonglong2 y0 = ld2x2s(ys + (cc+0)*SY + t4);
            ulonglong2 y1 = ld2x2s(ys + (cc+1)*SY + t4);
            ulonglong2 y2 = ld2x2s(ys + (cc+2)*SY + t4);
            ulonglong2 y3 = ld2x2s(ys + (cc+3)*SY + t4);
            float4 wq = ld4g(Wqk + (size_t)cq*64 + cc);
            qa.x = fma2(pk2(wq.x), y0.x, qa.x); qa.y = fma2(pk2(wq.x), y0.y, qa.y);
            qa.x = fma2(pk2(wq.y), y1.x, qa.x); qa.y = fma2(pk2(wq.y), y1.y, qa.y);
            qa.x = fma2(pk2(wq.z), y2.x, qa.x); qa.y = fma2(pk2(wq.z), y2.y, qa.y);
            qa.x = fma2(pk2(wq.w), y3.x, qa.x); qa.y = fma2(pk2(wq.w), y3.y, qa.y);
#pragma unroll
            for (int i = 0; i < 4; i++) {
                float4 wv = ld4g(vw + (size_t)(c4+i)*64 + cc);
                acc[i].x = fma2(pk2(wv.x), y0.x, acc[i].x); acc[i].y = fma2(pk2(wv.x), y0.y, acc[i].y);
                acc[i].x = fma2(pk2(wv.y), y1.x, acc[i].x); acc[i].y = fma2(pk2(wv.y), y1.y, acc[i].y);
                acc[i].x = fma2(pk2(wv.z), y2.x, acc[i].x); acc[i].y = fma2(pk2(wv.z), y2.y, acc[i].y);
                acc[i].x = fma2(pk2(wv.w), y3.x, acc[i].x); acc[i].y = fma2(pk2(wv.w), y3.y, acc[i].y);
            }
        }
#pragma unroll
        for (int i = 0; i < 4; i++) st2x2s(vs + (c4+i)*SY + t4, acc[i]);
        st2x2s((which ? ks : qs) + cq*SY + t4, qa);
    }
    __syncthreads();

    { // QK (f32x2) -> E_T[s][t] = sum_c ks[c][s]*qs[c][t]
        int s0 = (tid >> 4) * 4, t0 = (tid & 15) * 8;
        u64 acc[4][4];
#pragma unroll
        for (int i = 0; i < 4; i++)
#pragma unroll
            for (int j = 0; j < 4; j++) acc[i][j] = 0ull;
#pragma unroll
        for (int c = 0; c < 8; c++) {
            float kv[4];
#pragma unroll
            for (int i = 0; i < 4; i++) kv[i] = ks[c*SY + s0 + i];
            ulonglong2 qA = ld2x2s(qs + c*SY + t0);
            ulonglong2 qB = ld2x2s(qs + c*SY + t0 + 4);
#pragma unroll
            for (int i = 0; i < 4; i++) {
                u64 kp = pk2(kv[i]);
                acc[i][0] = fma2(kp, qA.x, acc[i][0]);
                acc[i][1] = fma2(kp, qA.y, acc[i][1]);
                acc[i][2] = fma2(kp, qB.x, acc[i][2]);
                acc[i][3] = fma2(kp, qB.y, acc[i][3]);
            }
        }
#pragma unroll
        for (int i = 0; i < 4; i++) {
            float2 p0 = up2(acc[i][0]), p1 = up2(acc[i][1]);
            float2 p2 = up2(acc[i][2]), p3 = up2(acc[i][3]);
            float vals[8] = {p0.x,p0.y,p1.x,p1.y,p2.x,p2.y,p3.x,p3.y};
            if (ISH) {
                int d = s0 + i - t0;
                if (d >= 0 && d < 8) vals[d] = -1e30f;
            }
            st4s(E + (s0+i)*SY + t0,   make_float4(vals[0],vals[1],vals[2],vals[3]));
            st4s(E + (s0+i)*SY + t0+4, make_float4(vals[4],vals[5],vals[6],vals[7]));
        }
    }
    __syncthreads();

    { // softmax over s for each column t
        int t = tid & 127, q = tid >> 7;
        int sbeg = q * 32;
        float m = -INFINITY;
#pragma unroll 8
        for (int s = sbeg; s < sbeg + 32; s++) m = fmaxf(m, E[s*SY + t]);
        pm[q*128 + t] = m;
        __syncthreads();
        float M = fmaxf(fmaxf(pm[t], pm[128+t]), fmaxf(pm[256+t], pm[384+t]));
        float Z = 0.f;
#pragma unroll 8
        for (int s = sbeg; s < sbeg + 32; s++) {
            float p = __expf(E[s*SY + t] - M);
            E[s*SY + t] = p; Z += p;
        }
        pz[q*128 + t] = Z;
        __syncthreads();
        if (q == 0) {
            float Zt = pz[t] + pz[128+t] + pz[256+t] + pz[384+t];
            if (ISH) { g_mH[((size_t)b*VV + t)*TT + idx] = M; g_ZH[((size_t)b*VV + t)*TT + idx] = Zt; }
            else     { g_mW[((size_t)b*VV + idx)*TT + t] = M; g_ZW[((size_t)b*VV + idx)*TT + t] = Zt; }
        }
    }
    __syncthreads();

    { // apply, split-K over s
        int shalf = tid >> 8;
        int u = tid & 255;
        int c8 = (u >> 5) * 8;
        int ta = (u & 31) * 4;
        int sbase = shalf * 64;
        ulonglong2 acc[8];
#pragma unroll
        for (int i = 0; i < 8; i++) { acc[i].x = 0ull; acc[i].y = 0ull; }
        for (int s0 = sbase; s0 < sbase + 64; s0 += 4) {
            ulonglong2 e0 = ld2x2s(E + (s0+0)*SY + ta);
            ulonglong2 e1 = ld2x2s(E + (s0+1)*SY + ta);
            ulonglong2 e2 = ld2x2s(E + (s0+2)*SY + ta);
            ulonglong2 e3 = ld2x2s(E + (s0+3)*SY + ta);
#pragma unroll
            for (int i = 0; i < 8; i++) {
                float4 vv = ld4s(vs + (c8+i)*SY + s0);
                acc[i].x = fma2(pk2(vv.x), e0.x, acc[i].x); acc[i].y = fma2(pk2(vv.x), e0.y, acc[i].y);
                acc[i].x = fma2(pk2(vv.y), e1.x, acc[i].x); acc[i].y = fma2(pk2(vv.y), e1.y, acc[i].y);
                acc[i].x = fma2(pk2(vv.z), e2.x, acc[i].x); acc[i].y = fma2(pk2(vv.z), e2.y, acc[i].y);
                acc[i].x = fma2(pk2(vv.w), e3.x, acc[i].x); acc[i].y = fma2(pk2(vv.w), e3.y, acc[i].y);
            }
        }
        __syncthreads();
        if (shalf == 1) {
#pragma unroll
            for (int i = 0; i < 8; i++) st2x2s(E + (c8+i)*SY + ta, acc[i]);
        }
        __syncthreads();
        if (shalf == 0) {
#pragma unroll
            for (int i = 0; i < 8; i++) {
                ulonglong2 p = ld2x2s(E + (c8+i)*SY + ta);
                acc[i].x = add2(acc[i].x, p.x);
                acc[i].y = add2(acc[i].y, p.y);
            }
            if (ISH) {
                float* dst = g_ytr + (size_t)(b*TT + idx)*8192 + ta;
#pragma unroll
                for (int i = 0; i < 8; i++) st2x2s(dst + (c8+i)*128, acc[i]);
            } else {
                float* dst = g_OW + (size_t)b*1048576 + (size_t)idx*TT + ta;
#pragma unroll
                for (int i = 0; i < 8; i++) st2x2s(dst + (size_t)(c8+i)*16384, acc[i]);
            }
        }
    }
}

// ------------- channel attention per (b,v) -------------
__global__ __launch_bounds__(512, 2) void k_c(
    const float* __restrict__ cqw, const float* __restrict__ cqb,
    const float* __restrict__ ckw, const float* __restrict__ ckb,
    const float* __restrict__ cvw, const float* __restrict__ cvb) {
    int v = blockIdx.x, b = blockIdx.y;
    int tid = threadIdx.x, lane = tid & 31, warp = tid >> 5, t4 = lane*4;
    extern __shared__ float sm[];
    float* ys = sm;
    float* qc = sm + 64*SY;
    float* kc = sm + 128*SY;
    float* bC = sm + 192*SY;
    float* Ec = kc;
    float* M  = qc;
    int c4 = warp * 4;

    const float* ysrc = g_y + (size_t)b*1048576 + (size_t)v*TT;
    for (int i = tid; i < 2048; i += 512) {
        int c = i >> 5, tt = (i & 31)*4;
        st4s(ys + c*SY + tt, ld4g(ysrc + (size_t)c*16384 + tt));
    }
    __syncthreads();

    { // FUSED qc+kc projection
        ulonglong2 qa[4], ka[4];
#pragma unroll
        for (int i = 0; i < 4; i++) {
            u64 bq = pk2(__ldg(cqb + c4 + i)); qa[i].x = bq; qa[i].y = bq;
            u64 bk = pk2(__ldg(ckb + c4 + i)); ka[i].x = bk; ka[i].y = bk;
        }
        for (int cc = 0; cc < 64; cc += 2) {
            ulonglong2 y0 = ld2x2s(ys + (cc+0)*SY + t4);
            ulonglong2 y1 = ld2x2s(ys + (cc+1)*SY + t4);
#pragma unroll
            for (int i = 0; i < 4; i++) {
                float2 wq = __ldg(reinterpret_cast<const float2*>(cqw + (size_t)(c4+i)*64 + cc));
                float2 wk = __ldg(reinterpret_cast<const float2*>(ckw + (size_t)(c4+i)*64 + cc));
                qa[i].x = fma2(pk2(wq.x), y0.x, qa[i].x); qa[i].y = fma2(pk2(wq.x), y0.y, qa[i].y);
                qa[i].x = fma2(pk2(wq.y), y1.x, qa[i].x); qa[i].y = fma2(pk2(wq.y), y1.y, qa[i].y);
                ka[i].x = fma2(pk2(wk.x), y0.x, ka[i].x); ka[i].y = fma2(pk2(wk.x), y0.y, ka[i].y);
                ka[i].x = fma2(pk2(wk.y), y1.x, ka[i].x); ka[i].y = fma2(pk2(wk.y), y1.y, ka[i].y);
            }
        }
#pragma unroll
        for (int i = 0; i < 4; i++) {
            st2x2s(qc + (c4+i)*SY + t4, qa[i]);
            st2x2s(kc + (c4+i)*SY + t4, ka[i]);
        }
    }
    __syncthreads();

    { // Ec[c][d] = sum_t qc[c][t]*kc[d][t]
        float a0[4], a1[4];
#pragma unroll
        for (int i = 0; i < 4; i++) { a0[i] = 0.f; a1[i] = 0.f; }
        for (int tt = 0; tt < 128; tt += 4) {
            float4 kA = ld4s(kc + lane*SY + tt);
            float4 kB = ld4s(kc + (lane+32)*SY + tt);
#pragma unroll
            for (int i = 0; i < 4; i++) {
                float4 q = ld4s(qc + (c4+i)*SY + tt);
                a0[i] = dot4(q, kA, a0[i]); a1[i] = dot4(q, kB, a1[i]);
            }
        }
        __syncthreads();
#pragma unroll
        for (int i = 0; i < 4; i++) { Ec[(c4+i)*68 + lane] = a0[i]; Ec[(c4+i)*68 + lane+32] = a1[i]; }
    }
    __syncthreads();

    { // softmax rows of Ec
        int r = tid >> 3, sub = tid & 7;
        float* row = Ec + r*68;
        float4 x0 = ld4s(row + sub*4), x1 = ld4s(row + sub*4 + 32);
        float m = fmaxf(fmaxf(fmaxf(x0.x,x0.y),fmaxf(x0.z,x0.w)),
                        fmaxf(fmaxf(x1.x,x1.y),fmaxf(x1.z,x1.w)));
        m = fmaxf(m, __shfl_xor_sync(~0u, m, 1));
        m = fmaxf(m, __shfl_xor_sync(~0u, m, 2));
        m = fmaxf(m, __shfl_xor_sync(~0u, m, 4));
        x0.x=__expf(x0.x-m); x0.y=__expf(x0.y-m); x0.z=__expf(x0.z-m); x0.w=__expf(x0.w-m);
        x1.x=__expf(x1.x-m); x1.y=__expf(x1.y-m); x1.z=__expf(x1.z-m); x1.w=__expf(x1.w-m);
        float Z = x0.x+x0.y+x0.z+x0.w + x1.x+x1.y+x1.z+x1.w;
        Z += __shfl_xor_sync(~0u, Z, 1);
        Z += __shfl_xor_sync(~0u, Z, 2);
        Z += __shfl_xor_sync(~0u, Z, 4);
        float inv = 1.f / Z;
        x0.x*=inv; x0.y*=inv; x0.z*=inv; x0.w*=inv;
        x1.x*=inv; x1.y*=inv; x1.z*=inv; x1.w*=inv;
        st4s(row + sub*4, x0); st4s(row + sub*4 + 32, x1);
    }
    __syncthreads();

    if (tid < 64) {
        float a = 0.f;
        for (int d = 0; d < 64; d++) a = fmaf(Ec[tid*68 + d], __ldg(cvb + d), a);
        bC[tid] = a;
    }
    { // M[c][e] = sum_d Ec[c][d]*cvw[d][e]
        float a0[4], a1[4];
#pragma unroll
        for (int i = 0; i < 4; i++) { a0[i] = 0.f; a1[i] = 0.f; }
        for (int d = 0; d < 64; d++) {
            float w0 = __ldg(cvw + (size_t)d*64 + lane);
            float w1 = __ldg(cvw + (size_t)d*64 + lane + 32);
#pragma unroll
            for (int i = 0; i < 4; i++) {
                float a = Ec[(c4+i)*68 + d];
                a0[i] = fmaf(a, w0, a0[i]); a1[i] = fmaf(a, w1, a1[i]);
            }
        }
        __syncthreads();
#pragma unroll
        for (int i = 0; i < 4; i++) { M[(c4+i)*68 + lane] = a0[i]; M[(c4+i)*68 + lane+32] = a1[i]; }
    }
    __syncthreads();

    { // av[c][t] = sum_e M[c][e]*ys[e][t] + bC[c]
        ulonglong2 acc[4];
#pragma unroll
        for (int i = 0; i < 4; i++) { u64 bp = pk2(bC[c4+i]); acc[i].x = bp; acc[i].y = bp; }
        for (int e = 0; e < 64; e += 2) {
            ulonglong2 y0 = ld2x2s(ys + (e+0)*SY + t4);
            ulonglong2 y1 = ld2x2s(ys + (e+1)*SY + t4);
#pragma unroll
            for (int i = 0; i < 4; i++) {
                u64 m0 = pk2(M[(c4+i)*68 + e]);
                u64 m1 = pk2(M[(c4+i)*68 + e + 1]);
                acc[i].x = fma2(m0, y0.x, acc[i].x); acc[i].y = fma2(m0, y0.y, acc[i].y);
                acc[i].x = fma2(m1, y1.x, acc[i].x); acc[i].y = fma2(m1, y1.y, acc[i].y);
            }
        }
        float* dst = g_av + (size_t)b*1048576 + (size_t)v*TT;
#pragma unroll
        for (int i = 0; i < 4; i++) st2x2s(dst + (size_t)(c4+i)*16384 + t4, acc[i]);
    }
}

// ------------- k_final: tf32 mma 3x3 conv + recombine -------------
// grid (64 tiles of 16x16, 8 b), 256 threads (8 warps = 4 Mtiles x 2 Nhalves)
#define AVR 20
#define AVC 360          // 18*AVR
#define CSP 260          // convS pitch (floats), multiple of 4 for aligned float4
__global__ __launch_bounds__(256, 2) void k_final(
    const float* __restrict__ gamma_p, const float* __restrict__ sigma_p,
    float* __restrict__ out) {
    extern __shared__ float smf[];
    float* avs = smf;                 // [16 ci][18 rows][AVR]
    float* wss = smf + 16*AVC;        // [16 ci][9 kk][64 o]  (tf32 bits)
    float* convS = smf;               // alias after mma: [64 o][CSP]
    float* scS = smf + 64*CSP;        // [2][256] scales
    int b = blockIdx.y, tile = blockIdx.x;
    int v0 = (tile >> 3) * 16, t0 = (tile & 7) * 16;
    int tid = threadIdx.x, lane = tid & 31, warp = tid >> 5;
    int g = lane >> 2, c = lane & 3;
    int warpM = warp >> 1, warpN = warp & 1;

    float d[16][4];
#pragma unroll
    for (int i = 0; i < 16; i++)
#pragma unroll
        for (int j = 0; j < 4; j++) d[i][j] = 0.f;

    for (int chunk = 0; chunk < 4; chunk++) {
        int ci0 = chunk * 16;
        __syncthreads();
        // stage av halo (16 ci x 18x18) -- fp32; cvt to tf32 at use
        for (int i = tid; i < 16*324; i += 256) {
            int ci = i / 324, rr = i - ci*324;
            int r = rr / 18, cc = rr - r*18;
            int vv = v0 - 1 + r, t = t0 - 1 + cc;
            float val = 0.f;
            if (vv >= 0 && vv < 128 && t >= 0 && t < 128)
                val = g_av[(size_t)(b*64 + ci0 + ci)*16384 + (size_t)vv*128 + t];
            avs[ci*AVC + r*AVR + cc] = val;
        }
        for (int i = tid; i < 16*576; i += 256)
            wss[i] = g_wtr[ci0*576 + i];
        __syncthreads();

        const unsigned* wsu = reinterpret_cast<const unsigned*>(wss);
#pragma unroll
        for (int kk = 0; kk < 9; kk++) {
            int dv = kk / 3, dt = kk - dv*3;
#pragma unroll
            for (int ks = 0; ks < 2; ks++) {
                // A fragment: W[o = warpM*16 + g (+8)][ci = ks*8 + c (+4)], tap kk
                const unsigned* wp = wsu + (ks*8 + c)*576 + kk*64 + warpM*16 + g;
                unsigned a0 = wp[0], a1 = wp[8];
                unsigned a2 = wp[4*576], a3 = wp[4*576 + 8];
                int cb0 = (ks*8 + c)*AVC + dv*AVR + dt;
#pragma unroll
                for (int nt = 0; nt < 16; nt++) {
                    int pr = warpN*8 + (nt >> 1);
                    int pc = (nt & 1)*8 + g;
                    float f0 = avs[cb0 + pr*AVR + pc];
                    float f1 = avs[cb0 + 4*AVC + pr*AVR + pc];
                    mma_tf32(d[nt], a0, a1, a2, a3, tf32b(f0), tf32b(f1));
                }
            }
        }
    }
    __syncthreads();   // all avs/wss reads done; alias convS

    // store D fragments to convS[o][pix]
#pragma unroll
    for (int nt = 0; nt < 16; nt++) {
        int pr = warpN*8 + (nt >> 1);
        int pc = (nt & 1)*8 + 2*c;
        int pix = pr*16 + pc;
        int o = warpM*16 + g;
        *reinterpret_cast<float2*>(convS + o*CSP + pix)     = make_float2(d[nt][0], d[nt][1]);
        *reinterpret_cast<float2*>(convS + (o+8)*CSP + pix) = make_float2(d[nt][2], d[nt][3]);
    }
    // per-pixel softmax recombination scales
    {
        float gamma = __ldg(gamma_p);
        int v = v0 + (tid >> 4), t = t0 + (tid & 15);
        size_t sidx = ((size_t)b*VV + v)*TT + t;
        float mH = __ldg(&g_mH[sidx]), ZH = __ldg(&g_ZH[sidx]);
        float mW = __ldg(&g_mW[sidx]), ZW = __ldg(&g_ZW[sidx]);
        float m = fmaxf(mH, mW);
        float eH = __expf(mH - m), eW = __expf(mW - m);
        float inv = gamma / (ZH*eH + ZW*eW);
        scS[tid]       = eH * inv;
        scS[256 + tid] = eW * inv;
    }
    __syncthreads();

    // coalesced epilogue: warp owns 8 o; thread: rows {g, g+8}, cols c*4..+3
    float sigma = __ldg(sigma_p);
    int o8 = warp * 8;
    int c4p = c * 4;
#pragma unroll
    for (int half = 0; half < 2; half++) {
        int rr = g + half*8;
        int pix = rr*16 + c4p;
        float sH0 = scS[pix],   sH1 = scS[pix+1],   sH2 = scS[pix+2],   sH3 = scS[pix+3];
        float sW0 = scS[256+pix], sW1 = scS[256+pix+1], sW2 = scS[256+pix+2], sW3 = scS[256+pix+3];
        int v = v0 + rr, t = t0 + c4p;
#pragma unroll
        for (int oi = 0; oi < 8; oi++) {
            int o = o8 + oi;
            size_t oidx = (((size_t)b*CO + o)*VV + v)*TT + t;
            float4 cv = ld4s(convS + o*CSP + pix);
            float4 yv = ld4g(&g_y[oidx]);
            float4 oh = ld4g(&g_OH[oidx]);
            float4 ow = ld4g(&g_OW[oidx]);
            float4 r;
            r.x = yv.x + sH0*oh.x + sW0*ow.x + sigma*cv.x;
            r.y = yv.y + sH1*oh.y + sW1*ow.y + sigma*cv.y;
            r.z = yv.z + sH2*oh.z + sW2*ow.z + sigma*cv.z;
            r.w = yv.w + sH3*oh.w + sW3*ow.w + sigma*cv.w;
            *reinterpret_cast<float4*>(out + oidx) = r;
        }
    }
}

// ---------------- launch: stream-parallel DAG ----------------
extern "C" void kernel_launch(void* const* d_in, const int* in_sizes, int n_in,
                              void* d_out, int out_size) {
    (void)in_sizes; (void)n_in; (void)out_size;
    const float* x    = (const float*)d_in[0];
    const float* dc_w = (const float*)d_in[1];
    const float* dc_b = (const float*)d_in[2];
    const float* q_w  = (const float*)d_in[3];
    const float* q_b  = (const float*)d_in[4];
    const float* k_w  = (const float*)d_in[5];
    const float* k_b  = (const float*)d_in[6];
    const float* v_w  = (const float*)d_in[7];
    const float* v_b  = (const float*)d_in[8];
    const float* gamma= (const float*)d_in[9];
    const float* cq_w = (const float*)d_in[10];
    const float* cq_b = (const float*)d_in[11];
    const float* ck_w = (const float*)d_in[12];
    const float* ck_b = (const float*)d_in[13];
    const float* cv_w = (const float*)d_in[14];
    const float* cv_b = (const float*)d_in[15];
    const float* av_w = (const float*)d_in[16];
    const float* sigma= (const float*)d_in[17];
    float* out = (float*)d_out;

    float *py, *pytr, *pOH;
    cudaGetSymbolAddress((void**)&py,   g_y);
    cudaGetSymbolAddress((void**)&pytr, g_ytr);
    cudaGetSymbolAddress((void**)&pOH,  g_OH);

    const int SMEM_ATT = 208*SY*4;                  // 109,824 B
    const int SMEM_C   = (192*SY + 64)*4;           // 101,632 B
    const int SMEM_F   = (64*CSP + 512)*4;          // 68,608 B  (>= staging 59,904)

    static cudaStream_t s1 = nullptr, s2 = nullptr;
    static cudaEvent_t evy = nullptr, evw = nullptr, evc = nullptr;
    if (!s1) {
        cudaFuncSetAttribute(k_att<false>, cudaFuncAttributeMaxDynamicSharedMemorySize, SMEM_ATT);
        cudaFuncSetAttribute(k_att<true>,  cudaFuncAttributeMaxDynamicSharedMemorySize, SMEM_ATT);
        cudaFuncSetAttribute(k_c,          cudaFuncAttributeMaxDynamicSharedMemorySize, SMEM_C);
        cudaFuncSetAttribute(k_final,      cudaFuncAttributeMaxDynamicSharedMemorySize, SMEM_F);
        cudaStreamCreateWithFlags(&s1, cudaStreamNonBlocking);
        cudaStreamCreateWithFlags(&s2, cudaStreamNonBlocking);
        cudaEventCreateWithFlags(&evy, cudaEventDisableTiming);
        cudaEventCreateWithFlags(&evw, cudaEventDisableTiming);
        cudaEventCreateWithFlags(&evc, cudaEventDisableTiming);
    }

    // independent prologue on s1
    k_wt <<<144, 256, 0, s1>>>(av_w);

    // default stream: k_y, then fork
    k_y  <<<dim3(128, 8), 256>>>(x, dc_w, dc_b);
    cudaEventRecord(evy, 0);
    cudaStreamWaitEvent(s1, evy, 0);
    cudaStreamWaitEvent(s2, evy, 0);

    // s1: W-attention  |  s2: channel attention  |  default: tr -> H-attention -> tr
    k_att<false><<<dim3(128, 8), 512, SMEM_ATT, s1>>>(q_w, q_b, k_w, k_b, v_w, v_b);
    cudaEventRecord(evw, s1);
    k_c  <<<dim3(128, 8), 512, SMEM_C, s2>>>(cq_w, cq_b, ck_w, ck_b, cv_w, cv_b);
    cudaEventRecord(evc, s2);

    k_tr <<<dim3(16, 64, 8), dim3(32, 8)>>>(py, pytr, 16384, 128, 128, 8192);
    k_att<true> <<<dim3(128, 8), 512, SMEM_ATT>>>(q_w, q_b, k_w, k_b, v_w, v_b);
    k_tr <<<dim3(16, 64, 8), dim3(32, 8)>>>(pytr, pOH, 128, 8192, 16384, 128);

    // join and finish
    cudaStreamWaitEvent(0, evw, 0);
    cudaStreamWaitEvent(0, evc, 0);
    k_final<<<dim3(64, 8), 256, SMEM_F>>>(gamma, sigma, out);
}